// round 1
// baseline (speedup 1.0000x reference)
#include <cuda_runtime.h>
#include <math.h>

#define MAX_NN 50000
#define MAX_NE 800000

// ---------------- scratch (static device memory; no allocs) ----------------
__device__ float    g_pre[(size_t)MAX_NN * 512];   // [N,512]: cols 0:256 src-part, 256:512 dst-part
__device__ float    g_logit[MAX_NE];
__device__ unsigned g_menc[MAX_NN];                // order-preserving float encoding for atomicMax
__device__ float    g_denom[MAX_NN];
__device__ float    g_agg[MAX_NN * 64];
__device__ float    g_w1pack[64 * 512];            // [k<64][c<512] packed (We1|Wa1) src/dst rows
__device__ float    g_wepack[32 * 256];            // rows 128..159 of (We1|Wa1)
__device__ float    g_b1c[256];                    // be1 | ba1

__device__ __forceinline__ unsigned enc_f(float f) {
    unsigned b = __float_as_uint(f);
    return (b & 0x80000000u) ? ~b : (b | 0x80000000u);
}
__device__ __forceinline__ float dec_f(unsigned u) {
    return (u & 0x80000000u) ? __uint_as_float(u ^ 0x80000000u) : __uint_as_float(~u);
}

// ---------------- weight packing ----------------
__global__ void pack_kernel(const float* __restrict__ We1, const float* __restrict__ Wa1,
                            const float* __restrict__ be1, const float* __restrict__ ba1) {
    int i = blockIdx.x * blockDim.x + threadIdx.x;
    if (i < 64 * 512) {
        int k = i >> 9, c = i & 511;
        int part = c >> 7, cc = c & 127;         // 0:We1-src 1:Wa1-src 2:We1-dst 3:Wa1-dst
        int row = (part >= 2) ? (64 + k) : k;
        g_w1pack[i] = ((part & 1) == 0) ? We1[row * 128 + cc] : Wa1[row * 128 + cc];
    }
    if (i < 32 * 256) {
        int k = i >> 8, c = i & 255;
        g_wepack[i] = (c < 128) ? We1[(128 + k) * 128 + c] : Wa1[(128 + k) * 128 + (c - 128)];
    }
    if (i < 256) g_b1c[i] = (i < 128) ? be1[i] : ba1[i - 128];
}

__global__ void init_kernel(int nNodes) {
    int i = blockIdx.x * blockDim.x + threadIdx.x;
    int stride = gridDim.x * blockDim.x;
    for (int j = i; j < nNodes * 64; j += stride) g_agg[j] = 0.f;
    for (int j = i; j < nNodes; j += stride) { g_denom[j] = 0.f; g_menc[j] = 0x007FFFFFu; } // enc(-inf)
}

// ---------------- node precompute GEMM: pre = nf @ W1pack  [N,64]@[64,512] ----------------
__global__ __launch_bounds__(256) void node_pre_kernel(const float* __restrict__ nf, int nNodes) {
    extern __shared__ float sm[];
    float* s_a = sm;            // 64x64
    float* s_w = sm + 64 * 64;  // 64x512
    const int tid = threadIdx.x;
    for (int i = tid; i < 64 * 512; i += 256) s_w[i] = g_w1pack[i];
    int n0 = blockIdx.x * 64;
    for (int i = tid; i < 64 * 64; i += 256) {
        int r = i >> 6, c = i & 63;
        int n = n0 + r;
        s_a[i] = (n < nNodes) ? nf[n * 64 + c] : 0.f;
    }
    __syncthreads();
    const int tx = tid & 31, ty = tid >> 5;
    float acc[8][16];
#pragma unroll
    for (int i = 0; i < 8; i++)
#pragma unroll
        for (int j = 0; j < 16; j++) acc[i][j] = 0.f;
#pragma unroll 4
    for (int k = 0; k < 64; k++) {
        float a[8], w[16];
#pragma unroll
        for (int i = 0; i < 8; i++) a[i] = s_a[(ty * 8 + i) * 64 + k];
#pragma unroll
        for (int j = 0; j < 16; j++) w[j] = s_w[k * 512 + tx + j * 32];
#pragma unroll
        for (int i = 0; i < 8; i++)
#pragma unroll
            for (int j = 0; j < 16; j++) acc[i][j] = fmaf(a[i], w[j], acc[i][j]);
    }
#pragma unroll
    for (int i = 0; i < 8; i++) {
        int n = n0 + ty * 8 + i;
        if (n < nNodes) {
#pragma unroll
            for (int j = 0; j < 16; j++)
                g_pre[(size_t)n * 512 + tx + j * 32] = acc[i][j];
        }
    }
}

// ---------------- edge kernel: hidden + layer2 (uh_e, logits) + atomicMax ----------------
__global__ __launch_bounds__(512) void edge_kernel(
    const float* __restrict__ ef, const int* __restrict__ src, const int* __restrict__ dst,
    const float* __restrict__ We2, const float* __restrict__ be2,
    const float* __restrict__ Wa2, const float* __restrict__ ba2,
    float* __restrict__ out_e, int nEdges) {
    extern __shared__ float sm[];
    float* s_h    = sm;                 // 128*256
    float* s_ef   = s_h + 128 * 256;    // 128*32
    float* s_w1e  = s_ef + 128 * 32;    // 32*256
    float* s_w2   = s_w1e + 32 * 256;   // 128*64
    float* s_wa2  = s_w2 + 128 * 64;    // 128
    float* s_b1   = s_wa2 + 128;        // 256
    float* s_b2   = s_b1 + 256;         // 64
    float* s_misc = s_b2 + 64;          // 8
    int*   s_src  = (int*)(s_misc + 8); // 128
    int*   s_dst  = s_src + 128;        // 128

    const int tid = threadIdx.x;
    const int e0 = blockIdx.x * 128;

    for (int i = tid; i < 32 * 256; i += 512) s_w1e[i] = g_wepack[i];
    for (int i = tid; i < 128 * 64; i += 512) s_w2[i] = We2[i];
    if (tid < 128) s_wa2[tid] = Wa2[tid];
    if (tid < 256) s_b1[tid] = g_b1c[tid];
    if (tid < 64)  s_b2[tid] = be2[tid];
    if (tid == 0)  s_misc[0] = ba2[0];
    for (int i = tid; i < 128; i += 512) {
        int e = e0 + i;
        s_src[i] = (e < nEdges) ? src[e] : 0;
        s_dst[i] = (e < nEdges) ? dst[e] : 0;
    }
    for (int i = tid; i < 128 * 32; i += 512) {
        int e = e0 + (i >> 5);
        s_ef[i] = (e < nEdges) ? ef[(size_t)e * 32 + (i & 31)] : 0.f;
    }
    __syncthreads();

    const int tx = tid & 31, ty = tid >> 5;   // ty in 0..15, 8 edges each
    float acc[8][8];
    // init accumulators with gathered node-precomputed parts + bias
#pragma unroll
    for (int i = 0; i < 8; i++) {
        int el = ty * 8 + i;
        const float* ps = g_pre + (size_t)s_src[el] * 512;
        const float* pd = g_pre + (size_t)s_dst[el] * 512 + 256;
#pragma unroll
        for (int j = 0; j < 8; j++) {
            int c = tx + j * 32;
            acc[i][j] = ps[c] + pd[c] + s_b1[c];
        }
    }
    // += ef @ W1e
#pragma unroll 4
    for (int k = 0; k < 32; k++) {
        float a[8], w[8];
#pragma unroll
        for (int i = 0; i < 8; i++) a[i] = s_ef[(ty * 8 + i) * 32 + k];
#pragma unroll
        for (int j = 0; j < 8; j++) w[j] = s_w1e[k * 256 + tx + j * 32];
#pragma unroll
        for (int i = 0; i < 8; i++)
#pragma unroll
            for (int j = 0; j < 8; j++) acc[i][j] = fmaf(a[i], w[j], acc[i][j]);
    }
    // ReLU -> shared
#pragma unroll
    for (int i = 0; i < 8; i++)
#pragma unroll
        for (int j = 0; j < 8; j++)
            s_h[(ty * 8 + i) * 256 + tx + j * 32] = fmaxf(acc[i][j], 0.f);
    __syncthreads();

    // layer2: uh_e = h[:,0:128] @ We2
    float acc2[8][2];
#pragma unroll
    for (int i = 0; i < 8; i++) { acc2[i][0] = 0.f; acc2[i][1] = 0.f; }
#pragma unroll 4
    for (int k = 0; k < 128; k++) {
        float w0 = s_w2[k * 64 + tx], w1 = s_w2[k * 64 + tx + 32];
#pragma unroll
        for (int i = 0; i < 8; i++) {
            float a = s_h[(ty * 8 + i) * 256 + k];
            acc2[i][0] = fmaf(a, w0, acc2[i][0]);
            acc2[i][1] = fmaf(a, w1, acc2[i][1]);
        }
    }
#pragma unroll
    for (int i = 0; i < 8; i++) {
        int e = e0 + ty * 8 + i;
        if (e < nEdges) {
            out_e[(size_t)e * 64 + tx]      = acc2[i][0] + s_b2[tx];
            out_e[(size_t)e * 64 + tx + 32] = acc2[i][1] + s_b2[tx + 32];
        }
    }
    // logits: h[:,128:256] @ Wa2 ; warp ty covers its 8 edges
    float ba2v = s_misc[0];
#pragma unroll
    for (int i = 0; i < 8; i++) {
        int el = ty * 8 + i;
        float p = 0.f;
#pragma unroll
        for (int kk = 0; kk < 4; kk++) {
            int k = tx + kk * 32;
            p = fmaf(s_h[el * 256 + 128 + k], s_wa2[k], p);
        }
#pragma unroll
        for (int off = 16; off > 0; off >>= 1)
            p += __shfl_xor_sync(0xFFFFFFFFu, p, off);
        if (tx == 0) {
            int e = e0 + el;
            if (e < nEdges) {
                float lg = p + ba2v;
                g_logit[e] = lg;
                atomicMax(&g_menc[s_dst[el]], enc_f(lg));
            }
        }
    }
}

// ---------------- softmax-weighted scatter aggregation (unnormalized) ----------------
__global__ __launch_bounds__(256) void aggregate_kernel(const float* __restrict__ out_e,
                                                        const int* __restrict__ dst, int nEdges) {
    int gw = (blockIdx.x * 256 + threadIdx.x) >> 5;
    int lane = threadIdx.x & 31;
    if (gw >= nEdges) return;
    int d = dst[gw];
    float m = dec_f(g_menc[d]);
    float ex = expf(g_logit[gw] - m);
    const float* ue = out_e + (size_t)gw * 64;
    atomicAdd(&g_agg[d * 64 + lane],      ue[lane] * ex);
    atomicAdd(&g_agg[d * 64 + lane + 32], ue[lane + 32] * ex);
    if (lane == 0) atomicAdd(&g_denom[d], ex);
}

// ---------------- node MLP: uh_n = MLP([agg/denom, nf]) ----------------
__global__ __launch_bounds__(256) void node_kernel(
    const float* __restrict__ nf,
    const float* __restrict__ Wn1, const float* __restrict__ bn1,
    const float* __restrict__ Wn2, const float* __restrict__ bn2,
    float* __restrict__ out_n, int nNodes) {
    extern __shared__ float sm[];
    float* s_x  = sm;               // 64*128
    float* s_w1 = s_x + 64 * 128;   // 128*128
    float* s_h  = s_w1 + 128 * 128; // 64*128
    float* s_w2 = s_h + 64 * 128;   // 128*64
    float* s_b1 = s_w2 + 128 * 64;  // 128
    float* s_b2 = s_b1 + 128;       // 64
    const int tid = threadIdx.x;
    const int n0 = blockIdx.x * 64;
    for (int i = tid; i < 128 * 128; i += 256) s_w1[i] = Wn1[i];
    for (int i = tid; i < 128 * 64; i += 256) s_w2[i] = Wn2[i];
    if (tid < 128) s_b1[tid] = bn1[tid];
    if (tid < 64)  s_b2[tid] = bn2[tid];
    for (int i = tid; i < 64 * 128; i += 256) {
        int r = i >> 7, c = i & 127;
        int n = n0 + r;
        float v = 0.f;
        if (n < nNodes) {
            if (c < 64) {
                float dn = fmaxf(g_denom[n], 1e-38f);
                v = g_agg[n * 64 + c] / dn;
            } else {
                v = nf[n * 64 + (c - 64)];
            }
        }
        s_x[i] = v;
    }
    __syncthreads();
    const int tx = tid & 31, ty = tid >> 5;
    float acc[8][4];
#pragma unroll
    for (int i = 0; i < 8; i++)
#pragma unroll
        for (int j = 0; j < 4; j++) acc[i][j] = 0.f;
#pragma unroll 4
    for (int k = 0; k < 128; k++) {
        float a[8], w[4];
#pragma unroll
        for (int i = 0; i < 8; i++) a[i] = s_x[(ty * 8 + i) * 128 + k];
#pragma unroll
        for (int j = 0; j < 4; j++) w[j] = s_w1[k * 128 + tx + j * 32];
#pragma unroll
        for (int i = 0; i < 8; i++)
#pragma unroll
            for (int j = 0; j < 4; j++) acc[i][j] = fmaf(a[i], w[j], acc[i][j]);
    }
#pragma unroll
    for (int i = 0; i < 8; i++)
#pragma unroll
        for (int j = 0; j < 4; j++)
            s_h[(ty * 8 + i) * 128 + tx + j * 32] = fmaxf(acc[i][j] + s_b1[tx + j * 32], 0.f);
    __syncthreads();
    float acc2[8][2];
#pragma unroll
    for (int i = 0; i < 8; i++) { acc2[i][0] = 0.f; acc2[i][1] = 0.f; }
#pragma unroll 4
    for (int k = 0; k < 128; k++) {
        float w0 = s_w2[k * 64 + tx], w1 = s_w2[k * 64 + tx + 32];
#pragma unroll
        for (int i = 0; i < 8; i++) {
            float a = s_h[(ty * 8 + i) * 128 + k];
            acc2[i][0] = fmaf(a, w0, acc2[i][0]);
            acc2[i][1] = fmaf(a, w1, acc2[i][1]);
        }
    }
#pragma unroll
    for (int i = 0; i < 8; i++) {
        int n = n0 + ty * 8 + i;
        if (n < nNodes) {
            out_n[(size_t)n * 64 + tx]      = acc2[i][0] + s_b2[tx];
            out_n[(size_t)n * 64 + tx + 32] = acc2[i][1] + s_b2[tx + 32];
        }
    }
}

// ---------------- launch ----------------
extern "C" void kernel_launch(void* const* d_in, const int* in_sizes, int n_in,
                              void* d_out, int out_size) {
    const float* nf  = (const float*)d_in[0];
    const float* ef  = (const float*)d_in[1];
    const int*   src = (const int*)d_in[2];
    const int*   dst = (const int*)d_in[3];
    const float* We1 = (const float*)d_in[4];
    const float* be1 = (const float*)d_in[5];
    const float* We2 = (const float*)d_in[6];
    const float* be2 = (const float*)d_in[7];
    const float* Wa1 = (const float*)d_in[8];
    const float* ba1 = (const float*)d_in[9];
    const float* Wa2 = (const float*)d_in[10];
    const float* ba2 = (const float*)d_in[11];
    const float* Wn1 = (const float*)d_in[12];
    const float* bn1 = (const float*)d_in[13];
    const float* Wn2 = (const float*)d_in[14];
    const float* bn2 = (const float*)d_in[15];

    int nNodes = in_sizes[0] / 64;
    int nEdges = in_sizes[2];

    float* out   = (float*)d_out;
    float* out_n = out;                              // [N,64]
    float* out_e = out + (size_t)nNodes * 64;        // [E,64]

    cudaFuncSetAttribute(node_pre_kernel, cudaFuncAttributeMaxDynamicSharedMemorySize, 147456);
    cudaFuncSetAttribute(edge_kernel,     cudaFuncAttributeMaxDynamicSharedMemorySize, 215840);
    cudaFuncSetAttribute(node_kernel,     cudaFuncAttributeMaxDynamicSharedMemorySize, 164608);

    pack_kernel<<<128, 256>>>(We1, Wa1, be1, ba1);
    init_kernel<<<256, 256>>>(nNodes);
    node_pre_kernel<<<(nNodes + 63) / 64, 256, 147456>>>(nf, nNodes);
    edge_kernel<<<(nEdges + 127) / 128, 512, 215840>>>(ef, src, dst, We2, be2, Wa2, ba2,
                                                       out_e, nEdges);
    aggregate_kernel<<<(nEdges + 7) / 8, 256>>>(out_e, dst, nEdges);
    node_kernel<<<(nNodes + 63) / 64, 256, 164608>>>(nf, Wn1, bn1, Wn2, bn2, out_n, nNodes);
}

// round 2
// speedup vs baseline: 1.4188x; 1.4188x over previous
#include <cuda_runtime.h>
#include <math.h>

#define MAX_NN 50000
#define MAX_NE 800000

// ---------------- scratch (static device memory; no allocs) ----------------
// g_pre[n][512]: permuted. [0:256) = src-part, [256:512) = dst-part.
// Within a 256 block, position p = t*8+j  <->  logical hidden col c = t + 32*j
// (c<128 -> We1 hidden col c ; c>=128 -> Wa1 hidden col c-128)
__device__ float g_pre[(size_t)MAX_NN * 512];
__device__ float g_denom[MAX_NN];
__device__ float g_agg[MAX_NN * 64];
__device__ float g_w1pack[64 * 512];   // node-pre weights, permuted cols (same p mapping, src|dst)
__device__ float g_wep[32 * 256];      // edge-part W1 rows 128..159, layout (k*32+t)*8+j
__device__ float g_w2p[128 * 64];      // layer2 We2, layout (p*32+t)*2+o  (p = s_h position)
__device__ float g_wa2p[128];          // Wa2 permuted: [t*4+q] = Wa2[t+32q]
__device__ float g_b1p[256];           // bias permuted: [t*8+j] = b1[c(t,j)]

// ---------------- weight packing ----------------
__global__ void pack_kernel(const float* __restrict__ We1, const float* __restrict__ Wa1,
                            const float* __restrict__ be1, const float* __restrict__ ba1,
                            const float* __restrict__ We2, const float* __restrict__ Wa2) {
    int i = blockIdx.x * blockDim.x + threadIdx.x;
    if (i < 64 * 512) {  // g_w1pack
        int k = i >> 9, p = i & 511;
        int blk = p >> 8, q = p & 255;
        int t = q >> 3, j = q & 7;
        int c = t + 32 * j;
        int row = blk ? (64 + k) : k;
        g_w1pack[i] = (c < 128) ? We1[row * 128 + c] : Wa1[row * 128 + (c - 128)];
    }
    if (i < 32 * 256) {  // g_wep
        int j = i & 7, t = (i >> 3) & 31, k = i >> 8;
        int c = t + 32 * j;
        int row = 128 + k;
        g_wep[i] = (c < 128) ? We1[row * 128 + c] : Wa1[row * 128 + (c - 128)];
    }
    if (i < 128 * 64) {  // g_w2p
        int o = i & 1, t = (i >> 1) & 31, p = i >> 6;
        int c = (p >> 2) + 32 * (p & 3);
        g_w2p[i] = We2[c * 64 + t + 32 * o];
    }
    if (i < 128) {       // g_wa2p
        int t = i >> 2, q = i & 3;
        g_wa2p[i] = Wa2[t + 32 * q];
    }
    if (i < 256) {       // g_b1p
        int t = i >> 3, j = i & 7;
        int c = t + 32 * j;
        g_b1p[i] = (c < 128) ? be1[c] : ba1[c - 128];
    }
}

__global__ void init_kernel(int nNodes) {
    int i = blockIdx.x * blockDim.x + threadIdx.x;
    int stride = gridDim.x * blockDim.x;
    float4* a4 = (float4*)g_agg;
    for (int j = i; j < nNodes * 16; j += stride) a4[j] = make_float4(0.f, 0.f, 0.f, 0.f);
    for (int j = i; j < nNodes; j += stride) g_denom[j] = 0.f;
}

// ---------------- node precompute GEMM: pre = nf @ W1pack  [N,64]@[64,512] ----------------
__global__ __launch_bounds__(256) void node_pre_kernel(const float* __restrict__ nf, int nNodes) {
    extern __shared__ float sm[];
    float* s_a = sm;            // 64x64
    float* s_w = sm + 64 * 64;  // 64x512
    const int tid = threadIdx.x;
    {
        float4* sw4 = (float4*)s_w;
        const float4* gw4 = (const float4*)g_w1pack;
        for (int i = tid; i < 64 * 128; i += 256) sw4[i] = gw4[i];
    }
    int n0 = blockIdx.x * 64;
    for (int i = tid; i < 64 * 64; i += 256) {
        int r = i >> 6, c = i & 63;
        int n = n0 + r;
        s_a[i] = (n < nNodes) ? nf[n * 64 + c] : 0.f;
    }
    __syncthreads();
    const int tx = tid & 31, ty = tid >> 5;
    float acc[8][16];
#pragma unroll
    for (int i = 0; i < 8; i++)
#pragma unroll
        for (int j = 0; j < 16; j++) acc[i][j] = 0.f;
    const float4* sw4 = (const float4*)s_w;
#pragma unroll 2
    for (int k = 0; k < 64; k++) {
        float a[8];
        float4 w[4];
#pragma unroll
        for (int i = 0; i < 8; i++) a[i] = s_a[(ty * 8 + i) * 64 + k];
#pragma unroll
        for (int m = 0; m < 4; m++) w[m] = sw4[k * 128 + tx * 4 + m];
#pragma unroll
        for (int i = 0; i < 8; i++) {
#pragma unroll
            for (int m = 0; m < 4; m++) {
                acc[i][m * 4 + 0] = fmaf(a[i], w[m].x, acc[i][m * 4 + 0]);
                acc[i][m * 4 + 1] = fmaf(a[i], w[m].y, acc[i][m * 4 + 1]);
                acc[i][m * 4 + 2] = fmaf(a[i], w[m].z, acc[i][m * 4 + 2]);
                acc[i][m * 4 + 3] = fmaf(a[i], w[m].w, acc[i][m * 4 + 3]);
            }
        }
    }
    float4* gp4 = (float4*)g_pre;
#pragma unroll
    for (int i = 0; i < 8; i++) {
        int n = n0 + ty * 8 + i;
        if (n < nNodes) {
#pragma unroll
            for (int m = 0; m < 4; m++)
                gp4[(size_t)n * 128 + tx * 4 + m] =
                    make_float4(acc[i][m * 4 + 0], acc[i][m * 4 + 1],
                                acc[i][m * 4 + 2], acc[i][m * 4 + 3]);
        }
    }
}

// ---------------- fused edge kernel: MLPs + logit + exp-weighted scatter ----------------
__global__ __launch_bounds__(512) void edge_kernel(
    const float* __restrict__ ef, const int* __restrict__ src, const int* __restrict__ dst,
    const float* __restrict__ be2, const float* __restrict__ ba2,
    float* __restrict__ out_e, int nEdges) {
    extern __shared__ float sm[];
    float4* s_h4  = (float4*)sm;                  // 128 x 32 float4 (We-hidden, permuted)
    float4* s_ef4 = s_h4 + 128 * 32;              // 128 x 8 float4
    int*    s_src = (int*)(s_ef4 + 128 * 8);      // 128
    int*    s_dst = s_src + 128;                  // 128

    const int tid = threadIdx.x;
    const int e0 = blockIdx.x * 128;
    const int tx = tid & 31, ty = tid >> 5;

    // stage ef + indices
    const float4* ef4 = (const float4*)ef;
    for (int i = tid; i < 128 * 8; i += 512) {
        int e = e0 + (i >> 3);
        s_ef4[i] = (e < nEdges) ? ef4[(size_t)e * 8 + (i & 7)]
                                : make_float4(0.f, 0.f, 0.f, 0.f);
    }
    for (int i = tid; i < 128; i += 512) {
        int e = e0 + i;
        s_src[i] = (e < nEdges) ? src[e] : 0;
        s_dst[i] = (e < nEdges) ? dst[e] : 0;
    }
    __syncthreads();

    // gather node-precomputed parts + bias -> acc init
    const float4* P = (const float4*)g_pre;
    const float4* b1p4 = (const float4*)g_b1p;
    float4 b1a = __ldg(b1p4 + tx * 2), b1b = __ldg(b1p4 + tx * 2 + 1);
    float acc[8][8];
#pragma unroll
    for (int i = 0; i < 8; i++) {
        int el = ty * 8 + i;
        size_t sb = (size_t)s_src[el] * 128;
        size_t db = (size_t)s_dst[el] * 128 + 64;
        float4 sa = __ldg(P + sb + tx * 2), s2 = __ldg(P + sb + tx * 2 + 1);
        float4 da = __ldg(P + db + tx * 2), d2 = __ldg(P + db + tx * 2 + 1);
        acc[i][0] = sa.x + da.x + b1a.x;  acc[i][1] = sa.y + da.y + b1a.y;
        acc[i][2] = sa.z + da.z + b1a.z;  acc[i][3] = sa.w + da.w + b1a.w;
        acc[i][4] = s2.x + d2.x + b1b.x;  acc[i][5] = s2.y + d2.y + b1b.y;
        acc[i][6] = s2.z + d2.z + b1b.z;  acc[i][7] = s2.w + d2.w + b1b.w;
    }

    // += ef @ W1e  (k = 0..31)
    const float4* w1p4 = (const float4*)g_wep;
#pragma unroll
    for (int kk = 0; kk < 8; kk++) {
        float4 aa[8];
#pragma unroll
        for (int i = 0; i < 8; i++) aa[i] = s_ef4[(ty * 8 + i) * 8 + kk];
#pragma unroll
        for (int k4 = 0; k4 < 4; k4++) {
            int k = kk * 4 + k4;
            float4 w0 = __ldg(w1p4 + (k * 32 + tx) * 2);
            float4 w1 = __ldg(w1p4 + (k * 32 + tx) * 2 + 1);
#pragma unroll
            for (int i = 0; i < 8; i++) {
                float a = (k4 == 0) ? aa[i].x : (k4 == 1) ? aa[i].y : (k4 == 2) ? aa[i].z : aa[i].w;
                acc[i][0] = fmaf(a, w0.x, acc[i][0]);
                acc[i][1] = fmaf(a, w0.y, acc[i][1]);
                acc[i][2] = fmaf(a, w0.z, acc[i][2]);
                acc[i][3] = fmaf(a, w0.w, acc[i][3]);
                acc[i][4] = fmaf(a, w1.x, acc[i][4]);
                acc[i][5] = fmaf(a, w1.y, acc[i][5]);
                acc[i][6] = fmaf(a, w1.z, acc[i][6]);
                acc[i][7] = fmaf(a, w1.w, acc[i][7]);
            }
        }
    }

    // ReLU: We-half -> smem; Wa-half -> logit in registers
    const float4* wa2p4 = (const float4*)g_wa2p;
    float4 wa = __ldg(wa2p4 + tx);
    float ba2v = __ldg(ba2);
    float ex[8];
#pragma unroll
    for (int i = 0; i < 8; i++) {
        int el = ty * 8 + i;
        s_h4[el * 32 + tx] = make_float4(fmaxf(acc[i][0], 0.f), fmaxf(acc[i][1], 0.f),
                                         fmaxf(acc[i][2], 0.f), fmaxf(acc[i][3], 0.f));
        float p = fmaxf(acc[i][4], 0.f) * wa.x + fmaxf(acc[i][5], 0.f) * wa.y
                + fmaxf(acc[i][6], 0.f) * wa.z + fmaxf(acc[i][7], 0.f) * wa.w;
#pragma unroll
        for (int off = 16; off > 0; off >>= 1)
            p += __shfl_xor_sync(0xFFFFFFFFu, p, off);
        ex[i] = expf(p + ba2v);
    }
    __syncthreads();

    // layer2: uh_e = relu_h @ We2  (over 128 permuted positions)
    const float2* w2p2 = (const float2*)g_w2p;
    float acc2[8][2];
#pragma unroll
    for (int i = 0; i < 8; i++) { acc2[i][0] = 0.f; acc2[i][1] = 0.f; }
#pragma unroll 4
    for (int p4 = 0; p4 < 32; p4++) {
        float4 a4[8];
#pragma unroll
        for (int i = 0; i < 8; i++) a4[i] = s_h4[(ty * 8 + i) * 32 + p4];
#pragma unroll
        for (int pp = 0; pp < 4; pp++) {
            float2 w2 = __ldg(w2p2 + (p4 * 4 + pp) * 32 + tx);
#pragma unroll
            for (int i = 0; i < 8; i++) {
                float a = (pp == 0) ? a4[i].x : (pp == 1) ? a4[i].y : (pp == 2) ? a4[i].z : a4[i].w;
                acc2[i][0] = fmaf(a, w2.x, acc2[i][0]);
                acc2[i][1] = fmaf(a, w2.y, acc2[i][1]);
            }
        }
    }

    // epilogue: write uh_e + exp-weighted scatter aggregation
    float b2a = __ldg(be2 + tx), b2b = __ldg(be2 + tx + 32);
#pragma unroll
    for (int i = 0; i < 8; i++) {
        int el = ty * 8 + i;
        int e = e0 + el;
        if (e < nEdges) {
            float v0 = acc2[i][0] + b2a;
            float v1 = acc2[i][1] + b2b;
            out_e[(size_t)e * 64 + tx]      = v0;
            out_e[(size_t)e * 64 + tx + 32] = v1;
            int d = s_dst[el];
            atomicAdd(&g_agg[d * 64 + tx],      v0 * ex[i]);
            atomicAdd(&g_agg[d * 64 + tx + 32], v1 * ex[i]);
            if (tx == 0) atomicAdd(&g_denom[d], ex[i]);
        }
    }
}

// ---------------- node MLP: uh_n = MLP([agg/denom, nf]) ----------------
__global__ __launch_bounds__(256) void node_kernel(
    const float* __restrict__ nf,
    const float* __restrict__ Wn1, const float* __restrict__ bn1,
    const float* __restrict__ Wn2, const float* __restrict__ bn2,
    float* __restrict__ out_n, int nNodes) {
    extern __shared__ float sm[];
    float* s_x  = sm;               // 64*128
    float* s_w1 = s_x + 64 * 128;   // 128*128
    float* s_h  = s_w1 + 128 * 128; // 64*128
    float* s_w2 = s_h + 64 * 128;   // 128*64
    float* s_b1 = s_w2 + 128 * 64;  // 128
    float* s_b2 = s_b1 + 128;       // 64
    const int tid = threadIdx.x;
    const int n0 = blockIdx.x * 64;
    for (int i = tid; i < 128 * 128; i += 256) s_w1[i] = Wn1[i];
    for (int i = tid; i < 128 * 64; i += 256) s_w2[i] = Wn2[i];
    if (tid < 128) s_b1[tid] = bn1[tid];
    if (tid < 64)  s_b2[tid] = bn2[tid];
    for (int i = tid; i < 64 * 128; i += 256) {
        int r = i >> 7, c = i & 127;
        int n = n0 + r;
        float v = 0.f;
        if (n < nNodes) {
            if (c < 64) {
                float dn = fmaxf(g_denom[n], 1e-38f);
                v = g_agg[n * 64 + c] / dn;
            } else {
                v = nf[n * 64 + (c - 64)];
            }
        }
        s_x[i] = v;
    }
    __syncthreads();
    const int tx = tid & 31, ty = tid >> 5;
    float acc[8][4];
#pragma unroll
    for (int i = 0; i < 8; i++)
#pragma unroll
        for (int j = 0; j < 4; j++) acc[i][j] = 0.f;
#pragma unroll 4
    for (int k = 0; k < 128; k++) {
        float a[8], w[4];
#pragma unroll
        for (int i = 0; i < 8; i++) a[i] = s_x[(ty * 8 + i) * 128 + k];
#pragma unroll
        for (int j = 0; j < 4; j++) w[j] = s_w1[k * 128 + tx + j * 32];
#pragma unroll
        for (int i = 0; i < 8; i++)
#pragma unroll
            for (int j = 0; j < 4; j++) acc[i][j] = fmaf(a[i], w[j], acc[i][j]);
    }
#pragma unroll
    for (int i = 0; i < 8; i++)
#pragma unroll
        for (int j = 0; j < 4; j++)
            s_h[(ty * 8 + i) * 128 + tx + j * 32] = fmaxf(acc[i][j] + s_b1[tx + j * 32], 0.f);
    __syncthreads();
    float acc2[8][2];
#pragma unroll
    for (int i = 0; i < 8; i++) { acc2[i][0] = 0.f; acc2[i][1] = 0.f; }
#pragma unroll 4
    for (int k = 0; k < 128; k++) {
        float w0 = s_w2[k * 64 + tx], w1 = s_w2[k * 64 + tx + 32];
#pragma unroll
        for (int i = 0; i < 8; i++) {
            float a = s_h[(ty * 8 + i) * 128 + k];
            acc2[i][0] = fmaf(a, w0, acc2[i][0]);
            acc2[i][1] = fmaf(a, w1, acc2[i][1]);
        }
    }
#pragma unroll
    for (int i = 0; i < 8; i++) {
        int n = n0 + ty * 8 + i;
        if (n < nNodes) {
            out_n[(size_t)n * 64 + tx]      = acc2[i][0] + s_b2[tx];
            out_n[(size_t)n * 64 + tx + 32] = acc2[i][1] + s_b2[tx + 32];
        }
    }
}

// ---------------- launch ----------------
extern "C" void kernel_launch(void* const* d_in, const int* in_sizes, int n_in,
                              void* d_out, int out_size) {
    const float* nf  = (const float*)d_in[0];
    const float* ef  = (const float*)d_in[1];
    const int*   src = (const int*)d_in[2];
    const int*   dst = (const int*)d_in[3];
    const float* We1 = (const float*)d_in[4];
    const float* be1 = (const float*)d_in[5];
    const float* We2 = (const float*)d_in[6];
    const float* be2 = (const float*)d_in[7];
    const float* Wa1 = (const float*)d_in[8];
    const float* ba1 = (const float*)d_in[9];
    const float* Wa2 = (const float*)d_in[10];
    const float* ba2 = (const float*)d_in[11];
    const float* Wn1 = (const float*)d_in[12];
    const float* bn1 = (const float*)d_in[13];
    const float* Wn2 = (const float*)d_in[14];
    const float* bn2 = (const float*)d_in[15];

    int nNodes = in_sizes[0] / 64;
    int nEdges = in_sizes[2];

    float* out   = (float*)d_out;
    float* out_n = out;                              // [N,64]
    float* out_e = out + (size_t)nNodes * 64;        // [E,64]

    int smem_pre  = (64 * 64 + 64 * 512) * 4;                       // 147456
    int smem_edge = (128 * 32 + 128 * 8) * 16 + 2 * 128 * 4;        // 82944
    int smem_node = (64 * 128 * 2 + 128 * 128 + 128 * 64 + 192) * 4;

    cudaFuncSetAttribute(node_pre_kernel, cudaFuncAttributeMaxDynamicSharedMemorySize, smem_pre);
    cudaFuncSetAttribute(edge_kernel,     cudaFuncAttributeMaxDynamicSharedMemorySize, smem_edge);
    cudaFuncSetAttribute(node_kernel,     cudaFuncAttributeMaxDynamicSharedMemorySize, smem_node);

    pack_kernel<<<128, 256>>>(We1, Wa1, be1, ba1, We2, Wa2);
    init_kernel<<<256, 256>>>(nNodes);
    node_pre_kernel<<<(nNodes + 63) / 64, 256, smem_pre>>>(nf, nNodes);
    edge_kernel<<<(nEdges + 127) / 128, 512, smem_edge>>>(ef, src, dst, be2, ba2, out_e, nEdges);
    node_kernel<<<(nNodes + 63) / 64, 256, smem_node>>>(nf, Wn1, bn1, Wn2, bn2, out_n, nNodes);
}

// round 3
// speedup vs baseline: 1.4638x; 1.0318x over previous
#include <cuda_runtime.h>
#include <cuda_bf16.h>
#include <math.h>

#define MAX_NN 50000
#define MAX_NE 800000

// ---------------- scratch (static device memory; no allocs) ----------------
__device__ float g_pre[(size_t)MAX_NN * 512];  // [N][512] natural: [0:256) src-part, [256:512) dst-part
__device__ float g_denom[MAX_NN];
__device__ float g_agg[MAX_NN * 64];
__device__ float g_w1pack[64 * 512];           // [k][p] natural cols (We1|Wa1, src|dst)
__device__ float g_b1c[256];                   // be1|ba1 natural
__device__ float g_wa2n[128];                  // Wa2 natural
__device__ __align__(16) __nv_bfloat16 g_w1eT_h[256 * 40];  // [c][k] W1e rows 128..159 (hi)
__device__ __align__(16) __nv_bfloat16 g_w1eT_l[256 * 40];  // (lo)
__device__ __align__(16) __nv_bfloat16 g_w2T_h[64 * 136];   // [n][k] We2 transposed (hi)
__device__ __align__(16) __nv_bfloat16 g_w2T_l[64 * 136];   // (lo)

__device__ __forceinline__ unsigned pk2(__nv_bfloat16 a, __nv_bfloat16 b) {
    return ((unsigned)__bfloat16_as_ushort(b) << 16) | (unsigned)__bfloat16_as_ushort(a);
}

__device__ __forceinline__ void mma_bf16(float* c, const unsigned* a, const unsigned* b) {
    asm volatile(
        "mma.sync.aligned.m16n8k16.row.col.f32.bf16.bf16.f32 "
        "{%0,%1,%2,%3}, {%4,%5,%6,%7}, {%8,%9}, {%0,%1,%2,%3};"
        : "+f"(c[0]), "+f"(c[1]), "+f"(c[2]), "+f"(c[3])
        : "r"(a[0]), "r"(a[1]), "r"(a[2]), "r"(a[3]), "r"(b[0]), "r"(b[1]));
}

__device__ __forceinline__ void red_add2(float* p, float x, float y) {
    asm volatile("red.global.add.v2.f32 [%0], {%1,%2};" :: "l"(p), "f"(x), "f"(y) : "memory");
}

// ---------------- weight packing ----------------
__global__ void pack_kernel(const float* __restrict__ We1, const float* __restrict__ Wa1,
                            const float* __restrict__ be1, const float* __restrict__ ba1,
                            const float* __restrict__ We2, const float* __restrict__ Wa2) {
    int i = blockIdx.x * blockDim.x + threadIdx.x;
    if (i < 64 * 512) {   // g_w1pack natural
        int k = i >> 9, p = i & 511;
        int blk = p >> 8, c = p & 255;
        int row = blk ? (64 + k) : k;
        g_w1pack[i] = (c < 128) ? We1[row * 128 + c] : Wa1[row * 128 + (c - 128)];
    }
    if (i < 256) g_b1c[i] = (i < 128) ? be1[i] : ba1[i - 128];
    if (i < 128) g_wa2n[i] = Wa2[i];
    if (i < 256 * 32) {   // W1e transposed, bf16 split
        int c = i >> 5, k = i & 31;
        float v = (c < 128) ? We1[(128 + k) * 128 + c] : Wa1[(128 + k) * 128 + (c - 128)];
        __nv_bfloat16 h = __float2bfloat16_rn(v);
        g_w1eT_h[c * 40 + k] = h;
        g_w1eT_l[c * 40 + k] = __float2bfloat16_rn(v - __bfloat162float(h));
    }
    if (i < 64 * 128) {   // We2 transposed, bf16 split
        int n = i >> 7, k = i & 127;
        float v = We2[k * 64 + n];
        __nv_bfloat16 h = __float2bfloat16_rn(v);
        g_w2T_h[n * 136 + k] = h;
        g_w2T_l[n * 136 + k] = __float2bfloat16_rn(v - __bfloat162float(h));
    }
}

__global__ void init_kernel(int nNodes) {
    int i = blockIdx.x * blockDim.x + threadIdx.x;
    int stride = gridDim.x * blockDim.x;
    float4* a4 = (float4*)g_agg;
    for (int j = i; j < nNodes * 16; j += stride) a4[j] = make_float4(0.f, 0.f, 0.f, 0.f);
    for (int j = i; j < nNodes; j += stride) g_denom[j] = 0.f;
}

// ---------------- node precompute GEMM: pre = nf @ W1pack  [N,64]@[64,512] ----------------
__global__ __launch_bounds__(256) void node_pre_kernel(const float* __restrict__ nf, int nNodes) {
    extern __shared__ float sm[];
    float* s_a = sm;            // 64x64
    float* s_w = sm + 64 * 64;  // 64x512
    const int tid = threadIdx.x;
    {
        float4* sw4 = (float4*)s_w;
        const float4* gw4 = (const float4*)g_w1pack;
        for (int i = tid; i < 64 * 128; i += 256) sw4[i] = gw4[i];
    }
    int n0 = blockIdx.x * 64;
    for (int i = tid; i < 64 * 64; i += 256) {
        int r = i >> 6, c = i & 63;
        int n = n0 + r;
        s_a[i] = (n < nNodes) ? nf[n * 64 + c] : 0.f;
    }
    __syncthreads();
    const int tx = tid & 31, ty = tid >> 5;
    float acc[8][16];
#pragma unroll
    for (int i = 0; i < 8; i++)
#pragma unroll
        for (int j = 0; j < 16; j++) acc[i][j] = 0.f;
    const float4* sw4 = (const float4*)s_w;
#pragma unroll 2
    for (int k = 0; k < 64; k++) {
        float a[8];
        float4 w[4];
#pragma unroll
        for (int i = 0; i < 8; i++) a[i] = s_a[(ty * 8 + i) * 64 + k];
#pragma unroll
        for (int m = 0; m < 4; m++) w[m] = sw4[k * 128 + tx * 4 + m];
#pragma unroll
        for (int i = 0; i < 8; i++) {
#pragma unroll
            for (int m = 0; m < 4; m++) {
                acc[i][m * 4 + 0] = fmaf(a[i], w[m].x, acc[i][m * 4 + 0]);
                acc[i][m * 4 + 1] = fmaf(a[i], w[m].y, acc[i][m * 4 + 1]);
                acc[i][m * 4 + 2] = fmaf(a[i], w[m].z, acc[i][m * 4 + 2]);
                acc[i][m * 4 + 3] = fmaf(a[i], w[m].w, acc[i][m * 4 + 3]);
            }
        }
    }
    float4* gp4 = (float4*)g_pre;
#pragma unroll
    for (int i = 0; i < 8; i++) {
        int n = n0 + ty * 8 + i;
        if (n < nNodes) {
#pragma unroll
            for (int m = 0; m < 4; m++)
                gp4[(size_t)n * 128 + tx * 4 + m] =
                    make_float4(acc[i][m * 4 + 0], acc[i][m * 4 + 1],
                                acc[i][m * 4 + 2], acc[i][m * 4 + 3]);
        }
    }
}

// ---------------- fused edge kernel (bf16x3 tensor-core) ----------------
// 128 edges / block, 512 threads = 16 warps.
// Layer1: hidden[128,256] = gather(pre_src+pre_dst+b1) + ef[128,32]@W1e[32,256]
//   warp w: m32 rows (w&3)*32, n64 cols (w>>2)*64
// Layer2: uh_e[128,64] = relu_h[128,128] @ We2[128,64]
//   warp w: m32 rows (w&3)*32, n16 cols (w>>2)*16
__global__ __launch_bounds__(512, 1) void edge_kernel(
    const float* __restrict__ ef, const int* __restrict__ src, const int* __restrict__ dst,
    const float* __restrict__ be2, const float* __restrict__ ba2,
    float* __restrict__ out_e, int nEdges) {
    extern __shared__ char smraw[];
    __nv_bfloat16* s_w1h = (__nv_bfloat16*)smraw;          // 256*40
    __nv_bfloat16* s_w1l = s_w1h + 256 * 40;
    __nv_bfloat16* s_w2h = s_w1l + 256 * 40;               // 64*136
    __nv_bfloat16* s_w2l = s_w2h + 64 * 136;
    __nv_bfloat16* s_efh = s_w2l + 64 * 136;               // 128*40
    __nv_bfloat16* s_efl = s_efh + 128 * 40;
    __nv_bfloat16* s_hh  = s_efl + 128 * 40;               // 128*136
    __nv_bfloat16* s_hl  = s_hh + 128 * 136;
    float* s_logit = (float*)(s_hl + 128 * 136);           // 128
    int*   s_src   = (int*)(s_logit + 128);                // 128
    int*   s_dst   = s_src + 128;                          // 128

    const int tid = threadIdx.x;
    const int e0 = blockIdx.x * 128;
    const int lane = tid & 31, w = tid >> 5;
    const int fr = lane >> 2, fc2 = (lane & 3) * 2;

    // ---- stage weights (L2-resident) ----
    for (int i = tid; i < 1280; i += 512) {
        ((uint4*)s_w1h)[i] = ((const uint4*)g_w1eT_h)[i];
        ((uint4*)s_w1l)[i] = ((const uint4*)g_w1eT_l)[i];
    }
    for (int i = tid; i < 1088; i += 512) {
        ((uint4*)s_w2h)[i] = ((const uint4*)g_w2T_h)[i];
        ((uint4*)s_w2l)[i] = ((const uint4*)g_w2T_l)[i];
    }
    if (tid < 128) s_logit[tid] = __ldg(ba2);
    for (int i = tid; i < 128; i += 512) {
        int e = e0 + i;
        s_src[i] = (e < nEdges) ? __ldg(src + e) : 0;
        s_dst[i] = (e < nEdges) ? __ldg(dst + e) : 0;
    }
    // ---- stage ef, bf16 split ----
    for (int i = tid; i < 128 * 32; i += 512) {
        int r = i >> 5, c = i & 31;
        int e = e0 + r;
        float v = (e < nEdges) ? __ldg(ef + (size_t)e * 32 + c) : 0.f;
        __nv_bfloat16 h = __float2bfloat16_rn(v);
        s_efh[r * 40 + c] = h;
        s_efl[r * 40 + c] = __float2bfloat16_rn(v - __bfloat162float(h));
    }
    __syncthreads();

    // ================= Layer 1 =================
    {
        const int mg1 = w & 3, ng1 = w >> 2;
        const int rbase = mg1 * 32;
        float acc[2][8][4];
        // gather-init accumulators (fragment layout)
#pragma unroll
        for (int mt = 0; mt < 2; mt++) {
            int r0 = rbase + mt * 16 + fr, r1 = r0 + 8;
            const float2* Ps0 = (const float2*)(g_pre + (size_t)s_src[r0] * 512);
            const float2* Pd0 = (const float2*)(g_pre + (size_t)s_dst[r0] * 512 + 256);
            const float2* Ps1 = (const float2*)(g_pre + (size_t)s_src[r1] * 512);
            const float2* Pd1 = (const float2*)(g_pre + (size_t)s_dst[r1] * 512 + 256);
#pragma unroll
            for (int nt = 0; nt < 8; nt++) {
                int c = ng1 * 64 + nt * 8 + fc2, i2 = c >> 1;
                float2 bv = __ldg((const float2*)g_b1c + i2);
                float2 a = Ps0[i2], b = Pd0[i2];
                acc[mt][nt][0] = a.x + b.x + bv.x;
                acc[mt][nt][1] = a.y + b.y + bv.y;
                float2 cc = Ps1[i2], dd = Pd1[i2];
                acc[mt][nt][2] = cc.x + dd.x + bv.x;
                acc[mt][nt][3] = cc.y + dd.y + bv.y;
            }
        }
        // mma: += ef @ W1e   (bf16x3)
#pragma unroll
        for (int ks = 0; ks < 2; ks++) {
            int kb = ks * 16;
            unsigned ah[2][4], al[2][4];
#pragma unroll
            for (int mt = 0; mt < 2; mt++) {
                int ra = rbase + mt * 16 + fr;
                ah[mt][0] = *(const unsigned*)(s_efh + ra * 40 + kb + fc2);
                ah[mt][1] = *(const unsigned*)(s_efh + (ra + 8) * 40 + kb + fc2);
                ah[mt][2] = *(const unsigned*)(s_efh + ra * 40 + kb + fc2 + 8);
                ah[mt][3] = *(const unsigned*)(s_efh + (ra + 8) * 40 + kb + fc2 + 8);
                al[mt][0] = *(const unsigned*)(s_efl + ra * 40 + kb + fc2);
                al[mt][1] = *(const unsigned*)(s_efl + (ra + 8) * 40 + kb + fc2);
                al[mt][2] = *(const unsigned*)(s_efl + ra * 40 + kb + fc2 + 8);
                al[mt][3] = *(const unsigned*)(s_efl + (ra + 8) * 40 + kb + fc2 + 8);
            }
#pragma unroll
            for (int nt = 0; nt < 8; nt++) {
                int cb = ng1 * 64 + nt * 8 + fr;
                unsigned bh[2], bl[2];
                bh[0] = *(const unsigned*)(s_w1h + cb * 40 + kb + fc2);
                bh[1] = *(const unsigned*)(s_w1h + cb * 40 + kb + fc2 + 8);
                bl[0] = *(const unsigned*)(s_w1l + cb * 40 + kb + fc2);
                bl[1] = *(const unsigned*)(s_w1l + cb * 40 + kb + fc2 + 8);
#pragma unroll
                for (int mt = 0; mt < 2; mt++) {
                    mma_bf16(acc[mt][nt], ah[mt], bh);
                    mma_bf16(acc[mt][nt], ah[mt], bl);
                    mma_bf16(acc[mt][nt], al[mt], bh);
                }
            }
        }
        // ReLU: We-half -> smem bf16-split; Wa-half -> logit partials
        if (ng1 < 2) {
#pragma unroll
            for (int mt = 0; mt < 2; mt++) {
                int r0 = rbase + mt * 16 + fr, r1 = r0 + 8;
#pragma unroll
                for (int nt = 0; nt < 8; nt++) {
                    int c = ng1 * 64 + nt * 8 + fc2;
                    float v0 = fmaxf(acc[mt][nt][0], 0.f), v1 = fmaxf(acc[mt][nt][1], 0.f);
                    float v2 = fmaxf(acc[mt][nt][2], 0.f), v3 = fmaxf(acc[mt][nt][3], 0.f);
                    __nv_bfloat16 h0 = __float2bfloat16_rn(v0), h1 = __float2bfloat16_rn(v1);
                    __nv_bfloat16 h2 = __float2bfloat16_rn(v2), h3 = __float2bfloat16_rn(v3);
                    *(unsigned*)(s_hh + r0 * 136 + c) = pk2(h0, h1);
                    *(unsigned*)(s_hh + r1 * 136 + c) = pk2(h2, h3);
                    *(unsigned*)(s_hl + r0 * 136 + c) =
                        pk2(__float2bfloat16_rn(v0 - __bfloat162float(h0)),
                            __float2bfloat16_rn(v1 - __bfloat162float(h1)));
                    *(unsigned*)(s_hl + r1 * 136 + c) =
                        pk2(__float2bfloat16_rn(v2 - __bfloat162float(h2)),
                            __float2bfloat16_rn(v3 - __bfloat162float(h3)));
                }
            }
        } else {
#pragma unroll
            for (int mt = 0; mt < 2; mt++) {
                float p0 = 0.f, p1 = 0.f;
#pragma unroll
                for (int nt = 0; nt < 8; nt++) {
                    int c = (ng1 - 2) * 64 + nt * 8 + fc2;
                    float2 wv = __ldg((const float2*)g_wa2n + (c >> 1));
                    p0 += fmaxf(acc[mt][nt][0], 0.f) * wv.x + fmaxf(acc[mt][nt][1], 0.f) * wv.y;
                    p1 += fmaxf(acc[mt][nt][2], 0.f) * wv.x + fmaxf(acc[mt][nt][3], 0.f) * wv.y;
                }
                p0 += __shfl_xor_sync(0xFFFFFFFFu, p0, 1);
                p0 += __shfl_xor_sync(0xFFFFFFFFu, p0, 2);
                p1 += __shfl_xor_sync(0xFFFFFFFFu, p1, 1);
                p1 += __shfl_xor_sync(0xFFFFFFFFu, p1, 2);
                if ((lane & 3) == 0) {
                    int r0 = rbase + mt * 16 + fr;
                    atomicAdd(&s_logit[r0], p0);
                    atomicAdd(&s_logit[r0 + 8], p1);
                }
            }
        }
    }
    __syncthreads();

    // ================= Layer 2 =================
    const int mg2 = w & 3, ng2 = w >> 2;
    float acc2[2][2][4];
#pragma unroll
    for (int mt = 0; mt < 2; mt++)
#pragma unroll
        for (int nt = 0; nt < 2; nt++)
#pragma unroll
            for (int q = 0; q < 4; q++) acc2[mt][nt][q] = 0.f;
#pragma unroll 2
    for (int ks = 0; ks < 8; ks++) {
        int kb = ks * 16;
        unsigned ah[2][4], al[2][4];
#pragma unroll
        for (int mt = 0; mt < 2; mt++) {
            int ra = mg2 * 32 + mt * 16 + fr;
            ah[mt][0] = *(const unsigned*)(s_hh + ra * 136 + kb + fc2);
            ah[mt][1] = *(const unsigned*)(s_hh + (ra + 8) * 136 + kb + fc2);
            ah[mt][2] = *(const unsigned*)(s_hh + ra * 136 + kb + fc2 + 8);
            ah[mt][3] = *(const unsigned*)(s_hh + (ra + 8) * 136 + kb + fc2 + 8);
            al[mt][0] = *(const unsigned*)(s_hl + ra * 136 + kb + fc2);
            al[mt][1] = *(const unsigned*)(s_hl + (ra + 8) * 136 + kb + fc2);
            al[mt][2] = *(const unsigned*)(s_hl + ra * 136 + kb + fc2 + 8);
            al[mt][3] = *(const unsigned*)(s_hl + (ra + 8) * 136 + kb + fc2 + 8);
        }
#pragma unroll
        for (int nt = 0; nt < 2; nt++) {
            int cb = ng2 * 16 + nt * 8 + fr;
            unsigned bh[2], bl[2];
            bh[0] = *(const unsigned*)(s_w2h + cb * 136 + kb + fc2);
            bh[1] = *(const unsigned*)(s_w2h + cb * 136 + kb + fc2 + 8);
            bl[0] = *(const unsigned*)(s_w2l + cb * 136 + kb + fc2);
            bl[1] = *(const unsigned*)(s_w2l + cb * 136 + kb + fc2 + 8);
#pragma unroll
            for (int mt = 0; mt < 2; mt++) {
                mma_bf16(acc2[mt][nt], ah[mt], bh);
                mma_bf16(acc2[mt][nt], ah[mt], bl);
                mma_bf16(acc2[mt][nt], al[mt], bh);
            }
        }
    }

    // ---- epilogue: out_e + exp-weighted scatter ----
#pragma unroll
    for (int mt = 0; mt < 2; mt++) {
        int r0 = mg2 * 32 + mt * 16 + fr, r1 = r0 + 8;
        int eg0 = e0 + r0, eg1 = e0 + r1;
        float ex0 = expf(s_logit[r0]);
        float ex1 = expf(s_logit[r1]);
        int d0 = s_dst[r0], d1 = s_dst[r1];
#pragma unroll
        for (int nt = 0; nt < 2; nt++) {
            int c = ng2 * 16 + nt * 8 + fc2;
            float2 b2 = __ldg((const float2*)be2 + (c >> 1));
            float v0 = acc2[mt][nt][0] + b2.x, v1 = acc2[mt][nt][1] + b2.y;
            float v2 = acc2[mt][nt][2] + b2.x, v3 = acc2[mt][nt][3] + b2.y;
            if (eg0 < nEdges) {
                *(float2*)(out_e + (size_t)eg0 * 64 + c) = make_float2(v0, v1);
                red_add2(&g_agg[d0 * 64 + c], v0 * ex0, v1 * ex0);
            }
            if (eg1 < nEdges) {
                *(float2*)(out_e + (size_t)eg1 * 64 + c) = make_float2(v2, v3);
                red_add2(&g_agg[d1 * 64 + c], v2 * ex1, v3 * ex1);
            }
        }
        if (ng2 == 0 && (lane & 3) == 0) {
            if (eg0 < nEdges) atomicAdd(&g_denom[d0], ex0);
            if (eg1 < nEdges) atomicAdd(&g_denom[d1], ex1);
        }
    }
}

// ---------------- node MLP: uh_n = MLP([agg/denom, nf]) ----------------
__global__ __launch_bounds__(256) void node_kernel(
    const float* __restrict__ nf,
    const float* __restrict__ Wn1, const float* __restrict__ bn1,
    const float* __restrict__ Wn2, const float* __restrict__ bn2,
    float* __restrict__ out_n, int nNodes) {
    extern __shared__ float sm[];
    float* s_x  = sm;               // 64*128
    float* s_w1 = s_x + 64 * 128;   // 128*128
    float* s_h  = s_w1 + 128 * 128; // 64*128
    float* s_w2 = s_h + 64 * 128;   // 128*64
    float* s_b1 = s_w2 + 128 * 64;  // 128
    float* s_b2 = s_b1 + 128;       // 64
    const int tid = threadIdx.x;
    const int n0 = blockIdx.x * 64;
    for (int i = tid; i < 128 * 128; i += 256) s_w1[i] = Wn1[i];
    for (int i = tid; i < 128 * 64; i += 256) s_w2[i] = Wn2[i];
    if (tid < 128) s_b1[tid] = bn1[tid];
    if (tid < 64)  s_b2[tid] = bn2[tid];
    for (int i = tid; i < 64 * 128; i += 256) {
        int r = i >> 7, c = i & 127;
        int n = n0 + r;
        float v = 0.f;
        if (n < nNodes) {
            if (c < 64) {
                float dn = fmaxf(g_denom[n], 1e-38f);
                v = g_agg[n * 64 + c] / dn;
            } else {
                v = nf[n * 64 + (c - 64)];
            }
        }
        s_x[i] = v;
    }
    __syncthreads();
    const int tx = tid & 31, ty = tid >> 5;
    float acc[8][4];
#pragma unroll
    for (int i = 0; i < 8; i++)
#pragma unroll
        for (int j = 0; j < 4; j++) acc[i][j] = 0.f;
#pragma unroll 4
    for (int k = 0; k < 128; k++) {
        float a[8], wv[4];
#pragma unroll
        for (int i = 0; i < 8; i++) a[i] = s_x[(ty * 8 + i) * 128 + k];
#pragma unroll
        for (int j = 0; j < 4; j++) wv[j] = s_w1[k * 128 + tx + j * 32];
#pragma unroll
        for (int i = 0; i < 8; i++)
#pragma unroll
            for (int j = 0; j < 4; j++) acc[i][j] = fmaf(a[i], wv[j], acc[i][j]);
    }
#pragma unroll
    for (int i = 0; i < 8; i++)
#pragma unroll
        for (int j = 0; j < 4; j++)
            s_h[(ty * 8 + i) * 128 + tx + j * 32] = fmaxf(acc[i][j] + s_b1[tx + j * 32], 0.f);
    __syncthreads();
    float acc2[8][2];
#pragma unroll
    for (int i = 0; i < 8; i++) { acc2[i][0] = 0.f; acc2[i][1] = 0.f; }
#pragma unroll 4
    for (int k = 0; k < 128; k++) {
        float w0 = s_w2[k * 64 + tx], w1 = s_w2[k * 64 + tx + 32];
#pragma unroll
        for (int i = 0; i < 8; i++) {
            float a = s_h[(ty * 8 + i) * 128 + k];
            acc2[i][0] = fmaf(a, w0, acc2[i][0]);
            acc2[i][1] = fmaf(a, w1, acc2[i][1]);
        }
    }
#pragma unroll
    for (int i = 0; i < 8; i++) {
        int n = n0 + ty * 8 + i;
        if (n < nNodes) {
            out_n[(size_t)n * 64 + tx]      = acc2[i][0] + s_b2[tx];
            out_n[(size_t)n * 64 + tx + 32] = acc2[i][1] + s_b2[tx + 32];
        }
    }
}

// ---------------- launch ----------------
extern "C" void kernel_launch(void* const* d_in, const int* in_sizes, int n_in,
                              void* d_out, int out_size) {
    const float* nf  = (const float*)d_in[0];
    const float* ef  = (const float*)d_in[1];
    const int*   src = (const int*)d_in[2];
    const int*   dst = (const int*)d_in[3];
    const float* We1 = (const float*)d_in[4];
    const float* be1 = (const float*)d_in[5];
    const float* We2 = (const float*)d_in[6];
    const float* be2 = (const float*)d_in[7];
    const float* Wa1 = (const float*)d_in[8];
    const float* ba1 = (const float*)d_in[9];
    const float* Wa2 = (const float*)d_in[10];
    const float* ba2 = (const float*)d_in[11];
    const float* Wn1 = (const float*)d_in[12];
    const float* bn1 = (const float*)d_in[13];
    const float* Wn2 = (const float*)d_in[14];
    const float* bn2 = (const float*)d_in[15];

    int nNodes = in_sizes[0] / 64;
    int nEdges = in_sizes[2];

    float* out   = (float*)d_out;
    float* out_n = out;                              // [N,64]
    float* out_e = out + (size_t)nNodes * 64;        // [E,64]

    int smem_pre  = (64 * 64 + 64 * 512) * 4;        // 147456
    int smem_edge = (256 * 40 * 2 + 64 * 136 * 2 + 128 * 40 * 2 + 128 * 136 * 2) * 2
                  + 128 * 4 + 2 * 128 * 4;           // 167424
    int smem_node = (64 * 128 * 2 + 128 * 128 + 128 * 64 + 192) * 4;

    cudaFuncSetAttribute(node_pre_kernel, cudaFuncAttributeMaxDynamicSharedMemorySize, smem_pre);
    cudaFuncSetAttribute(edge_kernel,     cudaFuncAttributeMaxDynamicSharedMemorySize, smem_edge);
    cudaFuncSetAttribute(node_kernel,     cudaFuncAttributeMaxDynamicSharedMemorySize, smem_node);

    pack_kernel<<<128, 256>>>(We1, Wa1, be1, ba1, We2, Wa2);
    init_kernel<<<256, 256>>>(nNodes);
    node_pre_kernel<<<(nNodes + 63) / 64, 256, smem_pre>>>(nf, nNodes);
    edge_kernel<<<(nEdges + 127) / 128, 512, smem_edge>>>(ef, src, dst, be2, ba2, out_e, nEdges);
    node_kernel<<<(nNodes + 63) / 64, 256, smem_node>>>(nf, Wn1, bn1, Wn2, bn2, out_n, nNodes);
}

// round 6
// speedup vs baseline: 1.5911x; 1.0869x over previous
#include <cuda_runtime.h>
#include <cuda_bf16.h>
#include <math.h>

#define MAX_NN 50000

// ---------------- scratch (static device memory; no allocs) ----------------
// g_pre[n][512] PERMUTED: [half(2)][ng(4)][q(4)][nt(8)][e(2)]
//   natural hidden col c (within 256-half) = ng*64 + nt*8 + q*2 + e
__device__ float g_pre[(size_t)MAX_NN * 512];
__device__ float g_denom[MAX_NN];
__device__ float g_agg[MAX_NN * 64];
__device__ float g_w1pack[64 * 512];              // permuted cols to match g_pre
__device__ __align__(16) float g_b1p[256];        // bias, same permutation (no half)
__device__ float g_wa2n[128];                     // Wa2 natural
// packed B-fragments: uint4 = {bh(k0,k1), bh(k8,k9), bl(k0,k1), bl(k8,k9)}
__device__ __align__(16) uint4 g_w1f[256 * 2 * 4];   // [cb][ks][q]
__device__ __align__(16) uint4 g_w2f[64 * 8 * 4];    // [cb][ks][q]

__device__ __forceinline__ unsigned pk2(__nv_bfloat16 a, __nv_bfloat16 b) {
    return ((unsigned)__bfloat16_as_ushort(b) << 16) | (unsigned)__bfloat16_as_ushort(a);
}

__device__ __forceinline__ void mma_bf16(float* c, const unsigned* a, const unsigned* b) {
    asm volatile(
        "mma.sync.aligned.m16n8k16.row.col.f32.bf16.bf16.f32 "
        "{%0,%1,%2,%3}, {%4,%5,%6,%7}, {%8,%9}, {%0,%1,%2,%3};"
        : "+f"(c[0]), "+f"(c[1]), "+f"(c[2]), "+f"(c[3])
        : "r"(a[0]), "r"(a[1]), "r"(a[2]), "r"(a[3]), "r"(b[0]), "r"(b[1]));
}

__device__ __forceinline__ void red_add2(float* p, float x, float y) {
    asm volatile("red.global.add.v2.f32 [%0], {%1,%2};" :: "l"(p), "f"(x), "f"(y) : "memory");
}

// W1e element: rows 128..159 of (We1|Wa1), k in [0,32), col in [0,256)
__device__ __forceinline__ float w1e_at(const float* We1, const float* Wa1, int k, int c) {
    return (c < 128) ? We1[(128 + k) * 128 + c] : Wa1[(128 + k) * 128 + (c - 128)];
}

// ---------------- weight packing ----------------
__global__ void pack_kernel(const float* __restrict__ We1, const float* __restrict__ Wa1,
                            const float* __restrict__ be1, const float* __restrict__ ba1,
                            const float* __restrict__ We2, const float* __restrict__ Wa2) {
    int i = blockIdx.x * blockDim.x + threadIdx.x;
    if (i < 64 * 512) {   // g_w1pack with permuted columns
        int k = i >> 9, pos = i & 511;
        int half = pos >> 8, wi = pos & 255;
        int ng = wi >> 6, qq = (wi >> 4) & 3, nt = (wi >> 1) & 7, e = wi & 1;
        int c = ng * 64 + nt * 8 + qq * 2 + e;
        int row = half ? (64 + k) : k;
        g_w1pack[i] = (c < 128) ? We1[row * 128 + c] : Wa1[row * 128 + (c - 128)];
    }
    if (i < 256) {        // g_b1p permuted
        int ng = i >> 6, qq = (i >> 4) & 3, nt = (i >> 1) & 7, e = i & 1;
        int c = ng * 64 + nt * 8 + qq * 2 + e;
        g_b1p[i] = (c < 128) ? be1[c] : ba1[c - 128];
    }
    if (i < 128) g_wa2n[i] = Wa2[i];
    if (i < 2048) {       // g_w1f: cb = i>>3, ks = (i>>2)&1, q = i&3
        int cb = i >> 3, ks = (i >> 2) & 1, qq = i & 3;
        int ka = ks * 16 + 2 * qq;
        float f0 = w1e_at(We1, Wa1, ka, cb),     f1 = w1e_at(We1, Wa1, ka + 1, cb);
        float f2 = w1e_at(We1, Wa1, ka + 8, cb), f3 = w1e_at(We1, Wa1, ka + 9, cb);
        __nv_bfloat16 h0 = __float2bfloat16_rn(f0), h1 = __float2bfloat16_rn(f1);
        __nv_bfloat16 h2 = __float2bfloat16_rn(f2), h3 = __float2bfloat16_rn(f3);
        uint4 v;
        v.x = pk2(h0, h1);
        v.y = pk2(h2, h3);
        v.z = pk2(__float2bfloat16_rn(f0 - __bfloat162float(h0)),
                  __float2bfloat16_rn(f1 - __bfloat162float(h1)));
        v.w = pk2(__float2bfloat16_rn(f2 - __bfloat162float(h2)),
                  __float2bfloat16_rn(f3 - __bfloat162float(h3)));
        g_w1f[i] = v;
    }
    if (i < 2048) {       // g_w2f: cb = i>>5, ks = (i>>2)&7, q = i&3
        int cb = i >> 5, ks = (i >> 2) & 7, qq = i & 3;
        int ka = ks * 16 + 2 * qq;
        float f0 = We2[ka * 64 + cb],       f1 = We2[(ka + 1) * 64 + cb];
        float f2 = We2[(ka + 8) * 64 + cb], f3 = We2[(ka + 9) * 64 + cb];
        __nv_bfloat16 h0 = __float2bfloat16_rn(f0), h1 = __float2bfloat16_rn(f1);
        __nv_bfloat16 h2 = __float2bfloat16_rn(f2), h3 = __float2bfloat16_rn(f3);
        uint4 v;
        v.x = pk2(h0, h1);
        v.y = pk2(h2, h3);
        v.z = pk2(__float2bfloat16_rn(f0 - __bfloat162float(h0)),
                  __float2bfloat16_rn(f1 - __bfloat162float(h1)));
        v.w = pk2(__float2bfloat16_rn(f2 - __bfloat162float(h2)),
                  __float2bfloat16_rn(f3 - __bfloat162float(h3)));
        g_w2f[i] = v;
    }
}

__global__ void init_kernel(int nNodes) {
    int i = blockIdx.x * blockDim.x + threadIdx.x;
    int stride = gridDim.x * blockDim.x;
    float4* a4 = (float4*)g_agg;
    for (int j = i; j < nNodes * 16; j += stride) a4[j] = make_float4(0.f, 0.f, 0.f, 0.f);
    for (int j = i; j < nNodes; j += stride) g_denom[j] = 0.f;
}

// ---------------- node precompute GEMM: pre = nf @ W1pack  [N,64]@[64,512] ----------------
__global__ __launch_bounds__(256) void node_pre_kernel(const float* __restrict__ nf, int nNodes) {
    extern __shared__ float sm[];
    float* s_a = sm;            // 64x64
    float* s_w = sm + 64 * 64;  // 64x512
    const int tid = threadIdx.x;
    {
        float4* sw4 = (float4*)s_w;
        const float4* gw4 = (const float4*)g_w1pack;
        for (int i = tid; i < 64 * 128; i += 256) sw4[i] = gw4[i];
    }
    int n0 = blockIdx.x * 64;
    for (int i = tid; i < 64 * 64; i += 256) {
        int r = i >> 6, c = i & 63;
        int n = n0 + r;
        s_a[i] = (n < nNodes) ? nf[n * 64 + c] : 0.f;
    }
    __syncthreads();
    const int tx = tid & 31, ty = tid >> 5;
    float acc[8][16];
#pragma unroll
    for (int i = 0; i < 8; i++)
#pragma unroll
        for (int j = 0; j < 16; j++) acc[i][j] = 0.f;
    const float4* sw4 = (const float4*)s_w;
#pragma unroll 2
    for (int k = 0; k < 64; k++) {
        float a[8];
        float4 w[4];
#pragma unroll
        for (int i = 0; i < 8; i++) a[i] = s_a[(ty * 8 + i) * 64 + k];
#pragma unroll
        for (int m = 0; m < 4; m++) w[m] = sw4[k * 128 + tx * 4 + m];
#pragma unroll
        for (int i = 0; i < 8; i++) {
#pragma unroll
            for (int m = 0; m < 4; m++) {
                acc[i][m * 4 + 0] = fmaf(a[i], w[m].x, acc[i][m * 4 + 0]);
                acc[i][m * 4 + 1] = fmaf(a[i], w[m].y, acc[i][m * 4 + 1]);
                acc[i][m * 4 + 2] = fmaf(a[i], w[m].z, acc[i][m * 4 + 2]);
                acc[i][m * 4 + 3] = fmaf(a[i], w[m].w, acc[i][m * 4 + 3]);
            }
        }
    }
    float4* gp4 = (float4*)g_pre;
#pragma unroll
    for (int i = 0; i < 8; i++) {
        int n = n0 + ty * 8 + i;
        if (n < nNodes) {
#pragma unroll
            for (int m = 0; m < 4; m++)
                gp4[(size_t)n * 128 + tx * 4 + m] =
                    make_float4(acc[i][m * 4 + 0], acc[i][m * 4 + 1],
                                acc[i][m * 4 + 2], acc[i][m * 4 + 3]);
        }
    }
}

// ---------------- fused edge kernel (bf16x3 tensor-core, 1024 threads) ----------------
// 128 edges/block, 32 warps. Layer1: warp = m16 (mg=w&7) x n64 (ng=w>>3).
// Layer2: warp = m16 (mg) x n16 (ng2=w>>3, over 64 cols).
__global__ __launch_bounds__(1024, 1) void edge_kernel(
    const float* __restrict__ ef, const int* __restrict__ src, const int* __restrict__ dst,
    const float* __restrict__ be2, const float* __restrict__ ba2,
    float* __restrict__ out_e, int nEdges) {
    extern __shared__ char smraw[];
    __nv_bfloat16* s_efh = (__nv_bfloat16*)smraw;          // 128*40
    __nv_bfloat16* s_efl = s_efh + 128 * 40;               // 128*40
    __nv_bfloat16* s_hh  = s_efl + 128 * 40;               // 128*136
    __nv_bfloat16* s_hl  = s_hh + 128 * 136;               // 128*136
    float* s_logit = (float*)(s_hl + 128 * 136);           // 128
    int*   s_src   = (int*)(s_logit + 128);                // 128
    int*   s_dst   = s_src + 128;                          // 128

    const int tid = threadIdx.x;
    const int e0 = blockIdx.x * 128;
    const int lane = tid & 31, w = tid >> 5;
    const int fr = lane >> 2, q = lane & 3, fc2 = q * 2;

    // ---- stage ef (bf16 split), indices, logit init ----
    if (tid < 128) s_logit[tid] = __ldg(ba2);
    for (int i = tid; i < 128; i += 1024) {
        int e = e0 + i;
        s_src[i] = (e < nEdges) ? __ldg(src + e) : 0;
        s_dst[i] = (e < nEdges) ? __ldg(dst + e) : 0;
    }
    for (int i = tid; i < 128 * 32; i += 1024) {
        int r = i >> 5, c = i & 31;
        int e = e0 + r;
        float v = (e < nEdges) ? __ldg(ef + (size_t)e * 32 + c) : 0.f;
        __nv_bfloat16 h = __float2bfloat16_rn(v);
        s_efh[r * 40 + c] = h;
        s_efl[r * 40 + c] = __float2bfloat16_rn(v - __bfloat162float(h));
    }
    __syncthreads();

    const int mg = w & 7, ng = w >> 3;
    const int r0 = mg * 16 + fr, r1 = r0 + 8;

    // ================= Layer 1 =================
    {
        float acc[8][4];
        // gather-init (permuted g_pre: contiguous 64B per pointer)
        {
            const float4* P = (const float4*)g_pre;
            int off = ng * 16 + q * 4;
            size_t bs0 = (size_t)s_src[r0] * 128 + off;
            size_t bd0 = (size_t)s_dst[r0] * 128 + 64 + off;
            size_t bs1 = (size_t)s_src[r1] * 128 + off;
            size_t bd1 = (size_t)s_dst[r1] * 128 + 64 + off;
            const float4* B = (const float4*)g_b1p + off;
#pragma unroll
            for (int i = 0; i < 4; i++) {
                float4 bv = __ldg(B + i);
                float4 a = __ldg(P + bs0 + i), b = __ldg(P + bd0 + i);
                acc[2 * i][0]     = a.x + b.x + bv.x;
                acc[2 * i][1]     = a.y + b.y + bv.y;
                acc[2 * i + 1][0] = a.z + b.z + bv.z;
                acc[2 * i + 1][1] = a.w + b.w + bv.w;
                float4 c2 = __ldg(P + bs1 + i), d2 = __ldg(P + bd1 + i);
                acc[2 * i][2]     = c2.x + d2.x + bv.x;
                acc[2 * i][3]     = c2.y + d2.y + bv.y;
                acc[2 * i + 1][2] = c2.z + d2.z + bv.z;
                acc[2 * i + 1][3] = c2.w + d2.w + bv.w;
            }
        }
        // += ef @ W1e (bf16x3)
#pragma unroll
        for (int ks = 0; ks < 2; ks++) {
            int kb = ks * 16;
            unsigned ah[4], al[4];
            ah[0] = *(const unsigned*)(s_efh + r0 * 40 + kb + fc2);
            ah[1] = *(const unsigned*)(s_efh + r1 * 40 + kb + fc2);
            ah[2] = *(const unsigned*)(s_efh + r0 * 40 + kb + fc2 + 8);
            ah[3] = *(const unsigned*)(s_efh + r1 * 40 + kb + fc2 + 8);
            al[0] = *(const unsigned*)(s_efl + r0 * 40 + kb + fc2);
            al[1] = *(const unsigned*)(s_efl + r1 * 40 + kb + fc2);
            al[2] = *(const unsigned*)(s_efl + r0 * 40 + kb + fc2 + 8);
            al[3] = *(const unsigned*)(s_efl + r1 * 40 + kb + fc2 + 8);
#pragma unroll
            for (int nt = 0; nt < 8; nt++) {
                int cb = ng * 64 + nt * 8 + fr;
                uint4 wb = __ldg(g_w1f + (cb * 2 + ks) * 4 + q);
                unsigned bh[2] = {wb.x, wb.y};
                unsigned bl[2] = {wb.z, wb.w};
                mma_bf16(acc[nt], ah, bh);
                mma_bf16(acc[nt], ah, bl);
                mma_bf16(acc[nt], al, bh);
            }
        }
        // ReLU: We-half -> smem bf16-split; Wa-half -> logit partials
        if (ng < 2) {
#pragma unroll
            for (int nt = 0; nt < 8; nt++) {
                int c = ng * 64 + nt * 8 + fc2;
                float v0 = fmaxf(acc[nt][0], 0.f), v1 = fmaxf(acc[nt][1], 0.f);
                float v2 = fmaxf(acc[nt][2], 0.f), v3 = fmaxf(acc[nt][3], 0.f);
                __nv_bfloat16 h0 = __float2bfloat16_rn(v0), h1 = __float2bfloat16_rn(v1);
                __nv_bfloat16 h2 = __float2bfloat16_rn(v2), h3 = __float2bfloat16_rn(v3);
                *(unsigned*)(s_hh + r0 * 136 + c) = pk2(h0, h1);
                *(unsigned*)(s_hh + r1 * 136 + c) = pk2(h2, h3);
                *(unsigned*)(s_hl + r0 * 136 + c) =
                    pk2(__float2bfloat16_rn(v0 - __bfloat162float(h0)),
                        __float2bfloat16_rn(v1 - __bfloat162float(h1)));
                *(unsigned*)(s_hl + r1 * 136 + c) =
                    pk2(__float2bfloat16_rn(v2 - __bfloat162float(h2)),
                        __float2bfloat16_rn(v3 - __bfloat162float(h3)));
            }
        } else {
            float p0 = 0.f, p1 = 0.f;
#pragma unroll
            for (int nt = 0; nt < 8; nt++) {
                int c = (ng - 2) * 64 + nt * 8 + fc2;
                float2 wv = __ldg((const float2*)g_wa2n + (c >> 1));
                p0 += fmaxf(acc[nt][0], 0.f) * wv.x + fmaxf(acc[nt][1], 0.f) * wv.y;
                p1 += fmaxf(acc[nt][2], 0.f) * wv.x + fmaxf(acc[nt][3], 0.f) * wv.y;
            }
            p0 += __shfl_xor_sync(0xFFFFFFFFu, p0, 1);
            p0 += __shfl_xor_sync(0xFFFFFFFFu, p0, 2);
            p1 += __shfl_xor_sync(0xFFFFFFFFu, p1, 1);
            p1 += __shfl_xor_sync(0xFFFFFFFFu, p1, 2);
            if (q == 0) {
                atomicAdd(&s_logit[r0], p0);
                atomicAdd(&s_logit[r1], p1);
            }
        }
    }
    __syncthreads();

    // ================= Layer 2 =================
    const int ng2 = w >> 3;
    float acc2[2][4];
#pragma unroll
    for (int nt = 0; nt < 2; nt++)
#pragma unroll
        for (int j = 0; j < 4; j++) acc2[nt][j] = 0.f;
#pragma unroll
    for (int ks = 0; ks < 8; ks++) {
        int kb = ks * 16;
        unsigned ah[4], al[4];
        ah[0] = *(const unsigned*)(s_hh + r0 * 136 + kb + fc2);
        ah[1] = *(const unsigned*)(s_hh + r1 * 136 + kb + fc2);
        ah[2] = *(const unsigned*)(s_hh + r0 * 136 + kb + fc2 + 8);
        ah[3] = *(const unsigned*)(s_hh + r1 * 136 + kb + fc2 + 8);
        al[0] = *(const unsigned*)(s_hl + r0 * 136 + kb + fc2);
        al[1] = *(const unsigned*)(s_hl + r1 * 136 + kb + fc2);
        al[2] = *(const unsigned*)(s_hl + r0 * 136 + kb + fc2 + 8);
        al[3] = *(const unsigned*)(s_hl + r1 * 136 + kb + fc2 + 8);
#pragma unroll
        for (int nt = 0; nt < 2; nt++) {
            int cb = ng2 * 16 + nt * 8 + fr;
            uint4 wb = __ldg(g_w2f + (cb * 8 + ks) * 4 + q);
            unsigned bh[2] = {wb.x, wb.y};
            unsigned bl[2] = {wb.z, wb.w};
            mma_bf16(acc2[nt], ah, bh);
            mma_bf16(acc2[nt], ah, bl);
            mma_bf16(acc2[nt], al, bh);
        }
    }

    // ---- epilogue: out_e + exp-weighted scatter ----
    {
        float ex0 = expf(s_logit[r0]);
        float ex1 = expf(s_logit[r1]);
        int d0 = s_dst[r0], d1 = s_dst[r1];
        int eg0 = e0 + r0, eg1 = e0 + r1;
#pragma unroll
        for (int nt = 0; nt < 2; nt++) {
            int c = ng2 * 16 + nt * 8 + fc2;
            float2 b2 = __ldg((const float2*)be2 + (c >> 1));
            float v0 = acc2[nt][0] + b2.x, v1 = acc2[nt][1] + b2.y;
            float v2 = acc2[nt][2] + b2.x, v3 = acc2[nt][3] + b2.y;
            if (eg0 < nEdges) {
                *(float2*)(out_e + (size_t)eg0 * 64 + c) = make_float2(v0, v1);
                red_add2(&g_agg[d0 * 64 + c], v0 * ex0, v1 * ex0);
            }
            if (eg1 < nEdges) {
                *(float2*)(out_e + (size_t)eg1 * 64 + c) = make_float2(v2, v3);
                red_add2(&g_agg[d1 * 64 + c], v2 * ex1, v3 * ex1);
            }
        }
        if (ng2 == 0 && q == 0) {
            if (eg0 < nEdges) atomicAdd(&g_denom[d0], ex0);
            if (eg1 < nEdges) atomicAdd(&g_denom[d1], ex1);
        }
    }
}

// ---------------- node MLP: uh_n = MLP([agg/denom, nf]) ----------------
__global__ __launch_bounds__(256) void node_kernel(
    const float* __restrict__ nf,
    const float* __restrict__ Wn1, const float* __restrict__ bn1,
    const float* __restrict__ Wn2, const float* __restrict__ bn2,
    float* __restrict__ out_n, int nNodes) {
    extern __shared__ float sm[];
    float* s_x  = sm;               // 64*128
    float* s_w1 = s_x + 64 * 128;   // 128*128
    float* s_h  = s_w1 + 128 * 128; // 64*128
    float* s_w2 = s_h + 64 * 128;   // 128*64
    float* s_b1 = s_w2 + 128 * 64;  // 128
    float* s_b2 = s_b1 + 128;       // 64
    const int tid = threadIdx.x;
    const int n0 = blockIdx.x * 64;
    for (int i = tid; i < 128 * 128; i += 256) s_w1[i] = Wn1[i];
    for (int i = tid; i < 128 * 64; i += 256) s_w2[i] = Wn2[i];
    if (tid < 128) s_b1[tid] = bn1[tid];
    if (tid < 64)  s_b2[tid] = bn2[tid];
    for (int i = tid; i < 64 * 128; i += 256) {
        int r = i >> 7, c = i & 127;
        int n = n0 + r;
        float v = 0.f;
        if (n < nNodes) {
            if (c < 64) {
                float dn = fmaxf(g_denom[n], 1e-38f);
                v = g_agg[n * 64 + c] / dn;
            } else {
                v = nf[n * 64 + (c - 64)];
            }
        }
        s_x[i] = v;
    }
    __syncthreads();
    const int tx = tid & 31, ty = tid >> 5;
    float acc[8][4];
#pragma unroll
    for (int i = 0; i < 8; i++)
#pragma unroll
        for (int j = 0; j < 4; j++) acc[i][j] = 0.f;
#pragma unroll 4
    for (int k = 0; k < 128; k++) {
        float a[8], wv[4];
#pragma unroll
        for (int i = 0; i < 8; i++) a[i] = s_x[(ty * 8 + i) * 128 + k];
#pragma unroll
        for (int j = 0; j < 4; j++) wv[j] = s_w1[k * 128 + tx + j * 32];
#pragma unroll
        for (int i = 0; i < 8; i++)
#pragma unroll
            for (int j = 0; j < 4; j++) acc[i][j] = fmaf(a[i], wv[j], acc[i][j]);
    }
#pragma unroll
    for (int i = 0; i < 8; i++)
#pragma unroll
        for (int j = 0; j < 4; j++)
            s_h[(ty * 8 + i) * 128 + tx + j * 32] = fmaxf(acc[i][j] + s_b1[tx + j * 32], 0.f);
    __syncthreads();
    float acc2[8][2];
#pragma unroll
    for (int i = 0; i < 8; i++) { acc2[i][0] = 0.f; acc2[i][1] = 0.f; }
#pragma unroll 4
    for (int k = 0; k < 128; k++) {
        float w0 = s_w2[k * 64 + tx], w1 = s_w2[k * 64 + tx + 32];
#pragma unroll
        for (int i = 0; i < 8; i++) {
            float a = s_h[(ty * 8 + i) * 128 + k];
            acc2[i][0] = fmaf(a, w0, acc2[i][0]);
            acc2[i][1] = fmaf(a, w1, acc2[i][1]);
        }
    }
#pragma unroll
    for (int i = 0; i < 8; i++) {
        int n = n0 + ty * 8 + i;
        if (n < nNodes) {
            out_n[(size_t)n * 64 + tx]      = acc2[i][0] + s_b2[tx];
            out_n[(size_t)n * 64 + tx + 32] = acc2[i][1] + s_b2[tx + 32];
        }
    }
}

// ---------------- launch ----------------
extern "C" void kernel_launch(void* const* d_in, const int* in_sizes, int n_in,
                              void* d_out, int out_size) {
    const float* nf  = (const float*)d_in[0];
    const float* ef  = (const float*)d_in[1];
    const int*   src = (const int*)d_in[2];
    const int*   dst = (const int*)d_in[3];
    const float* We1 = (const float*)d_in[4];
    const float* be1 = (const float*)d_in[5];
    const float* We2 = (const float*)d_in[6];
    const float* be2 = (const float*)d_in[7];
    const float* Wa1 = (const float*)d_in[8];
    const float* ba1 = (const float*)d_in[9];
    const float* Wa2 = (const float*)d_in[10];
    const float* ba2 = (const float*)d_in[11];
    const float* Wn1 = (const float*)d_in[12];
    const float* bn1 = (const float*)d_in[13];
    const float* Wn2 = (const float*)d_in[14];
    const float* bn2 = (const float*)d_in[15];

    int nNodes = in_sizes[0] / 64;
    int nEdges = in_sizes[2];

    float* out   = (float*)d_out;
    float* out_n = out;                              // [N,64]
    float* out_e = out + (size_t)nNodes * 64;        // [E,64]

    int smem_pre  = (64 * 64 + 64 * 512) * 4;        // 147456
    int smem_edge = (128 * 40 * 2 + 128 * 136 * 2) * 2 + 128 * 4 + 2 * 128 * 4;  // 91648
    int smem_node = (64 * 128 * 2 + 128 * 128 + 128 * 64 + 192) * 4;

    cudaFuncSetAttribute(node_pre_kernel, cudaFuncAttributeMaxDynamicSharedMemorySize, smem_pre);
    cudaFuncSetAttribute(edge_kernel,     cudaFuncAttributeMaxDynamicSharedMemorySize, smem_edge);
    cudaFuncSetAttribute(node_kernel,     cudaFuncAttributeMaxDynamicSharedMemorySize, smem_node);

    pack_kernel<<<128, 256>>>(We1, Wa1, be1, ba1, We2, Wa2);
    init_kernel<<<256, 256>>>(nNodes);
    node_pre_kernel<<<(nNodes + 63) / 64, 256, smem_pre>>>(nf, nNodes);
    edge_kernel<<<(nEdges + 127) / 128, 1024, smem_edge>>>(ef, src, dst, be2, ba2, out_e, nEdges);
    node_kernel<<<(nNodes + 63) / 64, 256, smem_node>>>(nf, Wn1, bn1, Wn2, bn2, out_n, nNodes);
}

// round 10
// speedup vs baseline: 2.1130x; 1.3280x over previous
#include <cuda_runtime.h>
#include <cuda_bf16.h>
#include <math.h>

#define MAX_NN 50000

// ---------------- scratch (static device memory; no allocs) ----------------
// g_pre[n][512] PERMUTED: pos = gi*64 + q*16 + nt*2 + e, gi = half*4+ng
//   natural col C = half*256 + ng*64 + nt*8 + q*2 + e
__device__ float g_pre[(size_t)MAX_NN * 512];
__device__ float g_denom[MAX_NN];
__device__ float g_agg[MAX_NN * 64];
__device__ __align__(16) float g_b1p[256];        // layer1 bias, permuted (no half)
__device__ float g_wa2n[128];                     // Wa2 natural
// packed B-fragments: uint4 = {bh(k0,k1), bh(k8,k9), bl(k0,k1), bl(k8,k9)}
__device__ __align__(16) uint4 g_w1f[256 * 2 * 4];    // edge W1e   [cb][ks(2)][q]
__device__ __align__(16) uint4 g_w2f[64 * 8 * 4];     // edge We2   [cb][ks(8)][q]
__device__ __align__(16) uint4 g_w1pf[512 * 4 * 4];   // node-pre W [cb][ks(4)][q]
__device__ __align__(16) uint4 g_wn1f[128 * 8 * 4];   // node Wn1   [cb][ks(8)][q]
__device__ __align__(16) uint4 g_wn2f[64 * 8 * 4];    // node Wn2   [cb][ks(8)][q]

__device__ __forceinline__ unsigned pk2(__nv_bfloat16 a, __nv_bfloat16 b) {
    return ((unsigned)__bfloat16_as_ushort(b) << 16) | (unsigned)__bfloat16_as_ushort(a);
}

__device__ __forceinline__ uint4 mk_frag(float f0, float f1, float f2, float f3) {
    __nv_bfloat16 h0 = __float2bfloat16_rn(f0), h1 = __float2bfloat16_rn(f1);
    __nv_bfloat16 h2 = __float2bfloat16_rn(f2), h3 = __float2bfloat16_rn(f3);
    uint4 v;
    v.x = pk2(h0, h1);
    v.y = pk2(h2, h3);
    v.z = pk2(__float2bfloat16_rn(f0 - __bfloat162float(h0)),
              __float2bfloat16_rn(f1 - __bfloat162float(h1)));
    v.w = pk2(__float2bfloat16_rn(f2 - __bfloat162float(h2)),
              __float2bfloat16_rn(f3 - __bfloat162float(h3)));
    return v;
}

__device__ __forceinline__ void mma_bf16(float* c, const unsigned* a, const unsigned* b) {
    asm volatile(
        "mma.sync.aligned.m16n8k16.row.col.f32.bf16.bf16.f32 "
        "{%0,%1,%2,%3}, {%4,%5,%6,%7}, {%8,%9}, {%0,%1,%2,%3};"
        : "+f"(c[0]), "+f"(c[1]), "+f"(c[2]), "+f"(c[3])
        : "r"(a[0]), "r"(a[1]), "r"(a[2]), "r"(a[3]), "r"(b[0]), "r"(b[1]));
}

__device__ __forceinline__ void red_add2(float* p, float x, float y) {
    asm volatile("red.global.add.v2.f32 [%0], {%1,%2};" :: "l"(p), "f"(x), "f"(y) : "memory");
}

__device__ __forceinline__ void split_st(float v, __nv_bfloat16* ph, __nv_bfloat16* pl) {
    __nv_bfloat16 h = __float2bfloat16_rn(v);
    *ph = h;
    *pl = __float2bfloat16_rn(v - __bfloat162float(h));
}

// W1e element: rows 128..159 of (We1|Wa1), k in [0,32), col in [0,256)
__device__ __forceinline__ float w1e_at(const float* We1, const float* Wa1, int k, int c) {
    return (c < 128) ? We1[(128 + k) * 128 + c] : Wa1[(128 + k) * 128 + (c - 128)];
}
// node-pre big-W element: natural out col C in [0,512), k in [0,64)
__device__ __forceinline__ float wpre_at(const float* We1, const float* Wa1, int k, int C) {
    int half = C >> 8, c = C & 255;
    int row = half * 64 + k;
    return (c < 128) ? We1[row * 128 + c] : Wa1[row * 128 + (c - 128)];
}

// ---------------- weight packing ----------------
__global__ void pack_kernel(const float* __restrict__ We1, const float* __restrict__ Wa1,
                            const float* __restrict__ be1, const float* __restrict__ ba1,
                            const float* __restrict__ We2, const float* __restrict__ Wa2,
                            const float* __restrict__ Wn1, const float* __restrict__ Wn2) {
    int i = blockIdx.x * blockDim.x + threadIdx.x;
    if (i < 256) {        // g_b1p permuted
        int ng = i >> 6, qq = (i >> 4) & 3, nt = (i >> 1) & 7, e = i & 1;
        int c = ng * 64 + nt * 8 + qq * 2 + e;
        g_b1p[i] = (c < 128) ? be1[c] : ba1[c - 128];
    }
    if (i < 128) g_wa2n[i] = Wa2[i];
    if (i < 2048) {       // g_w1f: cb = i>>3, ks = (i>>2)&1, q = i&3
        int cb = i >> 3, ks = (i >> 2) & 1, qq = i & 3;
        int ka = ks * 16 + 2 * qq;
        g_w1f[i] = mk_frag(w1e_at(We1, Wa1, ka, cb),     w1e_at(We1, Wa1, ka + 1, cb),
                           w1e_at(We1, Wa1, ka + 8, cb), w1e_at(We1, Wa1, ka + 9, cb));
    }
    if (i < 2048) {       // g_w2f: cb = i>>5, ks = (i>>2)&7, q = i&3
        int cb = i >> 5, ks = (i >> 2) & 7, qq = i & 3;
        int ka = ks * 16 + 2 * qq;
        g_w2f[i] = mk_frag(We2[ka * 64 + cb],       We2[(ka + 1) * 64 + cb],
                           We2[(ka + 8) * 64 + cb], We2[(ka + 9) * 64 + cb]);
    }
    if (i < 8192) {       // g_w1pf: cb = i>>4, ks = (i>>2)&3, q = i&3
        int cb = i >> 4, ks = (i >> 2) & 3, qq = i & 3;
        int ka = ks * 16 + 2 * qq;
        g_w1pf[i] = mk_frag(wpre_at(We1, Wa1, ka, cb),     wpre_at(We1, Wa1, ka + 1, cb),
                            wpre_at(We1, Wa1, ka + 8, cb), wpre_at(We1, Wa1, ka + 9, cb));
    }
    if (i < 4096) {       // g_wn1f: cb = i>>5, ks = (i>>2)&7, q = i&3
        int cb = i >> 5, ks = (i >> 2) & 7, qq = i & 3;
        int ka = ks * 16 + 2 * qq;
        g_wn1f[i] = mk_frag(Wn1[ka * 128 + cb],       Wn1[(ka + 1) * 128 + cb],
                            Wn1[(ka + 8) * 128 + cb], Wn1[(ka + 9) * 128 + cb]);
    }
    if (i < 2048) {       // g_wn2f: cb = i>>5, ks = (i>>2)&7, q = i&3
        int cb = i >> 5, ks = (i >> 2) & 7, qq = i & 3;
        int ka = ks * 16 + 2 * qq;
        g_wn2f[i] = mk_frag(Wn2[ka * 64 + cb],       Wn2[(ka + 1) * 64 + cb],
                            Wn2[(ka + 8) * 64 + cb], Wn2[(ka + 9) * 64 + cb]);
    }
}

__global__ void init_kernel(int nNodes) {
    int i = blockIdx.x * blockDim.x + threadIdx.x;
    int stride = gridDim.x * blockDim.x;
    float4* a4 = (float4*)g_agg;
    for (int j = i; j < nNodes * 16; j += stride) a4[j] = make_float4(0.f, 0.f, 0.f, 0.f);
    for (int j = i; j < nNodes; j += stride) g_denom[j] = 0.f;
}

// ---------------- node precompute (mma): pre = nf @ Wbig  [N,64]@[64,512] ----------------
// 64 nodes/block, 256 threads = 8 warps: mg = w&3 (m16), ngw = w>>2; col groups gi = nl*2+ngw
__global__ __launch_bounds__(256) void node_pre_kernel(const float* __restrict__ nf, int nNodes) {
    extern __shared__ char smraw[];
    __nv_bfloat16* s_ah = (__nv_bfloat16*)smraw;   // 64*72
    __nv_bfloat16* s_al = s_ah + 64 * 72;          // 64*72
    const int tid = threadIdx.x;
    const int lane = tid & 31, w = tid >> 5;
    const int fr = lane >> 2, q = lane & 3, fc2 = q * 2;
    const int n0 = blockIdx.x * 64;

    for (int i = tid; i < 64 * 64; i += 256) {
        int r = i >> 6, c = i & 63;
        int n = n0 + r;
        float v = (n < nNodes) ? __ldg(nf + (size_t)n * 64 + c) : 0.f;
        split_st(v, s_ah + r * 72 + c, s_al + r * 72 + c);
    }
    __syncthreads();

    const int mg = w & 3, ngw = w >> 2;
    const int r0 = mg * 16 + fr, r1 = r0 + 8;

    // preload A fragments for all 4 ksteps (reused across 4 col groups)
    unsigned ah[4][4], al[4][4];
#pragma unroll
    for (int ks = 0; ks < 4; ks++) {
        int kb = ks * 16;
        ah[ks][0] = *(const unsigned*)(s_ah + r0 * 72 + kb + fc2);
        ah[ks][1] = *(const unsigned*)(s_ah + r1 * 72 + kb + fc2);
        ah[ks][2] = *(const unsigned*)(s_ah + r0 * 72 + kb + fc2 + 8);
        ah[ks][3] = *(const unsigned*)(s_ah + r1 * 72 + kb + fc2 + 8);
        al[ks][0] = *(const unsigned*)(s_al + r0 * 72 + kb + fc2);
        al[ks][1] = *(const unsigned*)(s_al + r1 * 72 + kb + fc2);
        al[ks][2] = *(const unsigned*)(s_al + r0 * 72 + kb + fc2 + 8);
        al[ks][3] = *(const unsigned*)(s_al + r1 * 72 + kb + fc2 + 8);
    }

#pragma unroll
    for (int nl = 0; nl < 4; nl++) {
        int gi = nl * 2 + ngw;
        float acc[8][4];
#pragma unroll
        for (int nt = 0; nt < 8; nt++)
#pragma unroll
            for (int j = 0; j < 4; j++) acc[nt][j] = 0.f;
#pragma unroll
        for (int ks = 0; ks < 4; ks++) {
#pragma unroll
            for (int nt = 0; nt < 8; nt++) {
                int cbn = gi * 64 + nt * 8 + fr;
                uint4 wb = __ldg(g_w1pf + (cbn * 4 + ks) * 4 + q);
                unsigned bh[2] = {wb.x, wb.y};
                unsigned bl[2] = {wb.z, wb.w};
                mma_bf16(acc[nt], ah[ks], bh);
                mma_bf16(acc[nt], ah[ks], bl);
                mma_bf16(acc[nt], al[ks], bh);
            }
        }
        // store: row r floats at pos gi*64 + q*16 + nt*2 + e  (float4 m: nt = 2m,2m+1)
        float4* gp4 = (float4*)g_pre;
        int nr0 = n0 + r0, nr1 = n0 + r1;
        if (nr0 < nNodes) {
#pragma unroll
            for (int m = 0; m < 4; m++)
                gp4[(size_t)nr0 * 128 + gi * 16 + q * 4 + m] =
                    make_float4(acc[2 * m][0], acc[2 * m][1], acc[2 * m + 1][0], acc[2 * m + 1][1]);
        }
        if (nr1 < nNodes) {
#pragma unroll
            for (int m = 0; m < 4; m++)
                gp4[(size_t)nr1 * 128 + gi * 16 + q * 4 + m] =
                    make_float4(acc[2 * m][2], acc[2 * m][3], acc[2 * m + 1][2], acc[2 * m + 1][3]);
        }
    }
}

// ---------------- fused edge kernel (bf16x3 mma, 512 threads, 2 CTA/SM) ----------------
// 64 edges/block, 16 warps. Layer1: warp = m16 (mg=w&3) x n64 (ng=w>>2).
// Layer2: warp = m16 x n16 (ng2=w>>2).
__global__ __launch_bounds__(512, 2) void edge_kernel(
    const float* __restrict__ ef, const int* __restrict__ src, const int* __restrict__ dst,
    const float* __restrict__ be2, const float* __restrict__ ba2,
    float* __restrict__ out_e, int nEdges) {
    extern __shared__ char smraw[];
    __nv_bfloat16* s_efh = (__nv_bfloat16*)smraw;          // 64*40
    __nv_bfloat16* s_efl = s_efh + 64 * 40;                // 64*40
    __nv_bfloat16* s_hh  = s_efl + 64 * 40;                // 64*136
    __nv_bfloat16* s_hl  = s_hh + 64 * 136;                // 64*136
    float* s_logit = (float*)(s_hl + 64 * 136);            // 64
    int*   s_src   = (int*)(s_logit + 64);                 // 64
    int*   s_dst   = s_src + 64;                           // 64

    const int tid = threadIdx.x;
    const int e0 = blockIdx.x * 64;
    const int lane = tid & 31, w = tid >> 5;
    const int fr = lane >> 2, q = lane & 3, fc2 = q * 2;

    // ---- stage ef (bf16 split), indices, logit init ----
    if (tid < 64) s_logit[tid] = __ldg(ba2);
    if (tid >= 64 && tid < 128) {
        int i = tid - 64;
        int e = e0 + i;
        s_src[i] = (e < nEdges) ? __ldg(src + e) : 0;
        s_dst[i] = (e < nEdges) ? __ldg(dst + e) : 0;
    }
    for (int i = tid; i < 64 * 32; i += 512) {
        int r = i >> 5, c = i & 31;
        int e = e0 + r;
        float v = (e < nEdges) ? __ldg(ef + (size_t)e * 32 + c) : 0.f;
        split_st(v, s_efh + r * 40 + c, s_efl + r * 40 + c);
    }
    __syncthreads();

    const int mg = w & 3, ng = w >> 2;
    const int r0 = mg * 16 + fr, r1 = r0 + 8;

    // ================= Layer 1 =================
    {
        float acc[8][4];
        // gather-init (permuted g_pre: contiguous 64B per pointer)
        {
            const float4* P = (const float4*)g_pre;
            int off = ng * 16 + q * 4;
            size_t bs0 = (size_t)s_src[r0] * 128 + off;
            size_t bd0 = (size_t)s_dst[r0] * 128 + 64 + off;
            size_t bs1 = (size_t)s_src[r1] * 128 + off;
            size_t bd1 = (size_t)s_dst[r1] * 128 + 64 + off;
            const float4* B = (const float4*)g_b1p + off;
#pragma unroll
            for (int i = 0; i < 4; i++) {
                float4 bv = __ldg(B + i);
                float4 a = __ldg(P + bs0 + i), b = __ldg(P + bd0 + i);
                acc[2 * i][0]     = a.x + b.x + bv.x;
                acc[2 * i][1]     = a.y + b.y + bv.y;
                acc[2 * i + 1][0] = a.z + b.z + bv.z;
                acc[2 * i + 1][1] = a.w + b.w + bv.w;
                float4 c2 = __ldg(P + bs1 + i), d2 = __ldg(P + bd1 + i);
                acc[2 * i][2]     = c2.x + d2.x + bv.x;
                acc[2 * i][3]     = c2.y + d2.y + bv.y;
                acc[2 * i + 1][2] = c2.z + d2.z + bv.z;
                acc[2 * i + 1][3] = c2.w + d2.w + bv.w;
            }
        }
        // += ef @ W1e (bf16x3)
#pragma unroll
        for (int ks = 0; ks < 2; ks++) {
            int kb = ks * 16;
            unsigned ah[4], al[4];
            ah[0] = *(const unsigned*)(s_efh + r0 * 40 + kb + fc2);
            ah[1] = *(const unsigned*)(s_efh + r1 * 40 + kb + fc2);
            ah[2] = *(const unsigned*)(s_efh + r0 * 40 + kb + fc2 + 8);
            ah[3] = *(const unsigned*)(s_efh + r1 * 40 + kb + fc2 + 8);
            al[0] = *(const unsigned*)(s_efl + r0 * 40 + kb + fc2);
            al[1] = *(const unsigned*)(s_efl + r1 * 40 + kb + fc2);
            al[2] = *(const unsigned*)(s_efl + r0 * 40 + kb + fc2 + 8);
            al[3] = *(const unsigned*)(s_efl + r1 * 40 + kb + fc2 + 8);
#pragma unroll
            for (int nt = 0; nt < 8; nt++) {
                int cb = ng * 64 + nt * 8 + fr;
                uint4 wb = __ldg(g_w1f + (cb * 2 + ks) * 4 + q);
                unsigned bh[2] = {wb.x, wb.y};
                unsigned bl[2] = {wb.z, wb.w};
                mma_bf16(acc[nt], ah, bh);
                mma_bf16(acc[nt], ah, bl);
                mma_bf16(acc[nt], al, bh);
            }
        }
        // ReLU: We-half -> smem bf16-split; Wa-half -> logit partials
        if (ng < 2) {
#pragma unroll
            for (int nt = 0; nt < 8; nt++) {
                int c = ng * 64 + nt * 8 + fc2;
                float v0 = fmaxf(acc[nt][0], 0.f), v1 = fmaxf(acc[nt][1], 0.f);
                float v2 = fmaxf(acc[nt][2], 0.f), v3 = fmaxf(acc[nt][3], 0.f);
                __nv_bfloat16 h0 = __float2bfloat16_rn(v0), h1 = __float2bfloat16_rn(v1);
                __nv_bfloat16 h2 = __float2bfloat16_rn(v2), h3 = __float2bfloat16_rn(v3);
                *(unsigned*)(s_hh + r0 * 136 + c) = pk2(h0, h1);
                *(unsigned*)(s_hh + r1 * 136 + c) = pk2(h2, h3);
                *(unsigned*)(s_hl + r0 * 136 + c) =
                    pk2(__float2bfloat16_rn(v0 - __bfloat162float(h0)),
                        __float2bfloat16_rn(v1 - __bfloat162float(h1)));
                *(unsigned*)(s_hl + r1 * 136 + c) =
                    pk2(__float2bfloat16_rn(v2 - __bfloat162float(h2)),
                        __float2bfloat16_rn(v3 - __bfloat162float(h3)));
            }
        } else {
            float p0 = 0.f, p1 = 0.f;
#pragma unroll
            for (int nt = 0; nt < 8; nt++) {
                int c = (ng - 2) * 64 + nt * 8 + fc2;
                float2 wv = __ldg((const float2*)g_wa2n + (c >> 1));
                p0 += fmaxf(acc[nt][0], 0.f) * wv.x + fmaxf(acc[nt][1], 0.f) * wv.y;
                p1 += fmaxf(acc[nt][2], 0.f) * wv.x + fmaxf(acc[nt][3], 0.f) * wv.y;
            }
            p0 += __shfl_xor_sync(0xFFFFFFFFu, p0, 1);
            p0 += __shfl_xor_sync(0xFFFFFFFFu, p0, 2);
            p1 += __shfl_xor_sync(0xFFFFFFFFu, p1, 1);
            p1 += __shfl_xor_sync(0xFFFFFFFFu, p1, 2);
            if (q == 0) {
                atomicAdd(&s_logit[r0], p0);
                atomicAdd(&s_logit[r1], p1);
            }
        }
    }
    __syncthreads();

    // ================= Layer 2 =================
    const int ng2 = w >> 2;
    float acc2[2][4];
#pragma unroll
    for (int nt = 0; nt < 2; nt++)
#pragma unroll
        for (int j = 0; j < 4; j++) acc2[nt][j] = 0.f;
#pragma unroll
    for (int ks = 0; ks < 8; ks++) {
        int kb = ks * 16;
        unsigned ah[4], al[4];
        ah[0] = *(const unsigned*)(s_hh + r0 * 136 + kb + fc2);
        ah[1] = *(const unsigned*)(s_hh + r1 * 136 + kb + fc2);
        ah[2] = *(const unsigned*)(s_hh + r0 * 136 + kb + fc2 + 8);
        ah[3] = *(const unsigned*)(s_hh + r1 * 136 + kb + fc2 + 8);
        al[0] = *(const unsigned*)(s_hl + r0 * 136 + kb + fc2);
        al[1] = *(const unsigned*)(s_hl + r1 * 136 + kb + fc2);
        al[2] = *(const unsigned*)(s_hl + r0 * 136 + kb + fc2 + 8);
        al[3] = *(const unsigned*)(s_hl + r1 * 136 + kb + fc2 + 8);
#pragma unroll
        for (int nt = 0; nt < 2; nt++) {
            int cb = ng2 * 16 + nt * 8 + fr;
            uint4 wb = __ldg(g_w2f + (cb * 8 + ks) * 4 + q);
            unsigned bh[2] = {wb.x, wb.y};
            unsigned bl[2] = {wb.z, wb.w};
            mma_bf16(acc2[nt], ah, bh);
            mma_bf16(acc2[nt], ah, bl);
            mma_bf16(acc2[nt], al, bh);
        }
    }

    // ---- epilogue: out_e + exp-weighted scatter ----
    {
        float ex0 = expf(s_logit[r0]);
        float ex1 = expf(s_logit[r1]);
        int d0 = s_dst[r0], d1 = s_dst[r1];
        int eg0 = e0 + r0, eg1 = e0 + r1;
#pragma unroll
        for (int nt = 0; nt < 2; nt++) {
            int c = ng2 * 16 + nt * 8 + fc2;
            float2 b2 = __ldg((const float2*)be2 + (c >> 1));
            float v0 = acc2[nt][0] + b2.x, v1 = acc2[nt][1] + b2.y;
            float v2 = acc2[nt][2] + b2.x, v3 = acc2[nt][3] + b2.y;
            if (eg0 < nEdges) {
                *(float2*)(out_e + (size_t)eg0 * 64 + c) = make_float2(v0, v1);
                red_add2(&g_agg[d0 * 64 + c], v0 * ex0, v1 * ex0);
            }
            if (eg1 < nEdges) {
                *(float2*)(out_e + (size_t)eg1 * 64 + c) = make_float2(v2, v3);
                red_add2(&g_agg[d1 * 64 + c], v2 * ex1, v3 * ex1);
            }
        }
        if (ng2 == 0 && q == 0) {
            if (eg0 < nEdges) atomicAdd(&g_denom[d0], ex0);
            if (eg1 < nEdges) atomicAdd(&g_denom[d1], ex1);
        }
    }
}

// ---------------- node MLP (mma): uh_n = MLP([agg/denom, nf]) ----------------
// 64 nodes/block, 256 threads = 8 warps. Layer1: mg=w&3 (m16) x ng=w>>2 (n64).
// Layer2: mg x ng2=w>>2 (n32).
__global__ __launch_bounds__(256) void node_kernel(
    const float* __restrict__ nf,
    const float* __restrict__ bn1, const float* __restrict__ bn2,
    float* __restrict__ out_n, int nNodes) {
    extern __shared__ char smraw[];
    __nv_bfloat16* s_xh = (__nv_bfloat16*)smraw;   // 64*136
    __nv_bfloat16* s_xl = s_xh + 64 * 136;
    __nv_bfloat16* s_hh = s_xl + 64 * 136;
    __nv_bfloat16* s_hl = s_hh + 64 * 136;
    const int tid = threadIdx.x;
    const int lane = tid & 31, w = tid >> 5;
    const int fr = lane >> 2, q = lane & 3, fc2 = q * 2;
    const int n0 = blockIdx.x * 64;

    for (int i = tid; i < 64 * 128; i += 256) {
        int r = i >> 7, c = i & 127;
        int n = n0 + r;
        float v = 0.f;
        if (n < nNodes) {
            if (c < 64) {
                float dn = fmaxf(g_denom[n], 1e-38f);
                v = g_agg[n * 64 + c] / dn;
            } else {
                v = __ldg(nf + (size_t)n * 64 + (c - 64));
            }
        }
        split_st(v, s_xh + r * 136 + c, s_xl + r * 136 + c);
    }
    __syncthreads();

    const int mg = w & 3, ng = w >> 2;
    const int r0 = mg * 16 + fr, r1 = r0 + 8;

    // ---- layer1: h = relu(x @ Wn1 + bn1) ----
    {
        float acc[8][4];
#pragma unroll
        for (int nt = 0; nt < 8; nt++) {
            int c = ng * 64 + nt * 8 + fc2;
            float2 bv = __ldg((const float2*)bn1 + (c >> 1));
            acc[nt][0] = bv.x; acc[nt][1] = bv.y;
            acc[nt][2] = bv.x; acc[nt][3] = bv.y;
        }
#pragma unroll
        for (int ks = 0; ks < 8; ks++) {
            int kb = ks * 16;
            unsigned ah[4], al[4];
            ah[0] = *(const unsigned*)(s_xh + r0 * 136 + kb + fc2);
            ah[1] = *(const unsigned*)(s_xh + r1 * 136 + kb + fc2);
            ah[2] = *(const unsigned*)(s_xh + r0 * 136 + kb + fc2 + 8);
            ah[3] = *(const unsigned*)(s_xh + r1 * 136 + kb + fc2 + 8);
            al[0] = *(const unsigned*)(s_xl + r0 * 136 + kb + fc2);
            al[1] = *(const unsigned*)(s_xl + r1 * 136 + kb + fc2);
            al[2] = *(const unsigned*)(s_xl + r0 * 136 + kb + fc2 + 8);
            al[3] = *(const unsigned*)(s_xl + r1 * 136 + kb + fc2 + 8);
#pragma unroll
            for (int nt = 0; nt < 8; nt++) {
                int cb = ng * 64 + nt * 8 + fr;
                uint4 wb = __ldg(g_wn1f + (cb * 8 + ks) * 4 + q);
                unsigned bh[2] = {wb.x, wb.y};
                unsigned bl[2] = {wb.z, wb.w};
                mma_bf16(acc[nt], ah, bh);
                mma_bf16(acc[nt], ah, bl);
                mma_bf16(acc[nt], al, bh);
            }
        }
#pragma unroll
        for (int nt = 0; nt < 8; nt++) {
            int c = ng * 64 + nt * 8 + fc2;
            float v0 = fmaxf(acc[nt][0], 0.f), v1 = fmaxf(acc[nt][1], 0.f);
            float v2 = fmaxf(acc[nt][2], 0.f), v3 = fmaxf(acc[nt][3], 0.f);
            __nv_bfloat16 h0 = __float2bfloat16_rn(v0), h1 = __float2bfloat16_rn(v1);
            __nv_bfloat16 h2 = __float2bfloat16_rn(v2), h3 = __float2bfloat16_rn(v3);
            *(unsigned*)(s_hh + r0 * 136 + c) = pk2(h0, h1);
            *(unsigned*)(s_hh + r1 * 136 + c) = pk2(h2, h3);
            *(unsigned*)(s_hl + r0 * 136 + c) =
                pk2(__float2bfloat16_rn(v0 - __bfloat162float(h0)),
                    __float2bfloat16_rn(v1 - __bfloat162float(h1)));
            *(unsigned*)(s_hl + r1 * 136 + c) =
                pk2(__float2bfloat16_rn(v2 - __bfloat162float(h2)),
                    __float2bfloat16_rn(v3 - __bfloat162float(h3)));
        }
    }
    __syncthreads();

    // ---- layer2: out = h @ Wn2 + bn2 ----
    const int ng2 = w >> 2;
    float acc2[4][4];
#pragma unroll
    for (int nt = 0; nt < 4; nt++) {
        int c = ng2 * 32 + nt * 8 + fc2;
        float2 bv = __ldg((const float2*)bn2 + (c >> 1));
        acc2[nt][0] = bv.x; acc2[nt][1] = bv.y;
        acc2[nt][2] = bv.x; acc2[nt][3] = bv.y;
    }
#pragma unroll
    for (int ks = 0; ks < 8; ks++) {
        int kb = ks * 16;
        unsigned ah[4], al[4];
        ah[0] = *(const unsigned*)(s_hh + r0 * 136 + kb + fc2);
        ah[1] = *(const unsigned*)(s_hh + r1 * 136 + kb + fc2);
        ah[2] = *(const unsigned*)(s_hh + r0 * 136 + kb + fc2 + 8);
        ah[3] = *(const unsigned*)(s_hh + r1 * 136 + kb + fc2 + 8);
        al[0] = *(const unsigned*)(s_hl + r0 * 136 + kb + fc2);
        al[1] = *(const unsigned*)(s_hl + r1 * 136 + kb + fc2);
        al[2] = *(const unsigned*)(s_hl + r0 * 136 + kb + fc2 + 8);
        al[3] = *(const unsigned*)(s_hl + r1 * 136 + kb + fc2 + 8);
#pragma unroll
        for (int nt = 0; nt < 4; nt++) {
            int cb = ng2 * 32 + nt * 8 + fr;
            uint4 wb = __ldg(g_wn2f + (cb * 8 + ks) * 4 + q);
            unsigned bh[2] = {wb.x, wb.y};
            unsigned bl[2] = {wb.z, wb.w};
            mma_bf16(acc2[nt], ah, bh);
            mma_bf16(acc2[nt], ah, bl);
            mma_bf16(acc2[nt], al, bh);
        }
    }
    {
        int nr0 = n0 + r0, nr1 = n0 + r1;
#pragma unroll
        for (int nt = 0; nt < 4; nt++) {
            int c = ng2 * 32 + nt * 8 + fc2;
            if (nr0 < nNodes)
                *(float2*)(out_n + (size_t)nr0 * 64 + c) = make_float2(acc2[nt][0], acc2[nt][1]);
            if (nr1 < nNodes)
                *(float2*)(out_n + (size_t)nr1 * 64 + c) = make_float2(acc2[nt][2], acc2[nt][3]);
        }
    }
}

// ---------------- launch ----------------
extern "C" void kernel_launch(void* const* d_in, const int* in_sizes, int n_in,
                              void* d_out, int out_size) {
    const float* nf  = (const float*)d_in[0];
    const float* ef  = (const float*)d_in[1];
    const int*   src = (const int*)d_in[2];
    const int*   dst = (const int*)d_in[3];
    const float* We1 = (const float*)d_in[4];
    const float* be1 = (const float*)d_in[5];
    const float* We2 = (const float*)d_in[6];
    const float* be2 = (const float*)d_in[7];
    const float* Wa1 = (const float*)d_in[8];
    const float* ba1 = (const float*)d_in[9];
    const float* Wa2 = (const float*)d_in[10];
    const float* ba2 = (const float*)d_in[11];
    const float* Wn1 = (const float*)d_in[12];
    const float* bn1 = (const float*)d_in[13];
    const float* Wn2 = (const float*)d_in[14];
    const float* bn2 = (const float*)d_in[15];

    int nNodes = in_sizes[0] / 64;
    int nEdges = in_sizes[2];

    float* out   = (float*)d_out;
    float* out_n = out;                              // [N,64]
    float* out_e = out + (size_t)nNodes * 64;        // [E,64]

    int smem_pre  = 64 * 72 * 2 * 2;                                  // 18432
    int smem_edge = (64 * 40 * 2 + 64 * 136 * 2) * 2 + 64 * 4 + 2 * 64 * 4;  // 45824
    int smem_node = 64 * 136 * 2 * 2 * 2;                             // 69632

    cudaFuncSetAttribute(node_pre_kernel, cudaFuncAttributeMaxDynamicSharedMemorySize, smem_pre);
    cudaFuncSetAttribute(edge_kernel,     cudaFuncAttributeMaxDynamicSharedMemorySize, smem_edge);
    cudaFuncSetAttribute(node_kernel,     cudaFuncAttributeMaxDynamicSharedMemorySize, smem_node);

    pack_kernel<<<128, 256>>>(We1, Wa1, be1, ba1, We2, Wa2, Wn1, Wn2);
    init_kernel<<<256, 256>>>(nNodes);
    node_pre_kernel<<<(nNodes + 63) / 64, 256, smem_pre>>>(nf, nNodes);
    edge_kernel<<<(nEdges + 63) / 64, 512, smem_edge>>>(ef, src, dst, be2, ba2, out_e, nEdges);
    node_kernel<<<(nNodes + 63) / 64, 256, smem_node>>>(nf, bn1, bn2, out_n, nNodes);
}

// round 11
// speedup vs baseline: 2.4422x; 1.1558x over previous
#include <cuda_runtime.h>
#include <cuda_bf16.h>
#include <math.h>

#define MAX_NN 50000

// ---------------- scratch (static device memory; no allocs) ----------------
// g_pre[n][512] PERMUTED: pos = gi*64 + q*16 + nt*2 + e, gi = half*4+ng
//   natural col C = half*256 + ng*64 + nt*8 + q*2 + e
//   dst half (gi>=4) has b1 bias FOLDED IN.
__device__ float g_pre[(size_t)MAX_NN * 512];
__device__ float g_denom[MAX_NN];
// g_agg[n][64] PERMUTED: p = ng2*16 + q*4 + nt*2 + e  <->  natural c = ng2*16 + nt*8 + q*2 + e
__device__ float g_agg[MAX_NN * 64];
__device__ __align__(16) float g_b1p[256];        // layer1 bias, permuted (no half)
__device__ float g_wa2n[128];                     // Wa2 natural
// packed B-fragments: uint4 = {bh(k0,k1), bh(k8,k9), bl(k0,k1), bl(k8,k9)}
__device__ __align__(16) uint4 g_w1f[256 * 2 * 4];    // edge W1e   [cb][ks(2)][q]
__device__ __align__(16) uint4 g_w2f[64 * 8 * 4];     // edge We2   [cb][ks(8)][q]
__device__ __align__(16) uint4 g_w1pf[512 * 4 * 4];   // node-pre W [cb][ks(4)][q]
__device__ __align__(16) uint4 g_wn1f[128 * 8 * 4];   // node Wn1   [cb][ks(8)][q]
__device__ __align__(16) uint4 g_wn2f[64 * 8 * 4];    // node Wn2   [cb][ks(8)][q]

__device__ __forceinline__ unsigned pk2(__nv_bfloat16 a, __nv_bfloat16 b) {
    return ((unsigned)__bfloat16_as_ushort(b) << 16) | (unsigned)__bfloat16_as_ushort(a);
}

__device__ __forceinline__ uint4 mk_frag(float f0, float f1, float f2, float f3) {
    __nv_bfloat16 h0 = __float2bfloat16_rn(f0), h1 = __float2bfloat16_rn(f1);
    __nv_bfloat16 h2 = __float2bfloat16_rn(f2), h3 = __float2bfloat16_rn(f3);
    uint4 v;
    v.x = pk2(h0, h1);
    v.y = pk2(h2, h3);
    v.z = pk2(__float2bfloat16_rn(f0 - __bfloat162float(h0)),
              __float2bfloat16_rn(f1 - __bfloat162float(h1)));
    v.w = pk2(__float2bfloat16_rn(f2 - __bfloat162float(h2)),
              __float2bfloat16_rn(f3 - __bfloat162float(h3)));
    return v;
}

__device__ __forceinline__ void mma_bf16(float* c, const unsigned* a, const unsigned* b) {
    asm volatile(
        "mma.sync.aligned.m16n8k16.row.col.f32.bf16.bf16.f32 "
        "{%0,%1,%2,%3}, {%4,%5,%6,%7}, {%8,%9}, {%0,%1,%2,%3};"
        : "+f"(c[0]), "+f"(c[1]), "+f"(c[2]), "+f"(c[3])
        : "r"(a[0]), "r"(a[1]), "r"(a[2]), "r"(a[3]), "r"(b[0]), "r"(b[1]));
}

__device__ __forceinline__ void red_add4(float* p, float x, float y, float z, float w) {
    asm volatile("red.global.add.v4.f32 [%0], {%1,%2,%3,%4};"
                 :: "l"(p), "f"(x), "f"(y), "f"(z), "f"(w) : "memory");
}

// make {hh, hl} pair for two fp32 values
__device__ __forceinline__ uint2 mk_pair(float c0, float c1) {
    __nv_bfloat16 h0 = __float2bfloat16_rn(c0), h1 = __float2bfloat16_rn(c1);
    uint2 r;
    r.x = pk2(h0, h1);
    r.y = pk2(__float2bfloat16_rn(c0 - __bfloat162float(h0)),
              __float2bfloat16_rn(c1 - __bfloat162float(h1)));
    return r;
}

// col-pair index u (covering cols 2u,2u+1 of a 16*K tile) -> interleaved pos
__device__ __forceinline__ int pos_of_u(int u) {
    return (u >> 3) * 8 + (u & 3) * 2 + ((u >> 2) & 1);
}

// W1e element: rows 128..159 of (We1|Wa1), k in [0,32), col in [0,256)
__device__ __forceinline__ float w1e_at(const float* We1, const float* Wa1, int k, int c) {
    return (c < 128) ? We1[(128 + k) * 128 + c] : Wa1[(128 + k) * 128 + (c - 128)];
}
// node-pre big-W element: natural out col C in [0,512), k in [0,64)
__device__ __forceinline__ float wpre_at(const float* We1, const float* Wa1, int k, int C) {
    int half = C >> 8, c = C & 255;
    int row = half * 64 + k;
    return (c < 128) ? We1[row * 128 + c] : Wa1[row * 128 + (c - 128)];
}

// ---------------- weight packing ----------------
__global__ void pack_kernel(const float* __restrict__ We1, const float* __restrict__ Wa1,
                            const float* __restrict__ be1, const float* __restrict__ ba1,
                            const float* __restrict__ We2, const float* __restrict__ Wa2,
                            const float* __restrict__ Wn1, const float* __restrict__ Wn2) {
    int i = blockIdx.x * blockDim.x + threadIdx.x;
    if (i < 256) {        // g_b1p permuted
        int ng = i >> 6, qq = (i >> 4) & 3, nt = (i >> 1) & 7, e = i & 1;
        int c = ng * 64 + nt * 8 + qq * 2 + e;
        g_b1p[i] = (c < 128) ? be1[c] : ba1[c - 128];
    }
    if (i < 128) g_wa2n[i] = Wa2[i];
    if (i < 2048) {       // g_w1f: cb = i>>3, ks = (i>>2)&1, q = i&3
        int cb = i >> 3, ks = (i >> 2) & 1, qq = i & 3;
        int ka = ks * 16 + 2 * qq;
        g_w1f[i] = mk_frag(w1e_at(We1, Wa1, ka, cb),     w1e_at(We1, Wa1, ka + 1, cb),
                           w1e_at(We1, Wa1, ka + 8, cb), w1e_at(We1, Wa1, ka + 9, cb));
    }
    if (i < 2048) {       // g_w2f: cb = i>>5, ks = (i>>2)&7, q = i&3
        int cb = i >> 5, ks = (i >> 2) & 7, qq = i & 3;
        int ka = ks * 16 + 2 * qq;
        g_w2f[i] = mk_frag(We2[ka * 64 + cb],       We2[(ka + 1) * 64 + cb],
                           We2[(ka + 8) * 64 + cb], We2[(ka + 9) * 64 + cb]);
    }
    if (i < 8192) {       // g_w1pf: cb = i>>4, ks = (i>>2)&3, q = i&3
        int cb = i >> 4, ks = (i >> 2) & 3, qq = i & 3;
        int ka = ks * 16 + 2 * qq;
        g_w1pf[i] = mk_frag(wpre_at(We1, Wa1, ka, cb),     wpre_at(We1, Wa1, ka + 1, cb),
                            wpre_at(We1, Wa1, ka + 8, cb), wpre_at(We1, Wa1, ka + 9, cb));
    }
    if (i < 4096) {       // g_wn1f: cb = i>>5, ks = (i>>2)&7, q = i&3
        int cb = i >> 5, ks = (i >> 2) & 7, qq = i & 3;
        int ka = ks * 16 + 2 * qq;
        g_wn1f[i] = mk_frag(Wn1[ka * 128 + cb],       Wn1[(ka + 1) * 128 + cb],
                            Wn1[(ka + 8) * 128 + cb], Wn1[(ka + 9) * 128 + cb]);
    }
    if (i < 2048) {       // g_wn2f: cb = i>>5, ks = (i>>2)&7, q = i&3
        int cb = i >> 5, ks = (i >> 2) & 7, qq = i & 3;
        int ka = ks * 16 + 2 * qq;
        g_wn2f[i] = mk_frag(Wn2[ka * 64 + cb],       Wn2[(ka + 1) * 64 + cb],
                            Wn2[(ka + 8) * 64 + cb], Wn2[(ka + 9) * 64 + cb]);
    }
}

__global__ void init_kernel(int nNodes) {
    int i = blockIdx.x * blockDim.x + threadIdx.x;
    int stride = gridDim.x * blockDim.x;
    float4* a4 = (float4*)g_agg;
    for (int j = i; j < nNodes * 16; j += stride) a4[j] = make_float4(0.f, 0.f, 0.f, 0.f);
    for (int j = i; j < nNodes; j += stride) g_denom[j] = 0.f;
}

// ---------------- node precompute (mma): pre = nf @ Wbig, +b1 folded in dst half ----------------
__global__ __launch_bounds__(256) void node_pre_kernel(const float* __restrict__ nf, int nNodes) {
    extern __shared__ char smraw[];
    __nv_bfloat16* s_ah = (__nv_bfloat16*)smraw;   // 64*72
    __nv_bfloat16* s_al = s_ah + 64 * 72;          // 64*72
    const int tid = threadIdx.x;
    const int lane = tid & 31, w = tid >> 5;
    const int fr = lane >> 2, q = lane & 3, fc2 = q * 2;
    const int n0 = blockIdx.x * 64;

    for (int i = tid; i < 64 * 64; i += 256) {
        int r = i >> 6, c = i & 63;
        int n = n0 + r;
        float v = (n < nNodes) ? __ldg(nf + (size_t)n * 64 + c) : 0.f;
        __nv_bfloat16 h = __float2bfloat16_rn(v);
        s_ah[r * 72 + c] = h;
        s_al[r * 72 + c] = __float2bfloat16_rn(v - __bfloat162float(h));
    }
    __syncthreads();

    const int mg = w & 3, ngw = w >> 2;
    const int r0 = mg * 16 + fr, r1 = r0 + 8;

    unsigned ah[4][4], al[4][4];
#pragma unroll
    for (int ks = 0; ks < 4; ks++) {
        int kb = ks * 16;
        ah[ks][0] = *(const unsigned*)(s_ah + r0 * 72 + kb + fc2);
        ah[ks][1] = *(const unsigned*)(s_ah + r1 * 72 + kb + fc2);
        ah[ks][2] = *(const unsigned*)(s_ah + r0 * 72 + kb + fc2 + 8);
        ah[ks][3] = *(const unsigned*)(s_ah + r1 * 72 + kb + fc2 + 8);
        al[ks][0] = *(const unsigned*)(s_al + r0 * 72 + kb + fc2);
        al[ks][1] = *(const unsigned*)(s_al + r1 * 72 + kb + fc2);
        al[ks][2] = *(const unsigned*)(s_al + r0 * 72 + kb + fc2 + 8);
        al[ks][3] = *(const unsigned*)(s_al + r1 * 72 + kb + fc2 + 8);
    }

#pragma unroll
    for (int nl = 0; nl < 4; nl++) {
        int gi = nl * 2 + ngw;
        float acc[8][4];
#pragma unroll
        for (int nt = 0; nt < 8; nt++)
#pragma unroll
            for (int j = 0; j < 4; j++) acc[nt][j] = 0.f;
#pragma unroll
        for (int ks = 0; ks < 4; ks++) {
#pragma unroll
            for (int nt = 0; nt < 8; nt++) {
                int cbn = gi * 64 + nt * 8 + fr;
                uint4 wb = __ldg(g_w1pf + (cbn * 4 + ks) * 4 + q);
                unsigned bh[2] = {wb.x, wb.y};
                unsigned bl[2] = {wb.z, wb.w};
                mma_bf16(acc[nt], ah[ks], bh);
                mma_bf16(acc[nt], ah[ks], bl);
                mma_bf16(acc[nt], al[ks], bh);
            }
        }
        float4* gp4 = (float4*)g_pre;
        const float4* B4 = (const float4*)g_b1p;
        int nr0 = n0 + r0, nr1 = n0 + r1;
#pragma unroll
        for (int m = 0; m < 4; m++) {
            float4 bv = make_float4(0.f, 0.f, 0.f, 0.f);
            if (gi >= 4) bv = __ldg(B4 + (gi - 4) * 16 + q * 4 + m);
            if (nr0 < nNodes)
                gp4[(size_t)nr0 * 128 + gi * 16 + q * 4 + m] =
                    make_float4(acc[2 * m][0] + bv.x, acc[2 * m][1] + bv.y,
                                acc[2 * m + 1][0] + bv.z, acc[2 * m + 1][1] + bv.w);
            if (nr1 < nNodes)
                gp4[(size_t)nr1 * 128 + gi * 16 + q * 4 + m] =
                    make_float4(acc[2 * m][2] + bv.x, acc[2 * m][3] + bv.y,
                                acc[2 * m + 1][2] + bv.z, acc[2 * m + 1][3] + bv.w);
        }
    }
}

// ---------------- fused edge kernel (bf16x3 mma, interleaved-fragment smem) ----------------
// 64 edges/block, 512 threads, 2 CTA/SM. Layer1: warp = m16 (mg=w&3) x n64 (ng=w>>2).
// smem (words): s_ef 64x48, s_h 64x144 (row stride ≡16 mod 32 -> conflict-free LDS.128)
__global__ __launch_bounds__(512, 2) void edge_kernel(
    const float* __restrict__ ef, const int* __restrict__ src, const int* __restrict__ dst,
    const float* __restrict__ be2, const float* __restrict__ ba2,
    float* __restrict__ out_e, int nEdges) {
    extern __shared__ unsigned smw[];
    unsigned* s_ef = smw;                        // 64*48 words
    unsigned* s_h  = smw + 64 * 48;              // 64*144 words
    float* s_logit = (float*)(s_h + 64 * 144);   // 64
    int*   s_src   = (int*)(s_logit + 64);       // 64
    int*   s_dst   = s_src + 64;                 // 64

    const int tid = threadIdx.x;
    const int e0 = blockIdx.x * 64;
    const int lane = tid & 31, w = tid >> 5;
    const int fr = lane >> 2, q = lane & 3, fc2 = q * 2;

    if (tid < 64) s_logit[tid] = __ldg(ba2);
    if (tid >= 64 && tid < 128) {
        int i = tid - 64, e = e0 + i;
        s_src[i] = (e < nEdges) ? __ldg(src + e) : 0;
        s_dst[i] = (e < nEdges) ? __ldg(dst + e) : 0;
    }
    {   // stage ef: one float4 per thread -> 2 interleaved pairs
        int r = tid >> 3, m = tid & 7;
        int e = e0 + r;
        float4 v = make_float4(0.f, 0.f, 0.f, 0.f);
        if (e < nEdges) v = __ldg((const float4*)ef + (size_t)e * 8 + m);
        int u0 = 2 * m;
        *(uint2*)(s_ef + r * 48 + pos_of_u(u0) * 2)     = mk_pair(v.x, v.y);
        *(uint2*)(s_ef + r * 48 + pos_of_u(u0 + 1) * 2) = mk_pair(v.z, v.w);
    }
    __syncthreads();

    const int mg = w & 3, ng = w >> 2;
    const int r0 = mg * 16 + fr, r1 = r0 + 8;

    // ================= Layer 1 =================
    {
        float acc[8][4];
        {   // gather-init (bias pre-folded into dst half)
            const float4* P = (const float4*)g_pre;
            int off = ng * 16 + q * 4;
            size_t bs0 = (size_t)s_src[r0] * 128 + off;
            size_t bd0 = (size_t)s_dst[r0] * 128 + 64 + off;
            size_t bs1 = (size_t)s_src[r1] * 128 + off;
            size_t bd1 = (size_t)s_dst[r1] * 128 + 64 + off;
#pragma unroll
            for (int i = 0; i < 4; i++) {
                float4 a = __ldg(P + bs0 + i), b = __ldg(P + bd0 + i);
                acc[2 * i][0]     = a.x + b.x;  acc[2 * i][1]     = a.y + b.y;
                acc[2 * i + 1][0] = a.z + b.z;  acc[2 * i + 1][1] = a.w + b.w;
                float4 c2 = __ldg(P + bs1 + i), d2 = __ldg(P + bd1 + i);
                acc[2 * i][2]     = c2.x + d2.x;  acc[2 * i][3]     = c2.y + d2.y;
                acc[2 * i + 1][2] = c2.z + d2.z;  acc[2 * i + 1][3] = c2.w + d2.w;
            }
        }
        // += ef @ W1e (bf16x3), A-frags via 2 LDS.128 per kstep
#pragma unroll
        for (int ks = 0; ks < 2; ks++) {
            uint4 va0 = *(const uint4*)(s_ef + r0 * 48 + ks * 16 + q * 4);
            uint4 va1 = *(const uint4*)(s_ef + r1 * 48 + ks * 16 + q * 4);
            unsigned ah[4] = {va0.x, va1.x, va0.z, va1.z};
            unsigned al[4] = {va0.y, va1.y, va0.w, va1.w};
#pragma unroll
            for (int nt = 0; nt < 8; nt++) {
                int cb = ng * 64 + nt * 8 + fr;
                uint4 wb = __ldg(g_w1f + (cb * 2 + ks) * 4 + q);
                unsigned bh[2] = {wb.x, wb.y};
                unsigned bl[2] = {wb.z, wb.w};
                mma_bf16(acc[nt], ah, bh);
                mma_bf16(acc[nt], ah, bl);
                mma_bf16(acc[nt], al, bh);
            }
        }
        // ReLU: We-half -> interleaved smem; Wa-half -> logit partials
        if (ng < 2) {
#pragma unroll
            for (int nt = 0; nt < 8; nt++) {
                int pos = (ng * 4 + (nt >> 1)) * 8 + q * 2 + (nt & 1);
                *(uint2*)(s_h + r0 * 144 + pos * 2) =
                    mk_pair(fmaxf(acc[nt][0], 0.f), fmaxf(acc[nt][1], 0.f));
                *(uint2*)(s_h + r1 * 144 + pos * 2) =
                    mk_pair(fmaxf(acc[nt][2], 0.f), fmaxf(acc[nt][3], 0.f));
            }
        } else {
            float p0 = 0.f, p1 = 0.f;
#pragma unroll
            for (int nt = 0; nt < 8; nt++) {
                int c = (ng - 2) * 64 + nt * 8 + fc2;
                float2 wv = __ldg((const float2*)g_wa2n + (c >> 1));
                p0 += fmaxf(acc[nt][0], 0.f) * wv.x + fmaxf(acc[nt][1], 0.f) * wv.y;
                p1 += fmaxf(acc[nt][2], 0.f) * wv.x + fmaxf(acc[nt][3], 0.f) * wv.y;
            }
            p0 += __shfl_xor_sync(0xFFFFFFFFu, p0, 1);
            p0 += __shfl_xor_sync(0xFFFFFFFFu, p0, 2);
            p1 += __shfl_xor_sync(0xFFFFFFFFu, p1, 1);
            p1 += __shfl_xor_sync(0xFFFFFFFFu, p1, 2);
            if (q == 0) {
                atomicAdd(&s_logit[r0], p0);
                atomicAdd(&s_logit[r1], p1);
            }
        }
    }
    __syncthreads();

    // ================= Layer 2 =================
    const int ng2 = w >> 2;
    float acc2[2][4];
#pragma unroll
    for (int nt = 0; nt < 2; nt++)
#pragma unroll
        for (int j = 0; j < 4; j++) acc2[nt][j] = 0.f;
#pragma unroll
    for (int ks = 0; ks < 8; ks++) {
        uint4 va0 = *(const uint4*)(s_h + r0 * 144 + ks * 16 + q * 4);
        uint4 va1 = *(const uint4*)(s_h + r1 * 144 + ks * 16 + q * 4);
        unsigned ah[4] = {va0.x, va1.x, va0.z, va1.z};
        unsigned al[4] = {va0.y, va1.y, va0.w, va1.w};
#pragma unroll
        for (int nt = 0; nt < 2; nt++) {
            int cb = ng2 * 16 + nt * 8 + fr;
            uint4 wb = __ldg(g_w2f + (cb * 8 + ks) * 4 + q);
            unsigned bh[2] = {wb.x, wb.y};
            unsigned bl[2] = {wb.z, wb.w};
            mma_bf16(acc2[nt], ah, bh);
            mma_bf16(acc2[nt], ah, bl);
            mma_bf16(acc2[nt], al, bh);
        }
    }

    // ---- epilogue: out_e (natural) + exp-weighted scatter (permuted g_agg, red.v4) ----
    {
        float ex0 = expf(s_logit[r0]);
        float ex1 = expf(s_logit[r1]);
        int d0 = s_dst[r0], d1 = s_dst[r1];
        int eg0 = e0 + r0, eg1 = e0 + r1;
        float2 b2a = __ldg((const float2*)be2 + ((ng2 * 16 + fc2) >> 1));
        float2 b2b = __ldg((const float2*)be2 + ((ng2 * 16 + 8 + fc2) >> 1));
        if (eg0 < nEdges) {
            float v00 = acc2[0][0] + b2a.x, v01 = acc2[0][1] + b2a.y;
            float v10 = acc2[1][0] + b2b.x, v11 = acc2[1][1] + b2b.y;
            *(float2*)(out_e + (size_t)eg0 * 64 + ng2 * 16 + fc2)     = make_float2(v00, v01);
            *(float2*)(out_e + (size_t)eg0 * 64 + ng2 * 16 + 8 + fc2) = make_float2(v10, v11);
            red_add4(&g_agg[d0 * 64 + ng2 * 16 + q * 4],
                     v00 * ex0, v01 * ex0, v10 * ex0, v11 * ex0);
        }
        if (eg1 < nEdges) {
            float v00 = acc2[0][2] + b2a.x, v01 = acc2[0][3] + b2a.y;
            float v10 = acc2[1][2] + b2b.x, v11 = acc2[1][3] + b2b.y;
            *(float2*)(out_e + (size_t)eg1 * 64 + ng2 * 16 + fc2)     = make_float2(v00, v01);
            *(float2*)(out_e + (size_t)eg1 * 64 + ng2 * 16 + 8 + fc2) = make_float2(v10, v11);
            red_add4(&g_agg[d1 * 64 + ng2 * 16 + q * 4],
                     v00 * ex1, v01 * ex1, v10 * ex1, v11 * ex1);
        }
        if (ng2 == 0 && q == 0) {
            if (eg0 < nEdges) atomicAdd(&g_denom[d0], ex0);
            if (eg1 < nEdges) atomicAdd(&g_denom[d1], ex1);
        }
    }
}

// ---------------- node MLP (mma, interleaved-fragment smem) ----------------
// 64 nodes/block, 256 threads = 8 warps. Layer1: mg=w&3 x ng=w>>2 (n64). Layer2: n32.
__global__ __launch_bounds__(256) void node_kernel(
    const float* __restrict__ nf,
    const float* __restrict__ bn1, const float* __restrict__ bn2,
    float* __restrict__ out_n, int nNodes) {
    extern __shared__ unsigned smw[];
    unsigned* s_x = smw;             // 64*144 words
    unsigned* s_h = smw + 64 * 144;  // 64*144 words
    const int tid = threadIdx.x;
    const int lane = tid & 31, w = tid >> 5;
    const int fr = lane >> 2, q = lane & 3, fc2 = q * 2;
    const int n0 = blockIdx.x * 64;

    for (int i = tid; i < 64 * 64; i += 256) {
        int r = i >> 6, u = i & 63;     // col pair (2u, 2u+1) of 128
        int n = n0 + r;
        float2 v = make_float2(0.f, 0.f);
        if (n < nNodes) {
            if (u < 32) {   // agg cols, permuted storage
                int c = 2 * u;
                int g2 = c >> 4, ww = c & 15;
                int nt = ww >> 3, qq = (ww >> 1) & 3;
                int p = g2 * 16 + qq * 4 + nt * 2;
                float dn = fmaxf(g_denom[n], 1e-38f);
                float2 av = *(const float2*)(g_agg + (size_t)n * 64 + p);
                v.x = av.x / dn; v.y = av.y / dn;
            } else {
                v = __ldg((const float2*)(nf + (size_t)n * 64) + (u - 32));
            }
        }
        *(uint2*)(s_x + r * 144 + pos_of_u(u) * 2) = mk_pair(v.x, v.y);
    }
    __syncthreads();

    const int mg = w & 3, ng = w >> 2;
    const int r0 = mg * 16 + fr, r1 = r0 + 8;

    // ---- layer1: h = relu(x @ Wn1 + bn1) ----
    {
        float acc[8][4];
#pragma unroll
        for (int nt = 0; nt < 8; nt++) {
            int c = ng * 64 + nt * 8 + fc2;
            float2 bv = __ldg((const float2*)bn1 + (c >> 1));
            acc[nt][0] = bv.x; acc[nt][1] = bv.y;
            acc[nt][2] = bv.x; acc[nt][3] = bv.y;
        }
#pragma unroll
        for (int ks = 0; ks < 8; ks++) {
            uint4 va0 = *(const uint4*)(s_x + r0 * 144 + ks * 16 + q * 4);
            uint4 va1 = *(const uint4*)(s_x + r1 * 144 + ks * 16 + q * 4);
            unsigned ah[4] = {va0.x, va1.x, va0.z, va1.z};
            unsigned al[4] = {va0.y, va1.y, va0.w, va1.w};
#pragma unroll
            for (int nt = 0; nt < 8; nt++) {
                int cb = ng * 64 + nt * 8 + fr;
                uint4 wb = __ldg(g_wn1f + (cb * 8 + ks) * 4 + q);
                unsigned bh[2] = {wb.x, wb.y};
                unsigned bl[2] = {wb.z, wb.w};
                mma_bf16(acc[nt], ah, bh);
                mma_bf16(acc[nt], ah, bl);
                mma_bf16(acc[nt], al, bh);
            }
        }
#pragma unroll
        for (int nt = 0; nt < 8; nt++) {
            int pos = (ng * 4 + (nt >> 1)) * 8 + q * 2 + (nt & 1);
            *(uint2*)(s_h + r0 * 144 + pos * 2) =
                mk_pair(fmaxf(acc[nt][0], 0.f), fmaxf(acc[nt][1], 0.f));
            *(uint2*)(s_h + r1 * 144 + pos * 2) =
                mk_pair(fmaxf(acc[nt][2], 0.f), fmaxf(acc[nt][3], 0.f));
        }
    }
    __syncthreads();

    // ---- layer2: out = h @ Wn2 + bn2 ----
    const int ng2 = w >> 2;
    float acc2[4][4];
#pragma unroll
    for (int nt = 0; nt < 4; nt++) {
        int c = ng2 * 32 + nt * 8 + fc2;
        float2 bv = __ldg((const float2*)bn2 + (c >> 1));
        acc2[nt][0] = bv.x; acc2[nt][1] = bv.y;
        acc2[nt][2] = bv.x; acc2[nt][3] = bv.y;
    }
#pragma unroll
    for (int ks = 0; ks < 8; ks++) {
        uint4 va0 = *(const uint4*)(s_h + r0 * 144 + ks * 16 + q * 4);
        uint4 va1 = *(const uint4*)(s_h + r1 * 144 + ks * 16 + q * 4);
        unsigned ah[4] = {va0.x, va1.x, va0.z, va1.z};
        unsigned al[4] = {va0.y, va1.y, va0.w, va1.w};
#pragma unroll
        for (int nt = 0; nt < 4; nt++) {
            int cb = ng2 * 32 + nt * 8 + fr;
            uint4 wb = __ldg(g_wn2f + (cb * 8 + ks) * 4 + q);
            unsigned bh[2] = {wb.x, wb.y};
            unsigned bl[2] = {wb.z, wb.w};
            mma_bf16(acc2[nt], ah, bh);
            mma_bf16(acc2[nt], ah, bl);
            mma_bf16(acc2[nt], al, bh);
        }
    }
    {
        int nr0 = n0 + r0, nr1 = n0 + r1;
#pragma unroll
        for (int nt = 0; nt < 4; nt++) {
            int c = ng2 * 32 + nt * 8 + fc2;
            if (nr0 < nNodes)
                *(float2*)(out_n + (size_t)nr0 * 64 + c) = make_float2(acc2[nt][0], acc2[nt][1]);
            if (nr1 < nNodes)
                *(float2*)(out_n + (size_t)nr1 * 64 + c) = make_float2(acc2[nt][2], acc2[nt][3]);
        }
    }
}

// ---------------- launch ----------------
extern "C" void kernel_launch(void* const* d_in, const int* in_sizes, int n_in,
                              void* d_out, int out_size) {
    const float* nf  = (const float*)d_in[0];
    const float* ef  = (const float*)d_in[1];
    const int*   src = (const int*)d_in[2];
    const int*   dst = (const int*)d_in[3];
    const float* We1 = (const float*)d_in[4];
    const float* be1 = (const float*)d_in[5];
    const float* We2 = (const float*)d_in[6];
    const float* be2 = (const float*)d_in[7];
    const float* Wa1 = (const float*)d_in[8];
    const float* ba1 = (const float*)d_in[9];
    const float* Wa2 = (const float*)d_in[10];
    const float* ba2 = (const float*)d_in[11];
    const float* Wn1 = (const float*)d_in[12];
    const float* bn1 = (const float*)d_in[13];
    const float* Wn2 = (const float*)d_in[14];
    const float* bn2 = (const float*)d_in[15];

    int nNodes = in_sizes[0] / 64;
    int nEdges = in_sizes[2];

    float* out   = (float*)d_out;
    float* out_n = out;                              // [N,64]
    float* out_e = out + (size_t)nNodes * 64;        // [E,64]

    int smem_pre  = 64 * 72 * 2 * 2;                             // 18432
    int smem_edge = (64 * 48 + 64 * 144) * 4 + 64 * 4 + 2 * 64 * 4;  // 49920
    int smem_node = (64 * 144) * 2 * 4;                          // 73728

    cudaFuncSetAttribute(node_pre_kernel, cudaFuncAttributeMaxDynamicSharedMemorySize, smem_pre);
    cudaFuncSetAttribute(edge_kernel,     cudaFuncAttributeMaxDynamicSharedMemorySize, smem_edge);
    cudaFuncSetAttribute(node_kernel,     cudaFuncAttributeMaxDynamicSharedMemorySize, smem_node);

    pack_kernel<<<128, 256>>>(We1, Wa1, be1, ba1, We2, Wa2, Wn1, Wn2);
    init_kernel<<<256, 256>>>(nNodes);
    node_pre_kernel<<<(nNodes + 63) / 64, 256, smem_pre>>>(nf, nNodes);
    edge_kernel<<<(nEdges + 63) / 64, 512, smem_edge>>>(ef, src, dst, be2, ba2, out_e, nEdges);
    node_kernel<<<(nNodes + 63) / 64, 256, smem_node>>>(nf, bn1, bn2, out_n, nNodes);
}

// round 12
// speedup vs baseline: 2.7356x; 1.1201x over previous
#include <cuda_runtime.h>
#include <cuda_bf16.h>
#include <math.h>

#define MAX_NN 50000

// ---------------- scratch (static device memory; no allocs) ----------------
// g_pre[n][512] PERMUTED: pos = gi*64 + q*16 + nt*2 + e, gi = half*4+ng
//   natural col C = half*256 + ng*64 + nt*8 + q*2 + e
//   dst half (gi>=4) has b1 bias FOLDED IN.
__device__ float g_pre[(size_t)MAX_NN * 512];
__device__ float g_denom[MAX_NN];
// g_agg[n][64] PERMUTED: p = ng2*16 + q*4 + nt*2 + e  <->  natural c = ng2*16 + nt*8 + q*2 + e
__device__ float g_agg[MAX_NN * 64];
__device__ __align__(16) float g_b1p[256];        // layer1 bias, permuted (no half)
__device__ float g_wa2n[128];                     // Wa2 natural
// packed B-fragments, layout [ks][cb][q]: warp LDG of fixed (ks,nt) reads 512B contiguous
// uint4 = {bh(k0,k1), bh(k8,k9), bl(k0,k1), bl(k8,k9)}
__device__ __align__(16) uint4 g_w1f[2 * 256 * 4];    // edge W1e   [ks(2)][cb(256)][q]
__device__ __align__(16) uint4 g_w2f[8 * 64 * 4];     // edge We2   [ks(8)][cb(64)][q]
__device__ __align__(16) uint4 g_w1pf[4 * 512 * 4];   // node-pre W [ks(4)][cb(512)][q]
__device__ __align__(16) uint4 g_wn1f[8 * 128 * 4];   // node Wn1   [ks(8)][cb(128)][q]
__device__ __align__(16) uint4 g_wn2f[8 * 64 * 4];    // node Wn2   [ks(8)][cb(64)][q]

__device__ __forceinline__ unsigned pk2(__nv_bfloat16 a, __nv_bfloat16 b) {
    return ((unsigned)__bfloat16_as_ushort(b) << 16) | (unsigned)__bfloat16_as_ushort(a);
}

__device__ __forceinline__ uint4 mk_frag(float f0, float f1, float f2, float f3) {
    __nv_bfloat16 h0 = __float2bfloat16_rn(f0), h1 = __float2bfloat16_rn(f1);
    __nv_bfloat16 h2 = __float2bfloat16_rn(f2), h3 = __float2bfloat16_rn(f3);
    uint4 v;
    v.x = pk2(h0, h1);
    v.y = pk2(h2, h3);
    v.z = pk2(__float2bfloat16_rn(f0 - __bfloat162float(h0)),
              __float2bfloat16_rn(f1 - __bfloat162float(h1)));
    v.w = pk2(__float2bfloat16_rn(f2 - __bfloat162float(h2)),
              __float2bfloat16_rn(f3 - __bfloat162float(h3)));
    return v;
}

__device__ __forceinline__ void mma_bf16(float* c, const unsigned* a, const unsigned* b) {
    asm volatile(
        "mma.sync.aligned.m16n8k16.row.col.f32.bf16.bf16.f32 "
        "{%0,%1,%2,%3}, {%4,%5,%6,%7}, {%8,%9}, {%0,%1,%2,%3};"
        : "+f"(c[0]), "+f"(c[1]), "+f"(c[2]), "+f"(c[3])
        : "r"(a[0]), "r"(a[1]), "r"(a[2]), "r"(a[3]), "r"(b[0]), "r"(b[1]));
}

__device__ __forceinline__ void red_add4(float* p, float x, float y, float z, float w) {
    asm volatile("red.global.add.v4.f32 [%0], {%1,%2,%3,%4};"
                 :: "l"(p), "f"(x), "f"(y), "f"(z), "f"(w) : "memory");
}

// make {hh, hl} pair for two fp32 values
__device__ __forceinline__ uint2 mk_pair(float c0, float c1) {
    __nv_bfloat16 h0 = __float2bfloat16_rn(c0), h1 = __float2bfloat16_rn(c1);
    uint2 r;
    r.x = pk2(h0, h1);
    r.y = pk2(__float2bfloat16_rn(c0 - __bfloat162float(h0)),
              __float2bfloat16_rn(c1 - __bfloat162float(h1)));
    return r;
}

// col-pair index u (covering cols 2u,2u+1 of a 16*K tile) -> interleaved pos
__device__ __forceinline__ int pos_of_u(int u) {
    return (u >> 3) * 8 + (u & 3) * 2 + ((u >> 2) & 1);
}

// W1e element: rows 128..159 of (We1|Wa1), k in [0,32), col in [0,256)
__device__ __forceinline__ float w1e_at(const float* We1, const float* Wa1, int k, int c) {
    return (c < 128) ? We1[(128 + k) * 128 + c] : Wa1[(128 + k) * 128 + (c - 128)];
}
// node-pre big-W element: natural out col C in [0,512), k in [0,64)
__device__ __forceinline__ float wpre_at(const float* We1, const float* Wa1, int k, int C) {
    int half = C >> 8, c = C & 255;
    int row = half * 64 + k;
    return (c < 128) ? We1[row * 128 + c] : Wa1[row * 128 + (c - 128)];
}

// ---------------- weight packing ----------------
__global__ void pack_kernel(const float* __restrict__ We1, const float* __restrict__ Wa1,
                            const float* __restrict__ be1, const float* __restrict__ ba1,
                            const float* __restrict__ We2, const float* __restrict__ Wa2,
                            const float* __restrict__ Wn1, const float* __restrict__ Wn2) {
    int i = blockIdx.x * blockDim.x + threadIdx.x;
    if (i < 256) {        // g_b1p permuted
        int ng = i >> 6, qq = (i >> 4) & 3, nt = (i >> 1) & 7, e = i & 1;
        int c = ng * 64 + nt * 8 + qq * 2 + e;
        g_b1p[i] = (c < 128) ? be1[c] : ba1[c - 128];
    }
    if (i < 128) g_wa2n[i] = Wa2[i];
    if (i < 2048) {       // g_w1f [ks][cb][q]: ks = i>>10, cb = (i>>2)&255, q = i&3
        int ks = i >> 10, cb = (i >> 2) & 255, qq = i & 3;
        int ka = ks * 16 + 2 * qq;
        g_w1f[i] = mk_frag(w1e_at(We1, Wa1, ka, cb),     w1e_at(We1, Wa1, ka + 1, cb),
                           w1e_at(We1, Wa1, ka + 8, cb), w1e_at(We1, Wa1, ka + 9, cb));
    }
    if (i < 2048) {       // g_w2f [ks][cb][q]: ks = i>>8, cb = (i>>2)&63, q = i&3
        int ks = i >> 8, cb = (i >> 2) & 63, qq = i & 3;
        int ka = ks * 16 + 2 * qq;
        g_w2f[i] = mk_frag(We2[ka * 64 + cb],       We2[(ka + 1) * 64 + cb],
                           We2[(ka + 8) * 64 + cb], We2[(ka + 9) * 64 + cb]);
    }
    if (i < 8192) {       // g_w1pf [ks][cb][q]: ks = i>>11, cb = (i>>2)&511, q = i&3
        int ks = i >> 11, cb = (i >> 2) & 511, qq = i & 3;
        int ka = ks * 16 + 2 * qq;
        g_w1pf[i] = mk_frag(wpre_at(We1, Wa1, ka, cb),     wpre_at(We1, Wa1, ka + 1, cb),
                            wpre_at(We1, Wa1, ka + 8, cb), wpre_at(We1, Wa1, ka + 9, cb));
    }
    if (i < 4096) {       // g_wn1f [ks][cb][q]: ks = i>>9, cb = (i>>2)&127, q = i&3
        int ks = i >> 9, cb = (i >> 2) & 127, qq = i & 3;
        int ka = ks * 16 + 2 * qq;
        g_wn1f[i] = mk_frag(Wn1[ka * 128 + cb],       Wn1[(ka + 1) * 128 + cb],
                            Wn1[(ka + 8) * 128 + cb], Wn1[(ka + 9) * 128 + cb]);
    }
    if (i < 2048) {       // g_wn2f [ks][cb][q]
        int ks = i >> 8, cb = (i >> 2) & 63, qq = i & 3;
        int ka = ks * 16 + 2 * qq;
        g_wn2f[i] = mk_frag(Wn2[ka * 64 + cb],       Wn2[(ka + 1) * 64 + cb],
                            Wn2[(ka + 8) * 64 + cb], Wn2[(ka + 9) * 64 + cb]);
    }
}

__global__ void init_kernel(int nNodes) {
    int i = blockIdx.x * blockDim.x + threadIdx.x;
    int stride = gridDim.x * blockDim.x;
    float4* a4 = (float4*)g_agg;
    for (int j = i; j < nNodes * 16; j += stride) a4[j] = make_float4(0.f, 0.f, 0.f, 0.f);
    for (int j = i; j < nNodes; j += stride) g_denom[j] = 0.f;
}

// ---------------- node precompute (mma): pre = nf @ Wbig, +b1 folded in dst half ----------------
__global__ __launch_bounds__(256) void node_pre_kernel(const float* __restrict__ nf, int nNodes) {
    extern __shared__ char smraw[];
    __nv_bfloat16* s_ah = (__nv_bfloat16*)smraw;   // 64*72
    __nv_bfloat16* s_al = s_ah + 64 * 72;          // 64*72
    const int tid = threadIdx.x;
    const int lane = tid & 31, w = tid >> 5;
    const int fr = lane >> 2, q = lane & 3, fc2 = q * 2;
    const int n0 = blockIdx.x * 64;

    for (int i = tid; i < 64 * 64; i += 256) {
        int r = i >> 6, c = i & 63;
        int n = n0 + r;
        float v = (n < nNodes) ? __ldg(nf + (size_t)n * 64 + c) : 0.f;
        __nv_bfloat16 h = __float2bfloat16_rn(v);
        s_ah[r * 72 + c] = h;
        s_al[r * 72 + c] = __float2bfloat16_rn(v - __bfloat162float(h));
    }
    __syncthreads();

    const int mg = w & 3, ngw = w >> 2;
    const int r0 = mg * 16 + fr, r1 = r0 + 8;

    unsigned ah[4][4], al[4][4];
#pragma unroll
    for (int ks = 0; ks < 4; ks++) {
        int kb = ks * 16;
        ah[ks][0] = *(const unsigned*)(s_ah + r0 * 72 + kb + fc2);
        ah[ks][1] = *(const unsigned*)(s_ah + r1 * 72 + kb + fc2);
        ah[ks][2] = *(const unsigned*)(s_ah + r0 * 72 + kb + fc2 + 8);
        ah[ks][3] = *(const unsigned*)(s_ah + r1 * 72 + kb + fc2 + 8);
        al[ks][0] = *(const unsigned*)(s_al + r0 * 72 + kb + fc2);
        al[ks][1] = *(const unsigned*)(s_al + r1 * 72 + kb + fc2);
        al[ks][2] = *(const unsigned*)(s_al + r0 * 72 + kb + fc2 + 8);
        al[ks][3] = *(const unsigned*)(s_al + r1 * 72 + kb + fc2 + 8);
    }

#pragma unroll
    for (int nl = 0; nl < 4; nl++) {
        int gi = nl * 2 + ngw;
        float acc[8][4];
#pragma unroll
        for (int nt = 0; nt < 8; nt++)
#pragma unroll
            for (int j = 0; j < 4; j++) acc[nt][j] = 0.f;
#pragma unroll
        for (int ks = 0; ks < 4; ks++) {
#pragma unroll
            for (int nt = 0; nt < 8; nt++) {
                int cbn = gi * 64 + nt * 8 + fr;
                uint4 wb = __ldg(g_w1pf + ((ks * 512 + cbn) << 2) + q);
                unsigned bh[2] = {wb.x, wb.y};
                unsigned bl[2] = {wb.z, wb.w};
                mma_bf16(acc[nt], ah[ks], bh);
                mma_bf16(acc[nt], ah[ks], bl);
                mma_bf16(acc[nt], al[ks], bh);
            }
        }
        float4* gp4 = (float4*)g_pre;
        const float4* B4 = (const float4*)g_b1p;
        int nr0 = n0 + r0, nr1 = n0 + r1;
#pragma unroll
        for (int m = 0; m < 4; m++) {
            float4 bv = make_float4(0.f, 0.f, 0.f, 0.f);
            if (gi >= 4) bv = __ldg(B4 + (gi - 4) * 16 + q * 4 + m);
            if (nr0 < nNodes)
                gp4[(size_t)nr0 * 128 + gi * 16 + q * 4 + m] =
                    make_float4(acc[2 * m][0] + bv.x, acc[2 * m][1] + bv.y,
                                acc[2 * m + 1][0] + bv.z, acc[2 * m + 1][1] + bv.w);
            if (nr1 < nNodes)
                gp4[(size_t)nr1 * 128 + gi * 16 + q * 4 + m] =
                    make_float4(acc[2 * m][2] + bv.x, acc[2 * m][3] + bv.y,
                                acc[2 * m + 1][2] + bv.z, acc[2 * m + 1][3] + bv.w);
        }
    }
}

// ---------------- fused edge kernel (bf16x3 mma, coalesced weights + staged epilogue) ----------------
// 64 edges/block, 512 threads, 2 CTA/SM. Layer1: warp = m16 (mg=w&3) x n64 (ng=w>>2).
// smem words: alias region [0,12288) = {s_ef 64x48 | s_h 64x144 (offset 3072)} then reused
// as s_out 64x72 floats for the coalesced out_e epilogue. s_logit/s_src/s_dst outside alias.
__global__ __launch_bounds__(512, 2) void edge_kernel(
    const float* __restrict__ ef, const int* __restrict__ src, const int* __restrict__ dst,
    const float* __restrict__ be2, const float* __restrict__ ba2,
    float* __restrict__ out_e, int nEdges) {
    extern __shared__ unsigned smw[];
    unsigned* s_ef = smw;                        // 64*48 words
    unsigned* s_h  = smw + 64 * 48;              // 64*144 words
    float* s_logit = (float*)(smw + 12288);      // 64
    int*   s_src   = (int*)(s_logit + 64);       // 64
    int*   s_dst   = s_src + 64;                 // 64

    const int tid = threadIdx.x;
    const int e0 = blockIdx.x * 64;
    const int lane = tid & 31, w = tid >> 5;
    const int fr = lane >> 2, q = lane & 3, fc2 = q * 2;

    if (tid < 64) s_logit[tid] = __ldg(ba2);
    if (tid >= 64 && tid < 128) {
        int i = tid - 64, e = e0 + i;
        s_src[i] = (e < nEdges) ? __ldg(src + e) : 0;
        s_dst[i] = (e < nEdges) ? __ldg(dst + e) : 0;
    }
    {   // stage ef: one float4 per thread -> 2 interleaved pairs
        int r = tid >> 3, m = tid & 7;
        int e = e0 + r;
        float4 v = make_float4(0.f, 0.f, 0.f, 0.f);
        if (e < nEdges) v = __ldg((const float4*)ef + (size_t)e * 8 + m);
        int u0 = 2 * m;
        *(uint2*)(s_ef + r * 48 + pos_of_u(u0) * 2)     = mk_pair(v.x, v.y);
        *(uint2*)(s_ef + r * 48 + pos_of_u(u0 + 1) * 2) = mk_pair(v.z, v.w);
    }
    __syncthreads();

    const int mg = w & 3, ng = w >> 2;
    const int r0 = mg * 16 + fr, r1 = r0 + 8;

    // ================= Layer 1 =================
    {
        float acc[8][4];
        {   // gather-init (bias pre-folded into dst half)
            const float4* P = (const float4*)g_pre;
            int off = ng * 16 + q * 4;
            size_t bs0 = (size_t)s_src[r0] * 128 + off;
            size_t bd0 = (size_t)s_dst[r0] * 128 + 64 + off;
            size_t bs1 = (size_t)s_src[r1] * 128 + off;
            size_t bd1 = (size_t)s_dst[r1] * 128 + 64 + off;
#pragma unroll
            for (int i = 0; i < 4; i++) {
                float4 a = __ldg(P + bs0 + i), b = __ldg(P + bd0 + i);
                acc[2 * i][0]     = a.x + b.x;  acc[2 * i][1]     = a.y + b.y;
                acc[2 * i + 1][0] = a.z + b.z;  acc[2 * i + 1][1] = a.w + b.w;
                float4 c2 = __ldg(P + bs1 + i), d2 = __ldg(P + bd1 + i);
                acc[2 * i][2]     = c2.x + d2.x;  acc[2 * i][3]     = c2.y + d2.y;
                acc[2 * i + 1][2] = c2.z + d2.z;  acc[2 * i + 1][3] = c2.w + d2.w;
            }
        }
        // += ef @ W1e (bf16x3)
#pragma unroll
        for (int ks = 0; ks < 2; ks++) {
            uint4 va0 = *(const uint4*)(s_ef + r0 * 48 + ks * 16 + q * 4);
            uint4 va1 = *(const uint4*)(s_ef + r1 * 48 + ks * 16 + q * 4);
            unsigned ah[4] = {va0.x, va1.x, va0.z, va1.z};
            unsigned al[4] = {va0.y, va1.y, va0.w, va1.w};
#pragma unroll
            for (int nt = 0; nt < 8; nt++) {
                int cb = ng * 64 + nt * 8 + fr;
                uint4 wb = __ldg(g_w1f + ((ks * 256 + cb) << 2) + q);
                unsigned bh[2] = {wb.x, wb.y};
                unsigned bl[2] = {wb.z, wb.w};
                mma_bf16(acc[nt], ah, bh);
                mma_bf16(acc[nt], ah, bl);
                mma_bf16(acc[nt], al, bh);
            }
        }
        // ReLU: We-half -> interleaved smem; Wa-half -> logit partials
        if (ng < 2) {
#pragma unroll
            for (int nt = 0; nt < 8; nt++) {
                int pos = (ng * 4 + (nt >> 1)) * 8 + q * 2 + (nt & 1);
                *(uint2*)(s_h + r0 * 144 + pos * 2) =
                    mk_pair(fmaxf(acc[nt][0], 0.f), fmaxf(acc[nt][1], 0.f));
                *(uint2*)(s_h + r1 * 144 + pos * 2) =
                    mk_pair(fmaxf(acc[nt][2], 0.f), fmaxf(acc[nt][3], 0.f));
            }
        } else {
            float p0 = 0.f, p1 = 0.f;
#pragma unroll
            for (int nt = 0; nt < 8; nt++) {
                int c = (ng - 2) * 64 + nt * 8 + fc2;
                float2 wv = __ldg((const float2*)g_wa2n + (c >> 1));
                p0 += fmaxf(acc[nt][0], 0.f) * wv.x + fmaxf(acc[nt][1], 0.f) * wv.y;
                p1 += fmaxf(acc[nt][2], 0.f) * wv.x + fmaxf(acc[nt][3], 0.f) * wv.y;
            }
            p0 += __shfl_xor_sync(0xFFFFFFFFu, p0, 1);
            p0 += __shfl_xor_sync(0xFFFFFFFFu, p0, 2);
            p1 += __shfl_xor_sync(0xFFFFFFFFu, p1, 1);
            p1 += __shfl_xor_sync(0xFFFFFFFFu, p1, 2);
            if (q == 0) {
                atomicAdd(&s_logit[r0], p0);
                atomicAdd(&s_logit[r1], p1);
            }
        }
    }
    __syncthreads();

    // ================= Layer 2 =================
    const int ng2 = w >> 2;
    float acc2[2][4];
#pragma unroll
    for (int nt = 0; nt < 2; nt++)
#pragma unroll
        for (int j = 0; j < 4; j++) acc2[nt][j] = 0.f;
#pragma unroll
    for (int ks = 0; ks < 8; ks++) {
        uint4 va0 = *(const uint4*)(s_h + r0 * 144 + ks * 16 + q * 4);
        uint4 va1 = *(const uint4*)(s_h + r1 * 144 + ks * 16 + q * 4);
        unsigned ah[4] = {va0.x, va1.x, va0.z, va1.z};
        unsigned al[4] = {va0.y, va1.y, va0.w, va1.w};
#pragma unroll
        for (int nt = 0; nt < 2; nt++) {
            int cb = ng2 * 16 + nt * 8 + fr;
            uint4 wb = __ldg(g_w2f + ((ks * 64 + cb) << 2) + q);
            unsigned bh[2] = {wb.x, wb.y};
            unsigned bl[2] = {wb.z, wb.w};
            mma_bf16(acc2[nt], ah, bh);
            mma_bf16(acc2[nt], ah, bl);
            mma_bf16(acc2[nt], al, bh);
        }
    }

    // ---- epilogue: scatter (from regs) + staged coalesced out_e ----
    {
        float ex0 = expf(s_logit[r0]);
        float ex1 = expf(s_logit[r1]);
        int d0 = s_dst[r0], d1 = s_dst[r1];
        int eg0 = e0 + r0, eg1 = e0 + r1;
        float2 b2a = __ldg((const float2*)be2 + ((ng2 * 16 + fc2) >> 1));
        float2 b2b = __ldg((const float2*)be2 + ((ng2 * 16 + 8 + fc2) >> 1));
        float v00a = acc2[0][0] + b2a.x, v01a = acc2[0][1] + b2a.y;
        float v10a = acc2[1][0] + b2b.x, v11a = acc2[1][1] + b2b.y;
        float v00b = acc2[0][2] + b2a.x, v01b = acc2[0][3] + b2a.y;
        float v10b = acc2[1][2] + b2b.x, v11b = acc2[1][3] + b2b.y;
        if (eg0 < nEdges)
            red_add4(&g_agg[d0 * 64 + ng2 * 16 + q * 4],
                     v00a * ex0, v01a * ex0, v10a * ex0, v11a * ex0);
        if (eg1 < nEdges)
            red_add4(&g_agg[d1 * 64 + ng2 * 16 + q * 4],
                     v00b * ex1, v01b * ex1, v10b * ex1, v11b * ex1);
        if (ng2 == 0 && q == 0) {
            if (eg0 < nEdges) atomicAdd(&g_denom[d0], ex0);
            if (eg1 < nEdges) atomicAdd(&g_denom[d1], ex1);
        }
        __syncthreads();   // all warps done reading s_ef/s_h -> reuse as s_out
        float* s_out = (float*)smw;  // 64 x 72 floats
        int cA = ng2 * 16 + fc2;
        *(float2*)(s_out + r0 * 72 + cA)     = make_float2(v00a, v01a);
        *(float2*)(s_out + r0 * 72 + cA + 8) = make_float2(v10a, v11a);
        *(float2*)(s_out + r1 * 72 + cA)     = make_float2(v00b, v01b);
        *(float2*)(s_out + r1 * 72 + cA + 8) = make_float2(v10b, v11b);
    }
    __syncthreads();
    {   // coalesced write: 512 threads x 2 float4 = 64 edges x 64 floats
        const float* s_out = (const float*)smw;
        int base = tid * 4;
#pragma unroll
        for (int h = 0; h < 2; h++) {
            int j = base + h * 2048;
            int e = j >> 6, c = j & 63;
            if (e0 + e < nEdges) {
                float4 v = *(const float4*)(s_out + e * 72 + c);
                *(float4*)(out_e + (size_t)(e0 + e) * 64 + c) = v;
            }
        }
    }
}

// ---------------- node MLP (mma, interleaved-fragment smem) ----------------
// 64 nodes/block, 256 threads = 8 warps. Layer1: mg=w&3 x ng=w>>2 (n64). Layer2: n32.
__global__ __launch_bounds__(256) void node_kernel(
    const float* __restrict__ nf,
    const float* __restrict__ bn1, const float* __restrict__ bn2,
    float* __restrict__ out_n, int nNodes) {
    extern __shared__ unsigned smw[];
    unsigned* s_x = smw;             // 64*144 words
    unsigned* s_h = smw + 64 * 144;  // 64*144 words
    const int tid = threadIdx.x;
    const int lane = tid & 31, w = tid >> 5;
    const int fr = lane >> 2, q = lane & 3, fc2 = q * 2;
    const int n0 = blockIdx.x * 64;

    for (int i = tid; i < 64 * 64; i += 256) {
        int r = i >> 6, u = i & 63;     // col pair (2u, 2u+1) of 128
        int n = n0 + r;
        float2 v = make_float2(0.f, 0.f);
        if (n < nNodes) {
            if (u < 32) {   // agg cols, permuted storage
                int c = 2 * u;
                int g2 = c >> 4, ww = c & 15;
                int nt = ww >> 3, qq = (ww >> 1) & 3;
                int p = g2 * 16 + qq * 4 + nt * 2;
                float dn = fmaxf(g_denom[n], 1e-38f);
                float2 av = *(const float2*)(g_agg + (size_t)n * 64 + p);
                v.x = av.x / dn; v.y = av.y / dn;
            } else {
                v = __ldg((const float2*)(nf + (size_t)n * 64) + (u - 32));
            }
        }
        *(uint2*)(s_x + r * 144 + pos_of_u(u) * 2) = mk_pair(v.x, v.y);
    }
    __syncthreads();

    const int mg = w & 3, ng = w >> 2;
    const int r0 = mg * 16 + fr, r1 = r0 + 8;

    // ---- layer1: h = relu(x @ Wn1 + bn1) ----
    {
        float acc[8][4];
#pragma unroll
        for (int nt = 0; nt < 8; nt++) {
            int c = ng * 64 + nt * 8 + fc2;
            float2 bv = __ldg((const float2*)bn1 + (c >> 1));
            acc[nt][0] = bv.x; acc[nt][1] = bv.y;
            acc[nt][2] = bv.x; acc[nt][3] = bv.y;
        }
#pragma unroll
        for (int ks = 0; ks < 8; ks++) {
            uint4 va0 = *(const uint4*)(s_x + r0 * 144 + ks * 16 + q * 4);
            uint4 va1 = *(const uint4*)(s_x + r1 * 144 + ks * 16 + q * 4);
            unsigned ah[4] = {va0.x, va1.x, va0.z, va1.z};
            unsigned al[4] = {va0.y, va1.y, va0.w, va1.w};
#pragma unroll
            for (int nt = 0; nt < 8; nt++) {
                int cb = ng * 64 + nt * 8 + fr;
                uint4 wb = __ldg(g_wn1f + ((ks * 128 + cb) << 2) + q);
                unsigned bh[2] = {wb.x, wb.y};
                unsigned bl[2] = {wb.z, wb.w};
                mma_bf16(acc[nt], ah, bh);
                mma_bf16(acc[nt], ah, bl);
                mma_bf16(acc[nt], al, bh);
            }
        }
#pragma unroll
        for (int nt = 0; nt < 8; nt++) {
            int pos = (ng * 4 + (nt >> 1)) * 8 + q * 2 + (nt & 1);
            *(uint2*)(s_h + r0 * 144 + pos * 2) =
                mk_pair(fmaxf(acc[nt][0], 0.f), fmaxf(acc[nt][1], 0.f));
            *(uint2*)(s_h + r1 * 144 + pos * 2) =
                mk_pair(fmaxf(acc[nt][2], 0.f), fmaxf(acc[nt][3], 0.f));
        }
    }
    __syncthreads();

    // ---- layer2: out = h @ Wn2 + bn2 ----
    const int ng2 = w >> 2;
    float acc2[4][4];
#pragma unroll
    for (int nt = 0; nt < 4; nt++) {
        int c = ng2 * 32 + nt * 8 + fc2;
        float2 bv = __ldg((const float2*)bn2 + (c >> 1));
        acc2[nt][0] = bv.x; acc2[nt][1] = bv.y;
        acc2[nt][2] = bv.x; acc2[nt][3] = bv.y;
    }
#pragma unroll
    for (int ks = 0; ks < 8; ks++) {
        uint4 va0 = *(const uint4*)(s_h + r0 * 144 + ks * 16 + q * 4);
        uint4 va1 = *(const uint4*)(s_h + r1 * 144 + ks * 16 + q * 4);
        unsigned ah[4] = {va0.x, va1.x, va0.z, va1.z};
        unsigned al[4] = {va0.y, va1.y, va0.w, va1.w};
#pragma unroll
        for (int nt = 0; nt < 4; nt++) {
            int cb = ng2 * 32 + nt * 8 + fr;
            uint4 wb = __ldg(g_wn2f + ((ks * 64 + cb) << 2) + q);
            unsigned bh[2] = {wb.x, wb.y};
            unsigned bl[2] = {wb.z, wb.w};
            mma_bf16(acc2[nt], ah, bh);
            mma_bf16(acc2[nt], ah, bl);
            mma_bf16(acc2[nt], al, bh);
        }
    }
    {
        int nr0 = n0 + r0, nr1 = n0 + r1;
#pragma unroll
        for (int nt = 0; nt < 4; nt++) {
            int c = ng2 * 32 + nt * 8 + fc2;
            if (nr0 < nNodes)
                *(float2*)(out_n + (size_t)nr0 * 64 + c) = make_float2(acc2[nt][0], acc2[nt][1]);
            if (nr1 < nNodes)
                *(float2*)(out_n + (size_t)nr1 * 64 + c) = make_float2(acc2[nt][2], acc2[nt][3]);
        }
    }
}

// ---------------- launch ----------------
extern "C" void kernel_launch(void* const* d_in, const int* in_sizes, int n_in,
                              void* d_out, int out_size) {
    const float* nf  = (const float*)d_in[0];
    const float* ef  = (const float*)d_in[1];
    const int*   src = (const int*)d_in[2];
    const int*   dst = (const int*)d_in[3];
    const float* We1 = (const float*)d_in[4];
    const float* be1 = (const float*)d_in[5];
    const float* We2 = (const float*)d_in[6];
    const float* be2 = (const float*)d_in[7];
    const float* Wa1 = (const float*)d_in[8];
    const float* ba1 = (const float*)d_in[9];
    const float* Wa2 = (const float*)d_in[10];
    const float* ba2 = (const float*)d_in[11];
    const float* Wn1 = (const float*)d_in[12];
    const float* bn1 = (const float*)d_in[13];
    const float* Wn2 = (const float*)d_in[14];
    const float* bn2 = (const float*)d_in[15];

    int nNodes = in_sizes[0] / 64;
    int nEdges = in_sizes[2];

    float* out   = (float*)d_out;
    float* out_n = out;                              // [N,64]
    float* out_e = out + (size_t)nNodes * 64;        // [E,64]

    int smem_pre  = 64 * 72 * 2 * 2;                             // 18432
    int smem_edge = (64 * 48 + 64 * 144) * 4 + 64 * 4 + 2 * 64 * 4;  // 49920
    int smem_node = (64 * 144) * 2 * 4;                          // 73728

    cudaFuncSetAttribute(node_pre_kernel, cudaFuncAttributeMaxDynamicSharedMemorySize, smem_pre);
    cudaFuncSetAttribute(edge_kernel,     cudaFuncAttributeMaxDynamicSharedMemorySize, smem_edge);
    cudaFuncSetAttribute(node_kernel,     cudaFuncAttributeMaxDynamicSharedMemorySize, smem_node);

    pack_kernel<<<128, 256>>>(We1, Wa1, be1, ba1, We2, Wa2, Wn1, Wn2);
    init_kernel<<<256, 256>>>(nNodes);
    node_pre_kernel<<<(nNodes + 63) / 64, 256, smem_pre>>>(nf, nNodes);
    edge_kernel<<<(nEdges + 63) / 64, 512, smem_edge>>>(ef, src, dst, be2, ba2, out_e, nEdges);
    node_kernel<<<(nNodes + 63) / 64, 256, smem_node>>>(nf, bn1, bn2, out_n, nNodes);
}

// round 13
// speedup vs baseline: 3.5798x; 1.3086x over previous
#include <cuda_runtime.h>
#include <cuda_bf16.h>
#include <cuda_fp16.h>
#include <math.h>

#define MAX_NN 50000

// ---------------- scratch (static device memory; no allocs) ----------------
// g_preh[n][256 uint]: fp16 half2-packed, PERMUTED like the old fp32 g_pre:
//   old float4 index f = n*128 + gi*16 + q*4 + m  ->  uint2 at g_preh[2*f..2*f+1]
//   (uint = half2 of the float4's (x,y) / (z,w)). Row = 64 uint4.
//   dst half (gi>=4) has b1 bias FOLDED IN (pre-quantization).
__device__ __align__(16) unsigned g_preh[(size_t)MAX_NN * 256];
__device__ float g_denom[MAX_NN];
// g_agg[n][64] PERMUTED: p = ng2*16 + q*4 + nt*2 + e  <->  natural c = ng2*16 + nt*8 + q*2 + e
__device__ float g_agg[MAX_NN * 64];
__device__ __align__(16) float g_b1p[256];        // layer1 bias, permuted (no half)
__device__ float g_wa2n[128];                     // Wa2 natural
// packed B-fragments, layout [ks][cb][q]: warp LDG of fixed (ks,nt) reads 512B contiguous
// uint4 = {bh(k0,k1), bh(k8,k9), bl(k0,k1), bl(k8,k9)}
__device__ __align__(16) uint4 g_w1f[2 * 256 * 4];    // edge W1e   [ks(2)][cb(256)][q]
__device__ __align__(16) uint4 g_w2f[8 * 64 * 4];     // edge We2   [ks(8)][cb(64)][q]
__device__ __align__(16) uint4 g_w1pf[4 * 512 * 4];   // node-pre W [ks(4)][cb(512)][q]
__device__ __align__(16) uint4 g_wn1f[8 * 128 * 4];   // node Wn1   [ks(8)][cb(128)][q]
__device__ __align__(16) uint4 g_wn2f[8 * 64 * 4];    // node Wn2   [ks(8)][cb(64)][q]

__device__ __forceinline__ unsigned pk2(__nv_bfloat16 a, __nv_bfloat16 b) {
    return ((unsigned)__bfloat16_as_ushort(b) << 16) | (unsigned)__bfloat16_as_ushort(a);
}

__device__ __forceinline__ uint4 mk_frag(float f0, float f1, float f2, float f3) {
    __nv_bfloat16 h0 = __float2bfloat16_rn(f0), h1 = __float2bfloat16_rn(f1);
    __nv_bfloat16 h2 = __float2bfloat16_rn(f2), h3 = __float2bfloat16_rn(f3);
    uint4 v;
    v.x = pk2(h0, h1);
    v.y = pk2(h2, h3);
    v.z = pk2(__float2bfloat16_rn(f0 - __bfloat162float(h0)),
              __float2bfloat16_rn(f1 - __bfloat162float(h1)));
    v.w = pk2(__float2bfloat16_rn(f2 - __bfloat162float(h2)),
              __float2bfloat16_rn(f3 - __bfloat162float(h3)));
    return v;
}

__device__ __forceinline__ void mma_bf16(float* c, const unsigned* a, const unsigned* b) {
    asm volatile(
        "mma.sync.aligned.m16n8k16.row.col.f32.bf16.bf16.f32 "
        "{%0,%1,%2,%3}, {%4,%5,%6,%7}, {%8,%9}, {%0,%1,%2,%3};"
        : "+f"(c[0]), "+f"(c[1]), "+f"(c[2]), "+f"(c[3])
        : "r"(a[0]), "r"(a[1]), "r"(a[2]), "r"(a[3]), "r"(b[0]), "r"(b[1]));
}

__device__ __forceinline__ void red_add4(float* p, float x, float y, float z, float w) {
    asm volatile("red.global.add.v4.f32 [%0], {%1,%2,%3,%4};"
                 :: "l"(p), "f"(x), "f"(y), "f"(z), "f"(w) : "memory");
}

// make {hh, hl} pair for two fp32 values
__device__ __forceinline__ uint2 mk_pair(float c0, float c1) {
    __nv_bfloat16 h0 = __float2bfloat16_rn(c0), h1 = __float2bfloat16_rn(c1);
    uint2 r;
    r.x = pk2(h0, h1);
    r.y = pk2(__float2bfloat16_rn(c0 - __bfloat162float(h0)),
              __float2bfloat16_rn(c1 - __bfloat162float(h1)));
    return r;
}

__device__ __forceinline__ unsigned h2u(float a, float b) {
    __half2 h = __floats2half2_rn(a, b);
    return *(unsigned*)&h;
}
__device__ __forceinline__ float2 u2f(unsigned u) {
    return __half22float2(*(__half2*)&u);
}

// col-pair index u (covering cols 2u,2u+1 of a 16*K tile) -> interleaved pos
__device__ __forceinline__ int pos_of_u(int u) {
    return (u >> 3) * 8 + (u & 3) * 2 + ((u >> 2) & 1);
}

// W1e element: rows 128..159 of (We1|Wa1), k in [0,32), col in [0,256)
__device__ __forceinline__ float w1e_at(const float* We1, const float* Wa1, int k, int c) {
    return (c < 128) ? We1[(128 + k) * 128 + c] : Wa1[(128 + k) * 128 + (c - 128)];
}
// node-pre big-W element: natural out col C in [0,512), k in [0,64)
__device__ __forceinline__ float wpre_at(const float* We1, const float* Wa1, int k, int C) {
    int half = C >> 8, c = C & 255;
    int row = half * 64 + k;
    return (c < 128) ? We1[row * 128 + c] : Wa1[row * 128 + (c - 128)];
}

// ---------------- weight packing ----------------
__global__ void pack_kernel(const float* __restrict__ We1, const float* __restrict__ Wa1,
                            const float* __restrict__ be1, const float* __restrict__ ba1,
                            const float* __restrict__ We2, const float* __restrict__ Wa2,
                            const float* __restrict__ Wn1, const float* __restrict__ Wn2) {
    int i = blockIdx.x * blockDim.x + threadIdx.x;
    if (i < 256) {        // g_b1p permuted
        int ng = i >> 6, qq = (i >> 4) & 3, nt = (i >> 1) & 7, e = i & 1;
        int c = ng * 64 + nt * 8 + qq * 2 + e;
        g_b1p[i] = (c < 128) ? be1[c] : ba1[c - 128];
    }
    if (i < 128) g_wa2n[i] = Wa2[i];
    if (i < 2048) {       // g_w1f [ks][cb][q]: ks = i>>10, cb = (i>>2)&255, q = i&3
        int ks = i >> 10, cb = (i >> 2) & 255, qq = i & 3;
        int ka = ks * 16 + 2 * qq;
        g_w1f[i] = mk_frag(w1e_at(We1, Wa1, ka, cb),     w1e_at(We1, Wa1, ka + 1, cb),
                           w1e_at(We1, Wa1, ka + 8, cb), w1e_at(We1, Wa1, ka + 9, cb));
    }
    if (i < 2048) {       // g_w2f [ks][cb][q]: ks = i>>8, cb = (i>>2)&63, q = i&3
        int ks = i >> 8, cb = (i >> 2) & 63, qq = i & 3;
        int ka = ks * 16 + 2 * qq;
        g_w2f[i] = mk_frag(We2[ka * 64 + cb],       We2[(ka + 1) * 64 + cb],
                           We2[(ka + 8) * 64 + cb], We2[(ka + 9) * 64 + cb]);
    }
    if (i < 8192) {       // g_w1pf [ks][cb][q]: ks = i>>11, cb = (i>>2)&511, q = i&3
        int ks = i >> 11, cb = (i >> 2) & 511, qq = i & 3;
        int ka = ks * 16 + 2 * qq;
        g_w1pf[i] = mk_frag(wpre_at(We1, Wa1, ka, cb),     wpre_at(We1, Wa1, ka + 1, cb),
                            wpre_at(We1, Wa1, ka + 8, cb), wpre_at(We1, Wa1, ka + 9, cb));
    }
    if (i < 4096) {       // g_wn1f [ks][cb][q]: ks = i>>9, cb = (i>>2)&127, q = i&3
        int ks = i >> 9, cb = (i >> 2) & 127, qq = i & 3;
        int ka = ks * 16 + 2 * qq;
        g_wn1f[i] = mk_frag(Wn1[ka * 128 + cb],       Wn1[(ka + 1) * 128 + cb],
                            Wn1[(ka + 8) * 128 + cb], Wn1[(ka + 9) * 128 + cb]);
    }
    if (i < 2048) {       // g_wn2f [ks][cb][q]
        int ks = i >> 8, cb = (i >> 2) & 63, qq = i & 3;
        int ka = ks * 16 + 2 * qq;
        g_wn2f[i] = mk_frag(Wn2[ka * 64 + cb],       Wn2[(ka + 1) * 64 + cb],
                            Wn2[(ka + 8) * 64 + cb], Wn2[(ka + 9) * 64 + cb]);
    }
}

__global__ void init_kernel(int nNodes) {
    int i = blockIdx.x * blockDim.x + threadIdx.x;
    int stride = gridDim.x * blockDim.x;
    float4* a4 = (float4*)g_agg;
    for (int j = i; j < nNodes * 16; j += stride) a4[j] = make_float4(0.f, 0.f, 0.f, 0.f);
    for (int j = i; j < nNodes; j += stride) g_denom[j] = 0.f;
}

// ---------------- node precompute (mma): preh = fp16(nf @ Wbig [+b1 in dst half]) ----------------
__global__ __launch_bounds__(256) void node_pre_kernel(const float* __restrict__ nf, int nNodes) {
    extern __shared__ char smraw[];
    __nv_bfloat16* s_ah = (__nv_bfloat16*)smraw;   // 64*72
    __nv_bfloat16* s_al = s_ah + 64 * 72;          // 64*72
    const int tid = threadIdx.x;
    const int lane = tid & 31, w = tid >> 5;
    const int fr = lane >> 2, q = lane & 3, fc2 = q * 2;
    const int n0 = blockIdx.x * 64;

    for (int i = tid; i < 64 * 64; i += 256) {
        int r = i >> 6, c = i & 63;
        int n = n0 + r;
        float v = (n < nNodes) ? __ldg(nf + (size_t)n * 64 + c) : 0.f;
        __nv_bfloat16 h = __float2bfloat16_rn(v);
        s_ah[r * 72 + c] = h;
        s_al[r * 72 + c] = __float2bfloat16_rn(v - __bfloat162float(h));
    }
    __syncthreads();

    const int mg = w & 3, ngw = w >> 2;
    const int r0 = mg * 16 + fr, r1 = r0 + 8;

    unsigned ah[4][4], al[4][4];
#pragma unroll
    for (int ks = 0; ks < 4; ks++) {
        int kb = ks * 16;
        ah[ks][0] = *(const unsigned*)(s_ah + r0 * 72 + kb + fc2);
        ah[ks][1] = *(const unsigned*)(s_ah + r1 * 72 + kb + fc2);
        ah[ks][2] = *(const unsigned*)(s_ah + r0 * 72 + kb + fc2 + 8);
        ah[ks][3] = *(const unsigned*)(s_ah + r1 * 72 + kb + fc2 + 8);
        al[ks][0] = *(const unsigned*)(s_al + r0 * 72 + kb + fc2);
        al[ks][1] = *(const unsigned*)(s_al + r1 * 72 + kb + fc2);
        al[ks][2] = *(const unsigned*)(s_al + r0 * 72 + kb + fc2 + 8);
        al[ks][3] = *(const unsigned*)(s_al + r1 * 72 + kb + fc2 + 8);
    }

#pragma unroll
    for (int nl = 0; nl < 4; nl++) {
        int gi = nl * 2 + ngw;
        float acc[8][4];
#pragma unroll
        for (int nt = 0; nt < 8; nt++)
#pragma unroll
            for (int j = 0; j < 4; j++) acc[nt][j] = 0.f;
#pragma unroll
        for (int ks = 0; ks < 4; ks++) {
#pragma unroll
            for (int nt = 0; nt < 8; nt++) {
                int cbn = gi * 64 + nt * 8 + fr;
                uint4 wb = __ldg(g_w1pf + ((ks * 512 + cbn) << 2) + q);
                unsigned bh[2] = {wb.x, wb.y};
                unsigned bl[2] = {wb.z, wb.w};
                mma_bf16(acc[nt], ah[ks], bh);
                mma_bf16(acc[nt], ah[ks], bl);
                mma_bf16(acc[nt], al[ks], bh);
            }
        }
        // quantize to fp16 half2-packed, bias folded into dst half
        uint4* gp = (uint4*)g_preh;     // row = 64 uint4
        const float4* B4 = (const float4*)g_b1p;
        int nr0 = n0 + r0, nr1 = n0 + r1;
        float4 bv[4];
#pragma unroll
        for (int m = 0; m < 4; m++)
            bv[m] = (gi >= 4) ? __ldg(B4 + (gi - 4) * 16 + q * 4 + m)
                              : make_float4(0.f, 0.f, 0.f, 0.f);
        if (nr0 < nNodes) {
            uint4 o0, o1;
            o0.x = h2u(acc[0][0] + bv[0].x, acc[0][1] + bv[0].y);
            o0.y = h2u(acc[1][0] + bv[0].z, acc[1][1] + bv[0].w);
            o0.z = h2u(acc[2][0] + bv[1].x, acc[2][1] + bv[1].y);
            o0.w = h2u(acc[3][0] + bv[1].z, acc[3][1] + bv[1].w);
            o1.x = h2u(acc[4][0] + bv[2].x, acc[4][1] + bv[2].y);
            o1.y = h2u(acc[5][0] + bv[2].z, acc[5][1] + bv[2].w);
            o1.z = h2u(acc[6][0] + bv[3].x, acc[6][1] + bv[3].y);
            o1.w = h2u(acc[7][0] + bv[3].z, acc[7][1] + bv[3].w);
            gp[(size_t)nr0 * 64 + gi * 8 + q * 2]     = o0;
            gp[(size_t)nr0 * 64 + gi * 8 + q * 2 + 1] = o1;
        }
        if (nr1 < nNodes) {
            uint4 o0, o1;
            o0.x = h2u(acc[0][2] + bv[0].x, acc[0][3] + bv[0].y);
            o0.y = h2u(acc[1][2] + bv[0].z, acc[1][3] + bv[0].w);
            o0.z = h2u(acc[2][2] + bv[1].x, acc[2][3] + bv[1].y);
            o0.w = h2u(acc[3][2] + bv[1].z, acc[3][3] + bv[1].w);
            o1.x = h2u(acc[4][2] + bv[2].x, acc[4][3] + bv[2].y);
            o1.y = h2u(acc[5][2] + bv[2].z, acc[5][3] + bv[2].w);
            o1.z = h2u(acc[6][2] + bv[3].x, acc[6][3] + bv[3].y);
            o1.w = h2u(acc[7][2] + bv[3].z, acc[7][3] + bv[3].w);
            gp[(size_t)nr1 * 64 + gi * 8 + q * 2]     = o0;
            gp[(size_t)nr1 * 64 + gi * 8 + q * 2 + 1] = o1;
        }
    }
}

// ---------------- fused edge kernel (bf16x3 mma, fp16 gather) ----------------
// 64 edges/block, 512 threads, 2 CTA/SM. Layer1: warp = m16 (mg=w&3) x n64 (ng=w>>2).
__global__ __launch_bounds__(512, 2) void edge_kernel(
    const float* __restrict__ ef, const int* __restrict__ src, const int* __restrict__ dst,
    const float* __restrict__ be2, const float* __restrict__ ba2,
    float* __restrict__ out_e, int nEdges) {
    extern __shared__ unsigned smw[];
    unsigned* s_ef = smw;                        // 64*48 words
    unsigned* s_h  = smw + 64 * 48;              // 64*144 words
    float* s_logit = (float*)(smw + 12288);      // 64
    int*   s_src   = (int*)(s_logit + 64);       // 64
    int*   s_dst   = s_src + 64;                 // 64

    const int tid = threadIdx.x;
    const int e0 = blockIdx.x * 64;
    const int lane = tid & 31, w = tid >> 5;
    const int fr = lane >> 2, q = lane & 3, fc2 = q * 2;

    if (tid < 64) s_logit[tid] = __ldg(ba2);
    if (tid >= 64 && tid < 128) {
        int i = tid - 64, e = e0 + i;
        s_src[i] = (e < nEdges) ? __ldg(src + e) : 0;
        s_dst[i] = (e < nEdges) ? __ldg(dst + e) : 0;
    }
    {   // stage ef: one float4 per thread -> 2 interleaved pairs
        int r = tid >> 3, m = tid & 7;
        int e = e0 + r;
        float4 v = make_float4(0.f, 0.f, 0.f, 0.f);
        if (e < nEdges) v = __ldg((const float4*)ef + (size_t)e * 8 + m);
        int u0 = 2 * m;
        *(uint2*)(s_ef + r * 48 + pos_of_u(u0) * 2)     = mk_pair(v.x, v.y);
        *(uint2*)(s_ef + r * 48 + pos_of_u(u0 + 1) * 2) = mk_pair(v.z, v.w);
    }
    __syncthreads();

    const int mg = w & 3, ng = w >> 2;
    const int r0 = mg * 16 + fr, r1 = r0 + 8;

    // ================= Layer 1 =================
    {
        float acc[8][4];
        {   // fp16 gather-init (bias pre-folded into dst half)
            const uint4* Ph = (const uint4*)g_preh;   // row = 64 uint4
            int off = ng * 8 + q * 2;
            size_t bs0 = (size_t)s_src[r0] * 64 + off;
            size_t bd0 = (size_t)s_dst[r0] * 64 + 32 + off;
            size_t bs1 = (size_t)s_src[r1] * 64 + off;
            size_t bd1 = (size_t)s_dst[r1] * 64 + 32 + off;
            uint4 sa0 = __ldg(Ph + bs0), sb0 = __ldg(Ph + bs0 + 1);
            uint4 da0 = __ldg(Ph + bd0), db0 = __ldg(Ph + bd0 + 1);
            uint4 sa1 = __ldg(Ph + bs1), sb1 = __ldg(Ph + bs1 + 1);
            uint4 da1 = __ldg(Ph + bd1), db1 = __ldg(Ph + bd1 + 1);
            unsigned su0[8] = {sa0.x, sa0.y, sa0.z, sa0.w, sb0.x, sb0.y, sb0.z, sb0.w};
            unsigned du0[8] = {da0.x, da0.y, da0.z, da0.w, db0.x, db0.y, db0.z, db0.w};
            unsigned su1[8] = {sa1.x, sa1.y, sa1.z, sa1.w, sb1.x, sb1.y, sb1.z, sb1.w};
            unsigned du1[8] = {da1.x, da1.y, da1.z, da1.w, db1.x, db1.y, db1.z, db1.w};
#pragma unroll
            for (int nt = 0; nt < 8; nt++) {
                float2 s0 = u2f(su0[nt]), d0 = u2f(du0[nt]);
                float2 s1 = u2f(su1[nt]), d1 = u2f(du1[nt]);
                acc[nt][0] = s0.x + d0.x;  acc[nt][1] = s0.y + d0.y;
                acc[nt][2] = s1.x + d1.x;  acc[nt][3] = s1.y + d1.y;
            }
        }
        // += ef @ W1e (bf16x3)
#pragma unroll
        for (int ks = 0; ks < 2; ks++) {
            uint4 va0 = *(const uint4*)(s_ef + r0 * 48 + ks * 16 + q * 4);
            uint4 va1 = *(const uint4*)(s_ef + r1 * 48 + ks * 16 + q * 4);
            unsigned ah[4] = {va0.x, va1.x, va0.z, va1.z};
            unsigned al[4] = {va0.y, va1.y, va0.w, va1.w};
#pragma unroll
            for (int nt = 0; nt < 8; nt++) {
                int cb = ng * 64 + nt * 8 + fr;
                uint4 wb = __ldg(g_w1f + ((ks * 256 + cb) << 2) + q);
                unsigned bh[2] = {wb.x, wb.y};
                unsigned bl[2] = {wb.z, wb.w};
                mma_bf16(acc[nt], ah, bh);
                mma_bf16(acc[nt], ah, bl);
                mma_bf16(acc[nt], al, bh);
            }
        }
        // ReLU: We-half -> interleaved smem; Wa-half -> logit partials
        if (ng < 2) {
#pragma unroll
            for (int nt = 0; nt < 8; nt++) {
                int pos = (ng * 4 + (nt >> 1)) * 8 + q * 2 + (nt & 1);
                *(uint2*)(s_h + r0 * 144 + pos * 2) =
                    mk_pair(fmaxf(acc[nt][0], 0.f), fmaxf(acc[nt][1], 0.f));
                *(uint2*)(s_h + r1 * 144 + pos * 2) =
                    mk_pair(fmaxf(acc[nt][2], 0.f), fmaxf(acc[nt][3], 0.f));
            }
        } else {
            float p0 = 0.f, p1 = 0.f;
#pragma unroll
            for (int nt = 0; nt < 8; nt++) {
                int c = (ng - 2) * 64 + nt * 8 + fc2;
                float2 wv = __ldg((const float2*)g_wa2n + (c >> 1));
                p0 += fmaxf(acc[nt][0], 0.f) * wv.x + fmaxf(acc[nt][1], 0.f) * wv.y;
                p1 += fmaxf(acc[nt][2], 0.f) * wv.x + fmaxf(acc[nt][3], 0.f) * wv.y;
            }
            p0 += __shfl_xor_sync(0xFFFFFFFFu, p0, 1);
            p0 += __shfl_xor_sync(0xFFFFFFFFu, p0, 2);
            p1 += __shfl_xor_sync(0xFFFFFFFFu, p1, 1);
            p1 += __shfl_xor_sync(0xFFFFFFFFu, p1, 2);
            if (q == 0) {
                atomicAdd(&s_logit[r0], p0);
                atomicAdd(&s_logit[r1], p1);
            }
        }
    }
    __syncthreads();

    // ================= Layer 2 =================
    const int ng2 = w >> 2;
    float acc2[2][4];
#pragma unroll
    for (int nt = 0; nt < 2; nt++)
#pragma unroll
        for (int j = 0; j < 4; j++) acc2[nt][j] = 0.f;
#pragma unroll
    for (int ks = 0; ks < 8; ks++) {
        uint4 va0 = *(const uint4*)(s_h + r0 * 144 + ks * 16 + q * 4);
        uint4 va1 = *(const uint4*)(s_h + r1 * 144 + ks * 16 + q * 4);
        unsigned ah[4] = {va0.x, va1.x, va0.z, va1.z};
        unsigned al[4] = {va0.y, va1.y, va0.w, va1.w};
#pragma unroll
        for (int nt = 0; nt < 2; nt++) {
            int cb = ng2 * 16 + nt * 8 + fr;
            uint4 wb = __ldg(g_w2f + ((ks * 64 + cb) << 2) + q);
            unsigned bh[2] = {wb.x, wb.y};
            unsigned bl[2] = {wb.z, wb.w};
            mma_bf16(acc2[nt], ah, bh);
            mma_bf16(acc2[nt], ah, bl);
            mma_bf16(acc2[nt], al, bh);
        }
    }

    // ---- epilogue: scatter (from regs) + staged coalesced out_e ----
    {
        float ex0 = expf(s_logit[r0]);
        float ex1 = expf(s_logit[r1]);
        int d0 = s_dst[r0], d1 = s_dst[r1];
        int eg0 = e0 + r0, eg1 = e0 + r1;
        float2 b2a = __ldg((const float2*)be2 + ((ng2 * 16 + fc2) >> 1));
        float2 b2b = __ldg((const float2*)be2 + ((ng2 * 16 + 8 + fc2) >> 1));
        float v00a = acc2[0][0] + b2a.x, v01a = acc2[0][1] + b2a.y;
        float v10a = acc2[1][0] + b2b.x, v11a = acc2[1][1] + b2b.y;
        float v00b = acc2[0][2] + b2a.x, v01b = acc2[0][3] + b2a.y;
        float v10b = acc2[1][2] + b2b.x, v11b = acc2[1][3] + b2b.y;
        if (eg0 < nEdges)
            red_add4(&g_agg[d0 * 64 + ng2 * 16 + q * 4],
                     v00a * ex0, v01a * ex0, v10a * ex0, v11a * ex0);
        if (eg1 < nEdges)
            red_add4(&g_agg[d1 * 64 + ng2 * 16 + q * 4],
                     v00b * ex1, v01b * ex1, v10b * ex1, v11b * ex1);
        if (ng2 == 0 && q == 0) {
            if (eg0 < nEdges) atomicAdd(&g_denom[d0], ex0);
            if (eg1 < nEdges) atomicAdd(&g_denom[d1], ex1);
        }
        __syncthreads();   // all warps done reading s_ef/s_h -> reuse as s_out
        float* s_out = (float*)smw;  // 64 x 72 floats
        int cA = ng2 * 16 + fc2;
        *(float2*)(s_out + r0 * 72 + cA)     = make_float2(v00a, v01a);
        *(float2*)(s_out + r0 * 72 + cA + 8) = make_float2(v10a, v11a);
        *(float2*)(s_out + r1 * 72 + cA)     = make_float2(v00b, v01b);
        *(float2*)(s_out + r1 * 72 + cA + 8) = make_float2(v10b, v11b);
    }
    __syncthreads();
    {   // coalesced write: 512 threads x 2 float4 = 64 edges x 64 floats
        const float* s_out = (const float*)smw;
        int base = tid * 4;
#pragma unroll
        for (int h = 0; h < 2; h++) {
            int j = base + h * 2048;
            int e = j >> 6, c = j & 63;
            if (e0 + e < nEdges) {
                float4 v = *(const float4*)(s_out + e * 72 + c);
                *(float4*)(out_e + (size_t)(e0 + e) * 64 + c) = v;
            }
        }
    }
}

// ---------------- node MLP (mma, interleaved-fragment smem) ----------------
// 64 nodes/block, 256 threads = 8 warps. Layer1: mg=w&3 x ng=w>>2 (n64). Layer2: n32.
__global__ __launch_bounds__(256) void node_kernel(
    const float* __restrict__ nf,
    const float* __restrict__ bn1, const float* __restrict__ bn2,
    float* __restrict__ out_n, int nNodes) {
    extern __shared__ unsigned smw[];
    unsigned* s_x = smw;             // 64*144 words
    unsigned* s_h = smw + 64 * 144;  // 64*144 words
    const int tid = threadIdx.x;
    const int lane = tid & 31, w = tid >> 5;
    const int fr = lane >> 2, q = lane & 3, fc2 = q * 2;
    const int n0 = blockIdx.x * 64;

    for (int i = tid; i < 64 * 64; i += 256) {
        int r = i >> 6, u = i & 63;     // col pair (2u, 2u+1) of 128
        int n = n0 + r;
        float2 v = make_float2(0.f, 0.f);
        if (n < nNodes) {
            if (u < 32) {   // agg cols, permuted storage
                int c = 2 * u;
                int g2 = c >> 4, ww = c & 15;
                int nt = ww >> 3, qq = (ww >> 1) & 3;
                int p = g2 * 16 + qq * 4 + nt * 2;
                float dn = fmaxf(g_denom[n], 1e-38f);
                float2 av = *(const float2*)(g_agg + (size_t)n * 64 + p);
                v.x = av.x / dn; v.y = av.y / dn;
            } else {
                v = __ldg((const float2*)(nf + (size_t)n * 64) + (u - 32));
            }
        }
        *(uint2*)(s_x + r * 144 + pos_of_u(u) * 2) = mk_pair(v.x, v.y);
    }
    __syncthreads();

    const int mg = w & 3, ng = w >> 2;
    const int r0 = mg * 16 + fr, r1 = r0 + 8;

    // ---- layer1: h = relu(x @ Wn1 + bn1) ----
    {
        float acc[8][4];
#pragma unroll
        for (int nt = 0; nt < 8; nt++) {
            int c = ng * 64 + nt * 8 + fc2;
            float2 bv = __ldg((const float2*)bn1 + (c >> 1));
            acc[nt][0] = bv.x; acc[nt][1] = bv.y;
            acc[nt][2] = bv.x; acc[nt][3] = bv.y;
        }
#pragma unroll
        for (int ks = 0; ks < 8; ks++) {
            uint4 va0 = *(const uint4*)(s_x + r0 * 144 + ks * 16 + q * 4);
            uint4 va1 = *(const uint4*)(s_x + r1 * 144 + ks * 16 + q * 4);
            unsigned ah[4] = {va0.x, va1.x, va0.z, va1.z};
            unsigned al[4] = {va0.y, va1.y, va0.w, va1.w};
#pragma unroll
            for (int nt = 0; nt < 8; nt++) {
                int cb = ng * 64 + nt * 8 + fr;
                uint4 wb = __ldg(g_wn1f + ((ks * 128 + cb) << 2) + q);
                unsigned bh[2] = {wb.x, wb.y};
                unsigned bl[2] = {wb.z, wb.w};
                mma_bf16(acc[nt], ah, bh);
                mma_bf16(acc[nt], ah, bl);
                mma_bf16(acc[nt], al, bh);
            }
        }
#pragma unroll
        for (int nt = 0; nt < 8; nt++) {
            int pos = (ng * 4 + (nt >> 1)) * 8 + q * 2 + (nt & 1);
            *(uint2*)(s_h + r0 * 144 + pos * 2) =
                mk_pair(fmaxf(acc[nt][0], 0.f), fmaxf(acc[nt][1], 0.f));
            *(uint2*)(s_h + r1 * 144 + pos * 2) =
                mk_pair(fmaxf(acc[nt][2], 0.f), fmaxf(acc[nt][3], 0.f));
        }
    }
    __syncthreads();

    // ---- layer2: out = h @ Wn2 + bn2 ----
    const int ng2 = w >> 2;
    float acc2[4][4];
#pragma unroll
    for (int nt = 0; nt < 4; nt++) {
        int c = ng2 * 32 + nt * 8 + fc2;
        float2 bv = __ldg((const float2*)bn2 + (c >> 1));
        acc2[nt][0] = bv.x; acc2[nt][1] = bv.y;
        acc2[nt][2] = bv.x; acc2[nt][3] = bv.y;
    }
#pragma unroll
    for (int ks = 0; ks < 8; ks++) {
        uint4 va0 = *(const uint4*)(s_h + r0 * 144 + ks * 16 + q * 4);
        uint4 va1 = *(const uint4*)(s_h + r1 * 144 + ks * 16 + q * 4);
        unsigned ah[4] = {va0.x, va1.x, va0.z, va1.z};
        unsigned al[4] = {va0.y, va1.y, va0.w, va1.w};
#pragma unroll
        for (int nt = 0; nt < 4; nt++) {
            int cb = ng2 * 32 + nt * 8 + fr;
            uint4 wb = __ldg(g_wn2f + ((ks * 64 + cb) << 2) + q);
            unsigned bh[2] = {wb.x, wb.y};
            unsigned bl[2] = {wb.z, wb.w};
            mma_bf16(acc2[nt], ah, bh);
            mma_bf16(acc2[nt], ah, bl);
            mma_bf16(acc2[nt], al, bh);
        }
    }
    {
        int nr0 = n0 + r0, nr1 = n0 + r1;
#pragma unroll
        for (int nt = 0; nt < 4; nt++) {
            int c = ng2 * 32 + nt * 8 + fc2;
            if (nr0 < nNodes)
                *(float2*)(out_n + (size_t)nr0 * 64 + c) = make_float2(acc2[nt][0], acc2[nt][1]);
            if (nr1 < nNodes)
                *(float2*)(out_n + (size_t)nr1 * 64 + c) = make_float2(acc2[nt][2], acc2[nt][3]);
        }
    }
}

// ---------------- launch ----------------
extern "C" void kernel_launch(void* const* d_in, const int* in_sizes, int n_in,
                              void* d_out, int out_size) {
    const float* nf  = (const float*)d_in[0];
    const float* ef  = (const float*)d_in[1];
    const int*   src = (const int*)d_in[2];
    const int*   dst = (const int*)d_in[3];
    const float* We1 = (const float*)d_in[4];
    const float* be1 = (const float*)d_in[5];
    const float* We2 = (const float*)d_in[6];
    const float* be2 = (const float*)d_in[7];
    const float* Wa1 = (const float*)d_in[8];
    const float* ba1 = (const float*)d_in[9];
    const float* Wa2 = (const float*)d_in[10];
    const float* ba2 = (const float*)d_in[11];
    const float* Wn1 = (const float*)d_in[12];
    const float* bn1 = (const float*)d_in[13];
    const float* Wn2 = (const float*)d_in[14];
    const float* bn2 = (const float*)d_in[15];

    int nNodes = in_sizes[0] / 64;
    int nEdges = in_sizes[2];

    float* out   = (float*)d_out;
    float* out_n = out;                              // [N,64]
    float* out_e = out + (size_t)nNodes * 64;        // [E,64]

    int smem_pre  = 64 * 72 * 2 * 2;                             // 18432
    int smem_edge = (64 * 48 + 64 * 144) * 4 + 64 * 4 + 2 * 64 * 4;  // 49920
    int smem_node = (64 * 144) * 2 * 4;                          // 73728

    cudaFuncSetAttribute(node_pre_kernel, cudaFuncAttributeMaxDynamicSharedMemorySize, smem_pre);
    cudaFuncSetAttribute(edge_kernel,     cudaFuncAttributeMaxDynamicSharedMemorySize, smem_edge);
    cudaFuncSetAttribute(node_kernel,     cudaFuncAttributeMaxDynamicSharedMemorySize, smem_node);

    pack_kernel<<<128, 256>>>(We1, Wa1, be1, ba1, We2, Wa2, Wn1, Wn2);
    init_kernel<<<256, 256>>>(nNodes);
    node_pre_kernel<<<(nNodes + 63) / 64, 256, smem_pre>>>(nf, nNodes);
    edge_kernel<<<(nEdges + 63) / 64, 512, smem_edge>>>(ef, src, dst, be2, ba2, out_e, nEdges);
    node_kernel<<<(nNodes + 63) / 64, 256, smem_node>>>(nf, bn1, bn2, out_n, nNodes);
}

// round 15
// speedup vs baseline: 4.4684x; 1.2482x over previous
#include <cuda_runtime.h>
#include <cuda_bf16.h>
#include <cuda_fp16.h>
#include <math.h>

#define MAX_NN 50000

// ---------------- scratch (static device memory; no allocs) ----------------
// g_preh[n][256 uint]: fp16 half2-packed, permuted; dst half (gi>=4) has b1 FOLDED IN.
__device__ __align__(16) unsigned g_preh[(size_t)MAX_NN * 256];
__device__ float g_denom[MAX_NN];
// g_agg[n][64] PERMUTED: p = ng2*16 + q*4 + nt*2 + e  <->  natural c = ng2*16 + nt*8 + q*2 + e
__device__ float g_agg[MAX_NN * 64];
__device__ __align__(16) float g_b1p[256];        // layer1 bias, permuted (no half)
__device__ float g_wa2n[128];                     // Wa2 natural
// edge weights: fp16 single frags, layout [ks][cb][q], uint2 = {h(k0,k1), h(k8,k9)}
__device__ __align__(8) uint2 g_w1fh[2 * 256 * 4];   // edge W1e
__device__ __align__(8) uint2 g_w2fh[8 * 64 * 4];    // edge We2
// node kernels keep bf16x3: uint4 = {bh(k0,k1), bh(k8,k9), bl(k0,k1), bl(k8,k9)}
__device__ __align__(16) uint4 g_w1pf[4 * 512 * 4];   // node-pre W [ks(4)][cb(512)][q]
__device__ __align__(16) uint4 g_wn1f[8 * 128 * 4];   // node Wn1   [ks(8)][cb(128)][q]
__device__ __align__(16) uint4 g_wn2f[8 * 64 * 4];    // node Wn2   [ks(8)][cb(64)][q]

__device__ __forceinline__ unsigned pk2(__nv_bfloat16 a, __nv_bfloat16 b) {
    return ((unsigned)__bfloat16_as_ushort(b) << 16) | (unsigned)__bfloat16_as_ushort(a);
}

__device__ __forceinline__ uint4 mk_frag(float f0, float f1, float f2, float f3) {
    __nv_bfloat16 h0 = __float2bfloat16_rn(f0), h1 = __float2bfloat16_rn(f1);
    __nv_bfloat16 h2 = __float2bfloat16_rn(f2), h3 = __float2bfloat16_rn(f3);
    uint4 v;
    v.x = pk2(h0, h1);
    v.y = pk2(h2, h3);
    v.z = pk2(__float2bfloat16_rn(f0 - __bfloat162float(h0)),
              __float2bfloat16_rn(f1 - __bfloat162float(h1)));
    v.w = pk2(__float2bfloat16_rn(f2 - __bfloat162float(h2)),
              __float2bfloat16_rn(f3 - __bfloat162float(h3)));
    return v;
}

__device__ __forceinline__ void mma_bf16(float* c, const unsigned* a, const unsigned* b) {
    asm volatile(
        "mma.sync.aligned.m16n8k16.row.col.f32.bf16.bf16.f32 "
        "{%0,%1,%2,%3}, {%4,%5,%6,%7}, {%8,%9}, {%0,%1,%2,%3};"
        : "+f"(c[0]), "+f"(c[1]), "+f"(c[2]), "+f"(c[3])
        : "r"(a[0]), "r"(a[1]), "r"(a[2]), "r"(a[3]), "r"(b[0]), "r"(b[1]));
}

__device__ __forceinline__ void mma_f16(float* c, const unsigned* a, unsigned b0, unsigned b1) {
    asm volatile(
        "mma.sync.aligned.m16n8k16.row.col.f32.f16.f16.f32 "
        "{%0,%1,%2,%3}, {%4,%5,%6,%7}, {%8,%9}, {%0,%1,%2,%3};"
        : "+f"(c[0]), "+f"(c[1]), "+f"(c[2]), "+f"(c[3])
        : "r"(a[0]), "r"(a[1]), "r"(a[2]), "r"(a[3]), "r"(b0), "r"(b1));
}

__device__ __forceinline__ void red_add4(float* p, float x, float y, float z, float w) {
    asm volatile("red.global.add.v4.f32 [%0], {%1,%2,%3,%4};"
                 :: "l"(p), "f"(x), "f"(y), "f"(z), "f"(w) : "memory");
}

// make {hh, hl} bf16 pair for two fp32 values (node kernels)
__device__ __forceinline__ uint2 mk_pair(float c0, float c1) {
    __nv_bfloat16 h0 = __float2bfloat16_rn(c0), h1 = __float2bfloat16_rn(c1);
    uint2 r;
    r.x = pk2(h0, h1);
    r.y = pk2(__float2bfloat16_rn(c0 - __bfloat162float(h0)),
              __float2bfloat16_rn(c1 - __bfloat162float(h1)));
    return r;
}

__device__ __forceinline__ unsigned h2u(float a, float b) {
    __half2 h = __floats2half2_rn(a, b);
    return *(unsigned*)&h;
}
__device__ __forceinline__ float2 u2f(unsigned u) {
    return __half22float2(*(__half2*)&u);
}

// col-pair index u -> interleaved word pos: pos = (u>>3)*8 + (u&3)*2 + ((u>>2)&1)
__device__ __forceinline__ int pos_of_u(int u) {
    return (u >> 3) * 8 + (u & 3) * 2 + ((u >> 2) & 1);
}

// W1e element: rows 128..159 of (We1|Wa1), k in [0,32), col in [0,256)
__device__ __forceinline__ float w1e_at(const float* We1, const float* Wa1, int k, int c) {
    return (c < 128) ? We1[(128 + k) * 128 + c] : Wa1[(128 + k) * 128 + (c - 128)];
}
// node-pre big-W element: natural out col C in [0,512), k in [0,64)
__device__ __forceinline__ float wpre_at(const float* We1, const float* Wa1, int k, int C) {
    int half = C >> 8, c = C & 255;
    int row = half * 64 + k;
    return (c < 128) ? We1[row * 128 + c] : Wa1[row * 128 + (c - 128)];
}

// ---------------- weight packing ----------------
__global__ void pack_kernel(const float* __restrict__ We1, const float* __restrict__ Wa1,
                            const float* __restrict__ be1, const float* __restrict__ ba1,
                            const float* __restrict__ We2, const float* __restrict__ Wa2,
                            const float* __restrict__ Wn1, const float* __restrict__ Wn2) {
    int i = blockIdx.x * blockDim.x + threadIdx.x;
    if (i < 256) {        // g_b1p permuted
        int ng = i >> 6, qq = (i >> 4) & 3, nt = (i >> 1) & 7, e = i & 1;
        int c = ng * 64 + nt * 8 + qq * 2 + e;
        g_b1p[i] = (c < 128) ? be1[c] : ba1[c - 128];
    }
    if (i < 128) g_wa2n[i] = Wa2[i];
    if (i < 2048) {       // g_w1fh [ks][cb][q]: ks = i>>10, cb = (i>>2)&255, q = i&3
        int ks = i >> 10, cb = (i >> 2) & 255, qq = i & 3;
        int ka = ks * 16 + 2 * qq;
        g_w1fh[i] = make_uint2(
            h2u(w1e_at(We1, Wa1, ka, cb),     w1e_at(We1, Wa1, ka + 1, cb)),
            h2u(w1e_at(We1, Wa1, ka + 8, cb), w1e_at(We1, Wa1, ka + 9, cb)));
    }
    if (i < 2048) {       // g_w2fh [ks][cb][q]: ks = i>>8, cb = (i>>2)&63, q = i&3
        int ks = i >> 8, cb = (i >> 2) & 63, qq = i & 3;
        int ka = ks * 16 + 2 * qq;
        g_w2fh[i] = make_uint2(
            h2u(We2[ka * 64 + cb],       We2[(ka + 1) * 64 + cb]),
            h2u(We2[(ka + 8) * 64 + cb], We2[(ka + 9) * 64 + cb]));
    }
    if (i < 8192) {       // g_w1pf [ks][cb][q]
        int ks = i >> 11, cb = (i >> 2) & 511, qq = i & 3;
        int ka = ks * 16 + 2 * qq;
        g_w1pf[i] = mk_frag(wpre_at(We1, Wa1, ka, cb),     wpre_at(We1, Wa1, ka + 1, cb),
                            wpre_at(We1, Wa1, ka + 8, cb), wpre_at(We1, Wa1, ka + 9, cb));
    }
    if (i < 4096) {       // g_wn1f [ks][cb][q]
        int ks = i >> 9, cb = (i >> 2) & 127, qq = i & 3;
        int ka = ks * 16 + 2 * qq;
        g_wn1f[i] = mk_frag(Wn1[ka * 128 + cb],       Wn1[(ka + 1) * 128 + cb],
                            Wn1[(ka + 8) * 128 + cb], Wn1[(ka + 9) * 128 + cb]);
    }
    if (i < 2048) {       // g_wn2f [ks][cb][q]
        int ks = i >> 8, cb = (i >> 2) & 63, qq = i & 3;
        int ka = ks * 16 + 2 * qq;
        g_wn2f[i] = mk_frag(Wn2[ka * 64 + cb],       Wn2[(ka + 1) * 64 + cb],
                            Wn2[(ka + 8) * 64 + cb], Wn2[(ka + 9) * 64 + cb]);
    }
}

__global__ void init_kernel(int nNodes) {
    int i = blockIdx.x * blockDim.x + threadIdx.x;
    int stride = gridDim.x * blockDim.x;
    float4* a4 = (float4*)g_agg;
    for (int j = i; j < nNodes * 16; j += stride) a4[j] = make_float4(0.f, 0.f, 0.f, 0.f);
    for (int j = i; j < nNodes; j += stride) g_denom[j] = 0.f;
}

// ---------------- node precompute (bf16x3 mma): preh = fp16(nf @ Wbig [+b1 in dst half]) ----------------
__global__ __launch_bounds__(256) void node_pre_kernel(const float* __restrict__ nf, int nNodes) {
    extern __shared__ char smraw[];
    __nv_bfloat16* s_ah = (__nv_bfloat16*)smraw;   // 64*72
    __nv_bfloat16* s_al = s_ah + 64 * 72;          // 64*72
    const int tid = threadIdx.x;
    const int lane = tid & 31, w = tid >> 5;
    const int fr = lane >> 2, q = lane & 3, fc2 = q * 2;
    const int n0 = blockIdx.x * 64;

    for (int i = tid; i < 64 * 64; i += 256) {
        int r = i >> 6, c = i & 63;
        int n = n0 + r;
        float v = (n < nNodes) ? __ldg(nf + (size_t)n * 64 + c) : 0.f;
        __nv_bfloat16 h = __float2bfloat16_rn(v);
        s_ah[r * 72 + c] = h;
        s_al[r * 72 + c] = __float2bfloat16_rn(v - __bfloat162float(h));
    }
    __syncthreads();

    const int mg = w & 3, ngw = w >> 2;
    const int r0 = mg * 16 + fr, r1 = r0 + 8;

    unsigned ah[4][4], al[4][4];
#pragma unroll
    for (int ks = 0; ks < 4; ks++) {
        int kb = ks * 16;
        ah[ks][0] = *(const unsigned*)(s_ah + r0 * 72 + kb + fc2);
        ah[ks][1] = *(const unsigned*)(s_ah + r1 * 72 + kb + fc2);
        ah[ks][2] = *(const unsigned*)(s_ah + r0 * 72 + kb + fc2 + 8);
        ah[ks][3] = *(const unsigned*)(s_ah + r1 * 72 + kb + fc2 + 8);
        al[ks][0] = *(const unsigned*)(s_al + r0 * 72 + kb + fc2);
        al[ks][1] = *(const unsigned*)(s_al + r1 * 72 + kb + fc2);
        al[ks][2] = *(const unsigned*)(s_al + r0 * 72 + kb + fc2 + 8);
        al[ks][3] = *(const unsigned*)(s_al + r1 * 72 + kb + fc2 + 8);
    }

#pragma unroll
    for (int nl = 0; nl < 4; nl++) {
        int gi = nl * 2 + ngw;
        float acc[8][4];
#pragma unroll
        for (int nt = 0; nt < 8; nt++)
#pragma unroll
            for (int j = 0; j < 4; j++) acc[nt][j] = 0.f;
#pragma unroll
        for (int ks = 0; ks < 4; ks++) {
#pragma unroll
            for (int nt = 0; nt < 8; nt++) {
                int cbn = gi * 64 + nt * 8 + fr;
                uint4 wb = __ldg(g_w1pf + ((ks * 512 + cbn) << 2) + q);
                unsigned bh[2] = {wb.x, wb.y};
                unsigned bl[2] = {wb.z, wb.w};
                mma_bf16(acc[nt], ah[ks], bh);
                mma_bf16(acc[nt], ah[ks], bl);
                mma_bf16(acc[nt], al[ks], bh);
            }
        }
        // quantize to fp16 half2-packed, bias folded into dst half
        uint4* gp = (uint4*)g_preh;     // row = 64 uint4
        const float4* B4 = (const float4*)g_b1p;
        int nr0 = n0 + r0, nr1 = n0 + r1;
        float4 bv[4];
#pragma unroll
        for (int m = 0; m < 4; m++)
            bv[m] = (gi >= 4) ? __ldg(B4 + (gi - 4) * 16 + q * 4 + m)
                              : make_float4(0.f, 0.f, 0.f, 0.f);
        if (nr0 < nNodes) {
            uint4 o0, o1;
            o0.x = h2u(acc[0][0] + bv[0].x, acc[0][1] + bv[0].y);
            o0.y = h2u(acc[1][0] + bv[0].z, acc[1][1] + bv[0].w);
            o0.z = h2u(acc[2][0] + bv[1].x, acc[2][1] + bv[1].y);
            o0.w = h2u(acc[3][0] + bv[1].z, acc[3][1] + bv[1].w);
            o1.x = h2u(acc[4][0] + bv[2].x, acc[4][1] + bv[2].y);
            o1.y = h2u(acc[5][0] + bv[2].z, acc[5][1] + bv[2].w);
            o1.z = h2u(acc[6][0] + bv[3].x, acc[6][1] + bv[3].y);
            o1.w = h2u(acc[7][0] + bv[3].z, acc[7][1] + bv[3].w);
            gp[(size_t)nr0 * 64 + gi * 8 + q * 2]     = o0;
            gp[(size_t)nr0 * 64 + gi * 8 + q * 2 + 1] = o1;
        }
        if (nr1 < nNodes) {
            uint4 o0, o1;
            o0.x = h2u(acc[0][2] + bv[0].x, acc[0][3] + bv[0].y);
            o0.y = h2u(acc[1][2] + bv[0].z, acc[1][3] + bv[0].w);
            o0.z = h2u(acc[2][2] + bv[1].x, acc[2][3] + bv[1].y);
            o0.w = h2u(acc[3][2] + bv[1].z, acc[3][3] + bv[1].w);
            o1.x = h2u(acc[4][2] + bv[2].x, acc[4][3] + bv[2].y);
            o1.y = h2u(acc[5][2] + bv[2].z, acc[5][3] + bv[2].w);
            o1.z = h2u(acc[6][2] + bv[3].x, acc[6][3] + bv[3].y);
            o1.w = h2u(acc[7][2] + bv[3].z, acc[7][3] + bv[3].w);
            gp[(size_t)nr1 * 64 + gi * 8 + q * 2]     = o0;
            gp[(size_t)nr1 * 64 + gi * 8 + q * 2 + 1] = o1;
        }
    }
}

// ---------------- fused edge kernel (single fp16 mma, fp16 gather) ----------------
// 64 edges/block, 512 threads, 2 CTA/SM. Layer1: warp = m16 (mg=w&3) x n64 (ng=w>>2).
// smem words: s_ef 64x20 (16 used), s_h 64x68 (64 used), s_out 64x68 floats,
// s_logit 64, s_src/s_dst 64+64. Total 10176 words = 40704 B.
__global__ __launch_bounds__(512, 2) void edge_kernel(
    const float* __restrict__ ef, const int* __restrict__ src, const int* __restrict__ dst,
    const float* __restrict__ be2, const float* __restrict__ ba2,
    float* __restrict__ out_e, int nEdges) {
    extern __shared__ unsigned smw[];
    unsigned* s_ef = smw;                        // 64*20 = 1280
    unsigned* s_h  = smw + 1280;                 // 64*68 = 4352
    float* s_out   = (float*)(smw + 5632);       // 64*68 floats = 4352
    float* s_logit = (float*)(smw + 9984);       // 64
    int*   s_src   = (int*)(s_logit + 64);       // 64
    int*   s_dst   = s_src + 64;                 // 64

    const int tid = threadIdx.x;
    const int e0 = blockIdx.x * 64;
    const int lane = tid & 31, w = tid >> 5;
    const int fr = lane >> 2, q = lane & 3, fc2 = q * 2;

    if (tid < 64) s_logit[tid] = __ldg(ba2);
    if (tid >= 64 && tid < 128) {
        int i = tid - 64, e = e0 + i;
        s_src[i] = (e < nEdges) ? __ldg(src + e) : 0;
        s_dst[i] = (e < nEdges) ? __ldg(dst + e) : 0;
    }
    {   // stage ef: one float4 per thread -> 2 fp16 words
        int r = tid >> 3, m = tid & 7;
        int e = e0 + r;
        float4 v = make_float4(0.f, 0.f, 0.f, 0.f);
        if (e < nEdges) v = __ldg((const float4*)ef + (size_t)e * 8 + m);
        s_ef[r * 20 + pos_of_u(2 * m)]     = h2u(v.x, v.y);
        s_ef[r * 20 + pos_of_u(2 * m + 1)] = h2u(v.z, v.w);
    }
    __syncthreads();

    const int mg = w & 3, ng = w >> 2;
    const int r0 = mg * 16 + fr, r1 = r0 + 8;

    // ================= Layer 1 =================
    {
        float acc[8][4];
        {   // fp16 gather-init (bias pre-folded into dst half)
            const uint4* Ph = (const uint4*)g_preh;   // row = 64 uint4
            int off = ng * 8 + q * 2;
            size_t bs0 = (size_t)s_src[r0] * 64 + off;
            size_t bd0 = (size_t)s_dst[r0] * 64 + 32 + off;
            size_t bs1 = (size_t)s_src[r1] * 64 + off;
            size_t bd1 = (size_t)s_dst[r1] * 64 + 32 + off;
            uint4 sa0 = __ldg(Ph + bs0), sb0 = __ldg(Ph + bs0 + 1);
            uint4 da0 = __ldg(Ph + bd0), db0 = __ldg(Ph + bd0 + 1);
            uint4 sa1 = __ldg(Ph + bs1), sb1 = __ldg(Ph + bs1 + 1);
            uint4 da1 = __ldg(Ph + bd1), db1 = __ldg(Ph + bd1 + 1);
            unsigned su0[8] = {sa0.x, sa0.y, sa0.z, sa0.w, sb0.x, sb0.y, sb0.z, sb0.w};
            unsigned du0[8] = {da0.x, da0.y, da0.z, da0.w, db0.x, db0.y, db0.z, db0.w};
            unsigned su1[8] = {sa1.x, sa1.y, sa1.z, sa1.w, sb1.x, sb1.y, sb1.z, sb1.w};
            unsigned du1[8] = {da1.x, da1.y, da1.z, da1.w, db1.x, db1.y, db1.z, db1.w};
#pragma unroll
            for (int nt = 0; nt < 8; nt++) {
                float2 s0 = u2f(su0[nt]), d0 = u2f(du0[nt]);
                float2 s1 = u2f(su1[nt]), d1 = u2f(du1[nt]);
                acc[nt][0] = s0.x + d0.x;  acc[nt][1] = s0.y + d0.y;
                acc[nt][2] = s1.x + d1.x;  acc[nt][3] = s1.y + d1.y;
            }
        }
        // += ef @ W1e (single fp16 mma)
#pragma unroll
        for (int ks = 0; ks < 2; ks++) {
            uint2 ua0 = *(const uint2*)(s_ef + r0 * 20 + ks * 8 + q * 2);
            uint2 ua1 = *(const uint2*)(s_ef + r1 * 20 + ks * 8 + q * 2);
            unsigned a[4] = {ua0.x, ua1.x, ua0.y, ua1.y};
#pragma unroll
            for (int nt = 0; nt < 8; nt++) {
                int cb = ng * 64 + nt * 8 + fr;
                uint2 wb = __ldg(g_w1fh + ((ks * 256 + cb) << 2) + q);
                mma_f16(acc[nt], a, wb.x, wb.y);
            }
        }
        // ReLU: We-half -> fp16 smem; Wa-half -> logit partials (fp32)
        if (ng < 2) {
#pragma unroll
            for (int nt = 0; nt < 8; nt++) {
                int pos = (ng * 4 + (nt >> 1)) * 8 + q * 2 + (nt & 1);
                s_h[r0 * 68 + pos] = h2u(fmaxf(acc[nt][0], 0.f), fmaxf(acc[nt][1], 0.f));
                s_h[r1 * 68 + pos] = h2u(fmaxf(acc[nt][2], 0.f), fmaxf(acc[nt][3], 0.f));
            }
        } else {
            float p0 = 0.f, p1 = 0.f;
#pragma unroll
            for (int nt = 0; nt < 8; nt++) {
                int c = (ng - 2) * 64 + nt * 8 + fc2;
                float2 wv = __ldg((const float2*)g_wa2n + (c >> 1));
                p0 += fmaxf(acc[nt][0], 0.f) * wv.x + fmaxf(acc[nt][1], 0.f) * wv.y;
                p1 += fmaxf(acc[nt][2], 0.f) * wv.x + fmaxf(acc[nt][3], 0.f) * wv.y;
            }
            p0 += __shfl_xor_sync(0xFFFFFFFFu, p0, 1);
            p0 += __shfl_xor_sync(0xFFFFFFFFu, p0, 2);
            p1 += __shfl_xor_sync(0xFFFFFFFFu, p1, 1);
            p1 += __shfl_xor_sync(0xFFFFFFFFu, p1, 2);
            if (q == 0) {
                atomicAdd(&s_logit[r0], p0);
                atomicAdd(&s_logit[r1], p1);
            }
        }
    }
    __syncthreads();

    // ================= Layer 2 (single fp16 mma) =================
    const int ng2 = w >> 2;
    float acc2[2][4];
#pragma unroll
    for (int nt = 0; nt < 2; nt++)
#pragma unroll
        for (int j = 0; j < 4; j++) acc2[nt][j] = 0.f;
#pragma unroll
    for (int ks = 0; ks < 8; ks++) {
        uint2 ua0 = *(const uint2*)(s_h + r0 * 68 + ks * 8 + q * 2);
        uint2 ua1 = *(const uint2*)(s_h + r1 * 68 + ks * 8 + q * 2);
        unsigned a[4] = {ua0.x, ua1.x, ua0.y, ua1.y};
#pragma unroll
        for (int nt = 0; nt < 2; nt++) {
            int cb = ng2 * 16 + nt * 8 + fr;
            uint2 wb = __ldg(g_w2fh + ((ks * 64 + cb) << 2) + q);
            mma_f16(acc2[nt], a, wb.x, wb.y);
        }
    }

    // ---- epilogue: scatter (from regs) + staged coalesced out_e ----
    {
        float ex0 = expf(s_logit[r0]);
        float ex1 = expf(s_logit[r1]);
        int d0 = s_dst[r0], d1 = s_dst[r1];
        int eg0 = e0 + r0, eg1 = e0 + r1;
        float2 b2a = __ldg((const float2*)be2 + ((ng2 * 16 + fc2) >> 1));
        float2 b2b = __ldg((const float2*)be2 + ((ng2 * 16 + 8 + fc2) >> 1));
        float v00a = acc2[0][0] + b2a.x, v01a = acc2[0][1] + b2a.y;
        float v10a = acc2[1][0] + b2b.x, v11a = acc2[1][1] + b2b.y;
        float v00b = acc2[0][2] + b2a.x, v01b = acc2[0][3] + b2a.y;
        float v10b = acc2[1][2] + b2b.x, v11b = acc2[1][3] + b2b.y;
        if (eg0 < nEdges)
            red_add4(&g_agg[d0 * 64 + ng2 * 16 + q * 4],
                     v00a * ex0, v01a * ex0, v10a * ex0, v11a * ex0);
        if (eg1 < nEdges)
            red_add4(&g_agg[d1 * 64 + ng2 * 16 + q * 4],
                     v00b * ex1, v01b * ex1, v10b * ex1, v11b * ex1);
        if (ng2 == 0 && q == 0) {
            if (eg0 < nEdges) atomicAdd(&g_denom[d0], ex0);
            if (eg1 < nEdges) atomicAdd(&g_denom[d1], ex1);
        }
        int cA = ng2 * 16 + fc2;
        *(float2*)(s_out + r0 * 68 + cA)     = make_float2(v00a, v01a);
        *(float2*)(s_out + r0 * 68 + cA + 8) = make_float2(v10a, v11a);
        *(float2*)(s_out + r1 * 68 + cA)     = make_float2(v00b, v01b);
        *(float2*)(s_out + r1 * 68 + cA + 8) = make_float2(v10b, v11b);
    }
    __syncthreads();
    {   // coalesced write: 512 threads x 2 float4 = 64 edges x 64 floats
        int base = tid * 4;
#pragma unroll
        for (int h = 0; h < 2; h++) {
            int j = base + h * 2048;
            int e = j >> 6, c = j & 63;
            if (e0 + e < nEdges) {
                float4 v = *(const float4*)(s_out + e * 68 + c);
                *(float4*)(out_e + (size_t)(e0 + e) * 64 + c) = v;
            }
        }
    }
}

// ---------------- node MLP (bf16x3 mma, interleaved-fragment smem) ----------------
__global__ __launch_bounds__(256) void node_kernel(
    const float* __restrict__ nf,
    const float* __restrict__ bn1, const float* __restrict__ bn2,
    float* __restrict__ out_n, int nNodes) {
    extern __shared__ unsigned smw[];
    unsigned* s_x = smw;             // 64*144 words
    unsigned* s_h = smw + 64 * 144;  // 64*144 words
    const int tid = threadIdx.x;
    const int lane = tid & 31, w = tid >> 5;
    const int fr = lane >> 2, q = lane & 3, fc2 = q * 2;
    const int n0 = blockIdx.x * 64;

    for (int i = tid; i < 64 * 64; i += 256) {
        int r = i >> 6, u = i & 63;     // col pair (2u, 2u+1) of 128
        int n = n0 + r;
        float2 v = make_float2(0.f, 0.f);
        if (n < nNodes) {
            if (u < 32) {   // agg cols, permuted storage
                int c = 2 * u;
                int g2 = c >> 4, ww = c & 15;
                int nt = ww >> 3, qq = (ww >> 1) & 3;
                int p = g2 * 16 + qq * 4 + nt * 2;
                float dn = fmaxf(g_denom[n], 1e-38f);
                float2 av = *(const float2*)(g_agg + (size_t)n * 64 + p);
                v.x = av.x / dn; v.y = av.y / dn;
            } else {
                v = __ldg((const float2*)(nf + (size_t)n * 64) + (u - 32));
            }
        }
        *(uint2*)(s_x + r * 144 + pos_of_u(u) * 2) = mk_pair(v.x, v.y);
    }
    __syncthreads();

    const int mg = w & 3, ng = w >> 2;
    const int r0 = mg * 16 + fr, r1 = r0 + 8;

    // ---- layer1: h = relu(x @ Wn1 + bn1) ----
    {
        float acc[8][4];
#pragma unroll
        for (int nt = 0; nt < 8; nt++) {
            int c = ng * 64 + nt * 8 + fc2;
            float2 bv = __ldg((const float2*)bn1 + (c >> 1));
            acc[nt][0] = bv.x; acc[nt][1] = bv.y;
            acc[nt][2] = bv.x; acc[nt][3] = bv.y;
        }
#pragma unroll
        for (int ks = 0; ks < 8; ks++) {
            uint4 va0 = *(const uint4*)(s_x + r0 * 144 + ks * 16 + q * 4);
            uint4 va1 = *(const uint4*)(s_x + r1 * 144 + ks * 16 + q * 4);
            unsigned ah[4] = {va0.x, va1.x, va0.z, va1.z};
            unsigned al[4] = {va0.y, va1.y, va0.w, va1.w};
#pragma unroll
            for (int nt = 0; nt < 8; nt++) {
                int cb = ng * 64 + nt * 8 + fr;
                uint4 wb = __ldg(g_wn1f + ((ks * 128 + cb) << 2) + q);
                unsigned bh[2] = {wb.x, wb.y};
                unsigned bl[2] = {wb.z, wb.w};
                mma_bf16(acc[nt], ah, bh);
                mma_bf16(acc[nt], ah, bl);
                mma_bf16(acc[nt], al, bh);
            }
        }
#pragma unroll
        for (int nt = 0; nt < 8; nt++) {
            int pos = (ng * 4 + (nt >> 1)) * 8 + q * 2 + (nt & 1);
            *(uint2*)(s_h + r0 * 144 + pos * 2) =
                mk_pair(fmaxf(acc[nt][0], 0.f), fmaxf(acc[nt][1], 0.f));
            *(uint2*)(s_h + r1 * 144 + pos * 2) =
                mk_pair(fmaxf(acc[nt][2], 0.f), fmaxf(acc[nt][3], 0.f));
        }
    }
    __syncthreads();

    // ---- layer2: out = h @ Wn2 + bn2 ----
    const int ng2 = w >> 2;
    float acc2[4][4];
#pragma unroll
    for (int nt = 0; nt < 4; nt++) {
        int c = ng2 * 32 + nt * 8 + fc2;
        float2 bv = __ldg((const float2*)bn2 + (c >> 1));
        acc2[nt][0] = bv.x; acc2[nt][1] = bv.y;
        acc2[nt][2] = bv.x; acc2[nt][3] = bv.y;
    }
#pragma unroll
    for (int ks = 0; ks < 8; ks++) {
        uint4 va0 = *(const uint4*)(s_h + r0 * 144 + ks * 16 + q * 4);
        uint4 va1 = *(const uint4*)(s_h + r1 * 144 + ks * 16 + q * 4);
        unsigned ah[4] = {va0.x, va1.x, va0.z, va1.z};
        unsigned al[4] = {va0.y, va1.y, va0.w, va1.w};
#pragma unroll
        for (int nt = 0; nt < 4; nt++) {
            int cb = ng2 * 32 + nt * 8 + fr;
            uint4 wb = __ldg(g_wn2f + ((ks * 64 + cb) << 2) + q);
            unsigned bh[2] = {wb.x, wb.y};
            unsigned bl[2] = {wb.z, wb.w};
            mma_bf16(acc2[nt], ah, bh);
            mma_bf16(acc2[nt], ah, bl);
            mma_bf16(acc2[nt], al, bh);
        }
    }
    {
        int nr0 = n0 + r0, nr1 = n0 + r1;
#pragma unroll
        for (int nt = 0; nt < 4; nt++) {
            int c = ng2 * 32 + nt * 8 + fc2;
            if (nr0 < nNodes)
                *(float2*)(out_n + (size_t)nr0 * 64 + c) = make_float2(acc2[nt][0], acc2[nt][1]);
            if (nr1 < nNodes)
                *(float2*)(out_n + (size_t)nr1 * 64 + c) = make_float2(acc2[nt][2], acc2[nt][3]);
        }
    }
}

// ---------------- launch ----------------
extern "C" void kernel_launch(void* const* d_in, const int* in_sizes, int n_in,
                              void* d_out, int out_size) {
    const float* nf  = (const float*)d_in[0];
    const float* ef  = (const float*)d_in[1];
    const int*   src = (const int*)d_in[2];
    const int*   dst = (const int*)d_in[3];
    const float* We1 = (const float*)d_in[4];
    const float* be1 = (const float*)d_in[5];
    const float* We2 = (const float*)d_in[6];
    const float* be2 = (const float*)d_in[7];
    const float* Wa1 = (const float*)d_in[8];
    const float* ba1 = (const float*)d_in[9];
    const float* Wa2 = (const float*)d_in[10];
    const float* ba2 = (const float*)d_in[11];
    const float* Wn1 = (const float*)d_in[12];
    const float* bn1 = (const float*)d_in[13];
    const float* Wn2 = (const float*)d_in[14];
    const float* bn2 = (const float*)d_in[15];

    int nNodes = in_sizes[0] / 64;
    int nEdges = in_sizes[2];

    float* out   = (float*)d_out;
    float* out_n = out;                              // [N,64]
    float* out_e = out + (size_t)nNodes * 64;        // [E,64]

    int smem_pre  = 64 * 72 * 2 * 2;     // 18432
    int smem_edge = 10176 * 4;           // 40704
    int smem_node = (64 * 144) * 2 * 4;  // 73728

    cudaFuncSetAttribute(node_pre_kernel, cudaFuncAttributeMaxDynamicSharedMemorySize, smem_pre);
    cudaFuncSetAttribute(edge_kernel,     cudaFuncAttributeMaxDynamicSharedMemorySize, smem_edge);
    cudaFuncSetAttribute(node_kernel,     cudaFuncAttributeMaxDynamicSharedMemorySize, smem_node);

    pack_kernel<<<128, 256>>>(We1, Wa1, be1, ba1, We2, Wa2, Wn1, Wn2);
    init_kernel<<<256, 256>>>(nNodes);
    node_pre_kernel<<<(nNodes + 63) / 64, 256, smem_pre>>>(nf, nNodes);
    edge_kernel<<<(nEdges + 63) / 64, 512, smem_edge>>>(ef, src, dst, be2, ba2, out_e, nEdges);
    node_kernel<<<(nNodes + 63) / 64, 256, smem_node>>>(nf, bn1, bn2, out_n, nNodes);
}